// round 8
// baseline (speedup 1.0000x reference)
#include <cuda_runtime.h>
#include <cuda_fp16.h>
#include <cstdint>
#include <math.h>

#define B_ 16
#define C_ 512
#define N_ 4096
#define M_ 64

// ---------------- scratch (static device globals) ----------------
__device__ __align__(128) __half g_QnT16[B_*N_*M_];   // [b][n][m] fp16
__device__ __align__(128) __half g_Kn16 [B_*M_*N_];   // [b][m][n] fp16
__device__ __align__(128) __half g_matT16[B_*C_*M_];  // [b][c][m] fp16
__device__ __align__(128) float g_KXp[4][B_*M_*C_];   // k-split partials
__device__ __align__(128) float g_Knp[B_*32*M_];      // Knsum partials per n-tile
__device__ __align__(128) float g_Knsum[B_*M_];
__device__ __align__(128) float g_xsump[4][B_*C_];    // xsum k-split partials
__device__ __align__(128) float g_Vsum[B_*C_];

// ---------------- fp16 pack helpers ----------------
__device__ __forceinline__ uint32_t hpk2(float a, float b) {
    __half2 t = __floats2half2_rn(a, b);
    return *reinterpret_cast<uint32_t*>(&t);
}
__device__ __forceinline__ uint2 pk4(float4 v) {
    uint2 r; r.x = hpk2(v.x, v.y); r.y = hpk2(v.z, v.w); return r;
}
__device__ __forceinline__ uint32_t smem_u32(const void* p) {
    uint32_t a;
    asm("{ .reg .u64 t; cvta.to.shared.u64 t, %1; cvt.u32.u64 %0, t; }" : "=r"(a) : "l"(p));
    return a;
}

// ---------------- mma / ldmatrix helpers ----------------
__device__ __forceinline__ void mma_f16(float c[4], const uint32_t a[4], const uint32_t b[2]) {
    asm volatile("mma.sync.aligned.m16n8k16.row.col.f32.f16.f16.f32 "
        "{%0,%1,%2,%3}, {%4,%5,%6,%7}, {%8,%9}, {%0,%1,%2,%3};"
        : "+f"(c[0]), "+f"(c[1]), "+f"(c[2]), "+f"(c[3])
        : "r"(a[0]), "r"(a[1]), "r"(a[2]), "r"(a[3]), "r"(b[0]), "r"(b[1]));
}
__device__ __forceinline__ void ldsm_x4(uint32_t r[4], uint32_t a) {
    asm volatile("ldmatrix.sync.aligned.m8n8.x4.shared.b16 {%0,%1,%2,%3}, [%4];"
        : "=r"(r[0]), "=r"(r[1]), "=r"(r[2]), "=r"(r[3]) : "r"(a));
}
__device__ __forceinline__ void ldsm_x4t(uint32_t r[4], uint32_t a) {
    asm volatile("ldmatrix.sync.aligned.m8n8.x4.trans.shared.b16 {%0,%1,%2,%3}, [%4];"
        : "=r"(r[0]), "=r"(r[1]), "=r"(r[2]), "=r"(r[3]) : "r"(a));
}
__device__ __forceinline__ float fixv(float v) {
    if (isnan(v)) return 0.f;
    if (isinf(v)) return v > 0.f ? 1.f : -1.f;
    return v;
}

// =====================================================================
// qk_mma: D[128m(64q|64k)][128n] = Wqk @ x, K=512. grid(32,16), 256 thr
// fp16, ldmatrix x4 (A) + x4.trans (B), 1 sync/iter, double-buffered.
// smem: A(s)=s*10240 (128x40 halfs), B(s)=20480+s*8704 (32x136 halfs)
// epilogue Cs at 0 (128*133*4=68096); bias 68096, inq 68608, ink 69120
// =====================================================================
#define QK_A(s)  ((s) * 10240)
#define QK_B(s)  (20480 + (s) * 8704)
#define QK_CS 0
#define QK_BIAS 68096
#define QK_INQ 68608
#define QK_INK 69120
#define QK_BYTES 69632

__global__ __launch_bounds__(256, 1) void qk_mma(
    const float* __restrict__ x,  const float* __restrict__ Wq,
    const float* __restrict__ bq, const float* __restrict__ Wk,
    const float* __restrict__ bk) {
    extern __shared__ __align__(16) char sm[];
    const int t = threadIdx.x, lane = t & 31, wid = t >> 5;
    const int b = blockIdx.y, n0 = blockIdx.x * 128;
    const float* xb = x + (size_t)b * C_ * N_;
    float* bias = (float*)(sm + QK_BIAS);
    float* inq  = (float*)(sm + QK_INQ);
    float* ink  = (float*)(sm + QK_INK);
    if (t < 128) bias[t] = (t < 64) ? bq[t] : bk[t - 64];

    const int m0 = (wid >> 2) * 64, nw = (wid & 3) * 32;
    const int r = lane >> 2, kq = (lane & 3) * 2;
    float acc[4][4][4] = {};

    float4 aR[4], xR[4];
#pragma unroll
    for (int i = 0; i < 4; i++) {
        int idx = t + i * 256, row = idx >> 3, g = idx & 7;
        aR[i] = (row < 64) ? *(const float4*)(Wq + (size_t)row * C_ + 4*g)
                           : *(const float4*)(Wk + (size_t)(row - 64) * C_ + 4*g);
    }
#pragma unroll
    for (int i = 0; i < 4; i++) {
        int idx = t + i * 256, kk = idx >> 5, g = idx & 31;
        xR[i] = *(const float4*)(xb + (size_t)kk * N_ + n0 + 4*g);
    }

    for (int p = 0; p < 16; ++p) {
        const int s = p & 1;
        __half* Ah = (__half*)(sm + QK_A(s));
        __half* Bh = (__half*)(sm + QK_B(s));
#pragma unroll
        for (int i = 0; i < 4; i++) {   // A rows (m), 32 k, pitch 40
            int idx = t + i * 256, row = idx >> 3, g = idx & 7;
            *(uint2*)(Ah + row * 40 + 4*g) = pk4(aR[i]);
        }
#pragma unroll
        for (int i = 0; i < 4; i++) {   // B k-major: 32 k-rows x 128 n, pitch 136
            int idx = t + i * 256, kk = idx >> 5, g = idx & 31;
            *(uint2*)(Bh + kk * 136 + 4*g) = pk4(xR[i]);
        }
        __syncthreads();
        if (p < 15) {   // prefetch next k-step
            const int k0 = (p + 1) * 32;
#pragma unroll
            for (int i = 0; i < 4; i++) {
                int idx = t + i * 256, row = idx >> 3, g = idx & 7;
                aR[i] = (row < 64) ? *(const float4*)(Wq + (size_t)row * C_ + k0 + 4*g)
                                   : *(const float4*)(Wk + (size_t)(row - 64) * C_ + k0 + 4*g);
            }
#pragma unroll
            for (int i = 0; i < 4; i++) {
                int idx = t + i * 256, kk = idx >> 5, g = idx & 31;
                xR[i] = *(const float4*)(xb + (size_t)(k0 + kk) * N_ + n0 + 4*g);
            }
        }
        const uint32_t Ab = smem_u32(Ah), Bb = smem_u32(Bh);
#pragma unroll
        for (int kc = 0; kc < 32; kc += 16) {
            uint32_t ah[4][4], bh[4][2];
#pragma unroll
            for (int mf = 0; mf < 4; mf++)
                ldsm_x4(ah[mf], Ab + ((m0 + mf*16 + (lane & 15)) * 40 + kc + (lane >> 4) * 8) * 2);
#pragma unroll
            for (int nf = 0; nf < 4; nf += 2) {
                uint32_t rr[4];
                // lanes 0-15: n-octet nf (k rows kc+0..15); lanes 16-31: n-octet nf+1
                ldsm_x4t(rr, Bb + ((kc + (lane & 15)) * 136 + nw + nf*8 + (lane >> 4) * 8) * 2);
                bh[nf][0] = rr[0]; bh[nf][1] = rr[1];
                bh[nf+1][0] = rr[2]; bh[nf+1][1] = rr[3];
            }
#pragma unroll
            for (int mf = 0; mf < 4; mf++)
#pragma unroll
                for (int nf = 0; nf < 4; nf++) mma_f16(acc[mf][nf], ah[mf], bh[nf]);
        }
    }
    __syncthreads();   // panels dead; reuse smem as Cs

    float* Cs = (float*)(sm + QK_CS);
#pragma unroll
    for (int mf = 0; mf < 4; mf++) {
        int mA = m0 + mf*16 + r, mB = mA + 8;
        float bA = bias[mA], bB = bias[mB];
#pragma unroll
        for (int nf = 0; nf < 4; nf++) {
            int n = nw + nf*8 + kq;
            Cs[mA * 133 + n    ] = acc[mf][nf][0] + bA;
            Cs[mA * 133 + n + 1] = acc[mf][nf][1] + bA;
            Cs[mB * 133 + n    ] = acc[mf][nf][2] + bB;
            Cs[mB * 133 + n + 1] = acc[mf][nf][3] + bB;
        }
    }
    __syncthreads();
    {   // per-column L2 norms
        int n = t & 127, part = t >> 7, base = part * 64;
        float s = 0.f;
#pragma unroll 8
        for (int m = 0; m < 64; m++) {
            float v = Cs[(base + m) * 133 + n]; s = fmaf(v, v, s);
        }
        float inv = 1.f / fmaxf(sqrtf(s), 1e-6f);
        if (part == 0) inq[n] = inv; else ink[n] = inv;
    }
    __syncthreads();
    // write Kn16[m][n] (fp16) + Knsum partials (from fp32 values)
#pragma unroll
    for (int i = 0; i < 8; i++) {
        int idx = t + i * 256, m = idx >> 5, g = idx & 31;
        float4 v;
        v.x = Cs[(64 + m) * 133 + 4*g + 0] * ink[4*g + 0];
        v.y = Cs[(64 + m) * 133 + 4*g + 1] * ink[4*g + 1];
        v.z = Cs[(64 + m) * 133 + 4*g + 2] * ink[4*g + 2];
        v.w = Cs[(64 + m) * 133 + 4*g + 3] * ink[4*g + 3];
        *(uint2*)(g_Kn16 + ((size_t)b * M_ + m) * N_ + n0 + 4*g) = pk4(v);
        float rs = v.x + v.y + v.z + v.w;
#pragma unroll
        for (int o = 16; o; o >>= 1) rs += __shfl_xor_sync(0xffffffffu, rs, o);
        if (lane == 0) g_Knp[((size_t)b * 32 + blockIdx.x) * M_ + m] = rs;
    }
    // write QnT16[n][m] (fp16)
#pragma unroll
    for (int i = 0; i < 8; i++) {
        int idx = t + i * 256, n = idx >> 4, g = idx & 15;
        float iq = inq[n];
        float4 v;
        v.x = Cs[(4*g + 0) * 133 + n] * iq;
        v.y = Cs[(4*g + 1) * 133 + n] * iq;
        v.z = Cs[(4*g + 2) * 133 + n] * iq;
        v.w = Cs[(4*g + 3) * 133 + n] * iq;
        *(uint2*)(g_QnT16 + ((size_t)b * N_ + n0 + n) * M_ + 4*g) = pk4(v);
    }
}

// tiny: fold 32 n-tile partials into Knsum. grid(16), 64 thr
__global__ void rowsum_Kp() {
    int b = blockIdx.x, m = threadIdx.x;
    float s = 0.f;
#pragma unroll
    for (int i = 0; i < 32; i++) s += g_Knp[((size_t)b * 32 + i) * M_ + m];
    g_Knsum[b * M_ + m] = s;
}

// =====================================================================
// kx_mma: D[64m][128c] = Kn @ x^T over k-slice of 1024 (fp16, ldmatrix).
// Kn read directly fp16 (no conversion). grid (4, 16, 4), 256 thr.
// smem: A(s)=s*5120 (64x40), B(s)=10240+s*10240 (128x40); Cs at 0 (33792)
// =====================================================================
#define KX_A(s) ((s) * 5120)
#define KX_B(s) (10240 + (s) * 10240)
#define KX_CS 0
#define KX_BYTES 33792

__global__ __launch_bounds__(256, 1) void kx_mma(const float* __restrict__ x) {
    __shared__ __align__(16) char sm[KX_BYTES];
    const int t = threadIdx.x, lane = t & 31, wid = t >> 5;
    const int b = blockIdx.y, c0 = blockIdx.x * 128, ks = blockIdx.z;
    const __half* Kb = g_Kn16 + (size_t)b * M_ * N_;
    const float* xb = x + (size_t)b * C_ * N_ + (size_t)c0 * N_;
    const int m0 = (wid >> 2) * 32, cw = (wid & 3) * 32;
    const int r = lane >> 2, kq = (lane & 3) * 2;
    float acc[2][4][4] = {};
    float xs[4] = {0.f, 0.f, 0.f, 0.f};

    uint4 aR;       // 8 halfs of Kn
    float4 bR[4];
    {   // prologue: load step 0
        const int k0 = ks * 1024;
        { int row = t >> 2, g = t & 3;
          aR = *(const uint4*)(Kb + (size_t)row * N_ + k0 + 8*g); }
#pragma unroll
        for (int i = 0; i < 4; i++) {
            int idx = t + i * 256, row = idx >> 3, g = idx & 7;
            bR[i] = *(const float4*)(xb + (size_t)row * N_ + k0 + 4*g);
        }
    }

    for (int p = 0; p < 32; ++p) {
        const int s = p & 1;
        __half* Ah = (__half*)(sm + KX_A(s));
        __half* Bh = (__half*)(sm + KX_B(s));
        { int row = t >> 2, g = t & 3;
          *(uint4*)(Ah + row * 40 + 8*g) = aR; }
#pragma unroll
        for (int i = 0; i < 4; i++) {
            int idx = t + i * 256, row = idx >> 3, g = idx & 7;
            xs[i] += bR[i].x + bR[i].y + bR[i].z + bR[i].w;
            *(uint2*)(Bh + row * 40 + 4*g) = pk4(bR[i]);
        }
        __syncthreads();
        if (p < 31) {   // prefetch next step
            const int k0 = ks * 1024 + (p + 1) * 32;
            { int row = t >> 2, g = t & 3;
              aR = *(const uint4*)(Kb + (size_t)row * N_ + k0 + 8*g); }
#pragma unroll
            for (int i = 0; i < 4; i++) {
                int idx = t + i * 256, row = idx >> 3, g = idx & 7;
                bR[i] = *(const float4*)(xb + (size_t)row * N_ + k0 + 4*g);
            }
        }
        const uint32_t Ab = smem_u32(Ah), Bb = smem_u32(Bh);
#pragma unroll
        for (int kc = 0; kc < 32; kc += 16) {
            uint32_t ah[2][4], bh[4][2];
#pragma unroll
            for (int mf = 0; mf < 2; mf++)
                ldsm_x4(ah[mf], Ab + ((m0 + mf*16 + (lane & 15)) * 40 + kc + (lane >> 4) * 8) * 2);
#pragma unroll
            for (int nf = 0; nf < 4; nf += 2) {
                uint32_t rr[4];
                // lanes 0-15: c-octet nf (k halves); lanes 16-31: c-octet nf+1
                ldsm_x4(rr, Bb + ((cw + nf*8 + (lane & 7) + ((lane >> 4) << 3)) * 40
                                  + kc + ((lane >> 3) & 1) * 8) * 2);
                bh[nf][0] = rr[0]; bh[nf][1] = rr[1];
                bh[nf+1][0] = rr[2]; bh[nf+1][1] = rr[3];
            }
#pragma unroll
            for (int mf = 0; mf < 2; mf++)
#pragma unroll
                for (int nf = 0; nf < 4; nf++) mma_f16(acc[mf][nf], ah[mf], bh[nf]);
        }
    }

    // xsum partial: reduce over 8 column-group threads per row
#pragma unroll
    for (int i = 0; i < 4; i++) {
        float v = xs[i];
        v += __shfl_xor_sync(0xffffffffu, v, 1);
        v += __shfl_xor_sync(0xffffffffu, v, 2);
        v += __shfl_xor_sync(0xffffffffu, v, 4);
        if ((t & 7) == 0)
            g_xsump[ks][b * C_ + c0 + (t >> 3) + 32 * i] = v;
    }
    __syncthreads();

    float* Cs = (float*)(sm + KX_CS);
#pragma unroll
    for (int mf = 0; mf < 2; mf++) {
        int mA = m0 + mf*16 + r, mB = mA + 8;
#pragma unroll
        for (int nf = 0; nf < 4; nf++) {
            int c = cw + nf*8 + kq;
            Cs[mA * 132 + c    ] = acc[mf][nf][0];
            Cs[mA * 132 + c + 1] = acc[mf][nf][1];
            Cs[mB * 132 + c    ] = acc[mf][nf][2];
            Cs[mB * 132 + c + 1] = acc[mf][nf][3];
        }
    }
    __syncthreads();
#pragma unroll
    for (int i = 0; i < 8; i++) {
        int idx = t + i * 256, m = idx >> 5, g = idx & 31;
        float4 v = *(float4*)(Cs + m * 132 + 4*g);
        *(float4*)(g_KXp[ks] + ((size_t)b * M_ + m) * C_ + c0 + 4*g) = v;
    }
}

// =====================================================================
// vsum: Vsum[b][c] = Wv[c,:].xsum[b,:] + N*bv[c]. grid(16 b), 256 thr.
// warp-per-channel, xsum staged in smem; low regs.
// =====================================================================
__global__ __launch_bounds__(256, 1) void vsum_kernel(const float* __restrict__ Wv,
                                                      const float* __restrict__ bv) {
    __shared__ float xss[C_];
    const int t = threadIdx.x, b = blockIdx.x;
    const int w = t >> 5, lane = t & 31;
    for (int i = t; i < C_; i += 256)
        xss[i] = g_xsump[0][b * C_ + i] + g_xsump[1][b * C_ + i]
               + g_xsump[2][b * C_ + i] + g_xsump[3][b * C_ + i];
    __syncthreads();
    for (int c = w; c < C_; c += 8) {
        const float* wr = Wv + (size_t)c * C_;
        float s = 0.f;
#pragma unroll 4
        for (int k = lane; k < C_; k += 32) s = fmaf(wr[k], xss[k], s);
#pragma unroll
        for (int o = 16; o; o >>= 1) s += __shfl_xor_sync(0xffffffffu, s, o);
        if (lane == 0) g_Vsum[b * C_ + c] = s + (float)N_ * bv[c];
    }
}

// mat: D[m][c] = sum_k (sum_ks KXp)[m][k] Wv[c][k]; matT16[c][m] fp16 out
__global__ void mat_gemm(const float* __restrict__ Wv, const float* __restrict__ bv) {
    __shared__ float As[64][65];
    __shared__ float Bs[64][65];
    int b = blockIdx.y, c0 = blockIdx.x * 64, t = threadIdx.x;
    int tm = t >> 4, tc = t & 15;
    float acc[4][4] = {};
    const float* A0 = g_KXp[0] + (size_t)b * M_ * C_;
    const float* A1 = g_KXp[1] + (size_t)b * M_ * C_;
    const float* A2 = g_KXp[2] + (size_t)b * M_ * C_;
    const float* A3 = g_KXp[3] + (size_t)b * M_ * C_;
    const float* Bm = Wv + (size_t)c0 * C_;
    for (int k0 = 0; k0 < C_; k0 += 64) {
#pragma unroll
        for (int i = 0; i < 16; i++) {
            int idx = t + i * 256, rr = idx >> 6, kk = idx & 63;
            size_t off = (size_t)rr * C_ + k0 + kk;
            As[rr][kk] = A0[off] + A1[off] + A2[off] + A3[off];
            Bs[rr][kk] = Bm[off];
        }
        __syncthreads();
#pragma unroll
        for (int kk = 0; kk < 64; kk++) {
            float a[4], bb[4];
#pragma unroll
            for (int i = 0; i < 4; i++) a[i]  = As[tm + 16*i][kk];
#pragma unroll
            for (int j = 0; j < 4; j++) bb[j] = Bs[tc + 16*j][kk];
#pragma unroll
            for (int i = 0; i < 4; i++)
#pragma unroll
                for (int j = 0; j < 4; j++) acc[i][j] = fmaf(a[i], bb[j], acc[i][j]);
        }
        __syncthreads();
    }
#pragma unroll
    for (int i = 0; i < 4; i++) {
        int m = tm + 16*i;
        float kn = g_Knsum[b * M_ + m];
#pragma unroll
        for (int j = 0; j < 4; j++) {
            int c = c0 + tc + 16*j;
            g_matT16[((size_t)b * C_ + c) * M_ + m] = __float2half_rn(acc[i][j] + bv[c] * kn);
        }
    }
}

// =====================================================================
// final_mma: D[128c][128n] = matT @ QnT^T, K=64, fused tailor, ldmatrix.
// A/B read directly fp16. grid (32 n, 4 c, 16 b), 256 thr.
// smem: Ah 0 (128x72 halfs), Bh 18432 -> 36864; Cs 0 (67584); tl 67584,
//       vs 68096, ks 68608 -> 68864
// =====================================================================
#define FN_AH 0
#define FN_BH 18432
#define FN_CS 0
#define FN_TL 67584
#define FN_VS 68096
#define FN_KS 68608
#define FN_BYTES 68864

__global__ __launch_bounds__(256, 1) void final_mma(float* __restrict__ out,
                                                    const float* __restrict__ gamma) {
    extern __shared__ __align__(16) char sm[];
    const int t = threadIdx.x, lane = t & 31, wid = t >> 5;
    const int b = blockIdx.z, c0 = blockIdx.y * 128, n0 = blockIdx.x * 128;
    float* tl = (float*)(sm + FN_TL);
    float* vs = (float*)(sm + FN_VS);
    float* ks = (float*)(sm + FN_KS);
    if (t < 128) vs[t] = g_Vsum[b * C_ + c0 + t];
    if (t < 64)  ks[t] = g_Knsum[b * M_ + t];
    __half* Ah = (__half*)(sm + FN_AH);
    __half* Bh = (__half*)(sm + FN_BH);
#pragma unroll
    for (int i = 0; i < 4; i++) {       // A: matT16 rows (c), 64 k
        int idx = t + i * 256, row = idx >> 3, g = idx & 7;
        uint4 v = *(const uint4*)(g_matT16 + ((size_t)b * C_ + c0 + row) * M_ + 8*g);
        *(uint4*)(Ah + row * 72 + 8*g) = v;
    }
#pragma unroll
    for (int i = 0; i < 4; i++) {       // B: QnT16 rows (n), 64 k
        int idx = t + i * 256, row = idx >> 3, g = idx & 7;
        uint4 v = *(const uint4*)(g_QnT16 + ((size_t)b * N_ + n0 + row) * M_ + 8*g);
        *(uint4*)(Bh + row * 72 + 8*g) = v;
    }
    __syncthreads();

    // fused tailor: tl[n] = 1/max(N + Qn[n,:].Knsum, 1e-6)
    if (t < 128) {
        float d = (float)N_;
#pragma unroll
        for (int m = 0; m < 64; m++) d += __half2float(Bh[t * 72 + m]) * ks[m];
        tl[t] = 1.f / fmaxf(d, 1e-6f);
    }

    const int cw = (wid >> 2) * 64, nw = (wid & 3) * 32;
    const int r = lane >> 2, kq = (lane & 3) * 2;
    const uint32_t Ab = smem_u32(Ah), Bb = smem_u32(Bh);
    float acc[4][4][4] = {};
#pragma unroll
    for (int kc = 0; kc < 64; kc += 16) {
        uint32_t ah[4][4], bh[4][2];
#pragma unroll
        for (int mf = 0; mf < 4; mf++)
            ldsm_x4(ah[mf], Ab + ((cw + mf*16 + (lane & 15)) * 72 + kc + (lane >> 4) * 8) * 2);
#pragma unroll
        for (int nf = 0; nf < 4; nf += 2) {
            uint32_t rr[4];
            ldsm_x4(rr, Bb + ((nw + nf*8 + (lane & 7) + ((lane >> 4) << 3)) * 72
                              + kc + ((lane >> 3) & 1) * 8) * 2);
            bh[nf][0] = rr[0]; bh[nf][1] = rr[1];
            bh[nf+1][0] = rr[2]; bh[nf+1][1] = rr[3];
        }
#pragma unroll
        for (int mf = 0; mf < 4; mf++)
#pragma unroll
            for (int nf = 0; nf < 4; nf++) mma_f16(acc[mf][nf], ah[mf], bh[nf]);
    }
    __syncthreads();

    float* Cs = (float*)(sm + FN_CS);
    float gm = gamma[0];
#pragma unroll
    for (int mf = 0; mf < 4; mf++) {
        int cA = cw + mf*16 + r, cB = cA + 8;
        float vA = vs[cA], vB = vs[cB];
#pragma unroll
        for (int nf = 0; nf < 4; nf++) {
            int n = nw + nf*8 + kq;
            Cs[cA * 132 + n    ] = fixv(gm * tl[n    ] * (vA + acc[mf][nf][0]));
            Cs[cA * 132 + n + 1] = fixv(gm * tl[n + 1] * (vA + acc[mf][nf][1]));
            Cs[cB * 132 + n    ] = fixv(gm * tl[n    ] * (vB + acc[mf][nf][2]));
            Cs[cB * 132 + n + 1] = fixv(gm * tl[n + 1] * (vB + acc[mf][nf][3]));
        }
    }
    __syncthreads();
#pragma unroll
    for (int i = 0; i < 16; i++) {
        int idx = t + i * 256, c = idx >> 5, g = idx & 31;
        float4 v = *(float4*)(Cs + c * 132 + 4*g);
        *(float4*)(out + ((size_t)b * C_ + c0 + c) * N_ + n0 + 4*g) = v;
    }
}

// ---------------------------------------------------------------
extern "C" void kernel_launch(void* const* d_in, const int* in_sizes, int n_in,
                              void* d_out, int out_size) {
    const float* x     = (const float*)d_in[0];
    const float* Wq    = (const float*)d_in[1];
    const float* bq    = (const float*)d_in[2];
    const float* Wk    = (const float*)d_in[3];
    const float* bk    = (const float*)d_in[4];
    const float* Wv    = (const float*)d_in[5];
    const float* bv    = (const float*)d_in[6];
    const float* gamma = (const float*)d_in[7];
    float* out = (float*)d_out;

    cudaFuncSetAttribute(qk_mma,    cudaFuncAttributeMaxDynamicSharedMemorySize, QK_BYTES);
    cudaFuncSetAttribute(final_mma, cudaFuncAttributeMaxDynamicSharedMemorySize, FN_BYTES);

    qk_mma     <<<dim3(32, 16), 256, QK_BYTES>>>(x, Wq, bq, Wk, bk);
    rowsum_Kp  <<<16, 64>>>();
    kx_mma     <<<dim3(4, 16, 4), 256>>>(x);
    vsum_kernel<<<16, 256>>>(Wv, bv);
    mat_gemm   <<<dim3(8, 16), 256>>>(Wv, bv);
    final_mma  <<<dim3(32, 4, 16), 256, FN_BYTES>>>(out, gamma);
}

// round 9
// speedup vs baseline: 1.3873x; 1.3873x over previous
#include <cuda_runtime.h>
#include <cuda_fp16.h>
#include <cstdint>
#include <math.h>

#define B_ 16
#define C_ 512
#define N_ 4096
#define M_ 64

// ---------------- scratch (static device globals) ----------------
__device__ __align__(128) __half g_QnT16[B_*N_*M_];   // [b][n][m] fp16
__device__ __align__(128) __half g_Kn16 [B_*M_*N_];   // [b][m][n] fp16
__device__ __align__(128) __half g_matT16[B_*C_*M_];  // [b][c][m] fp16
__device__ __align__(128) float g_KXp[4][B_*M_*C_];   // k-split partials
__device__ __align__(128) float g_Knp[B_*32*M_];      // Knsum partials per n-tile
__device__ __align__(128) float g_Knsum[B_*M_];
__device__ __align__(128) float g_xsump[4][B_*C_];    // xsum k-split partials
__device__ __align__(128) float g_xsum[B_*C_];        // folded
__device__ __align__(128) float g_Vsum[B_*C_];

// ---------------- fp16 pack helpers ----------------
__device__ __forceinline__ uint32_t hpk2(float a, float b) {
    __half2 t = __floats2half2_rn(a, b);
    return *reinterpret_cast<uint32_t*>(&t);
}
__device__ __forceinline__ uint2 pk4(float4 v) {
    uint2 r; r.x = hpk2(v.x, v.y); r.y = hpk2(v.z, v.w); return r;
}
__device__ __forceinline__ uint32_t smem_u32(const void* p) {
    uint32_t a;
    asm("{ .reg .u64 t; cvta.to.shared.u64 t, %1; cvt.u32.u64 %0, t; }" : "=r"(a) : "l"(p));
    return a;
}

// ---------------- mma / ldmatrix helpers ----------------
__device__ __forceinline__ void mma_f16(float c[4], const uint32_t a[4], const uint32_t b[2]) {
    asm volatile("mma.sync.aligned.m16n8k16.row.col.f32.f16.f16.f32 "
        "{%0,%1,%2,%3}, {%4,%5,%6,%7}, {%8,%9}, {%0,%1,%2,%3};"
        : "+f"(c[0]), "+f"(c[1]), "+f"(c[2]), "+f"(c[3])
        : "r"(a[0]), "r"(a[1]), "r"(a[2]), "r"(a[3]), "r"(b[0]), "r"(b[1]));
}
__device__ __forceinline__ void ldsm_x4(uint32_t r[4], uint32_t a) {
    asm volatile("ldmatrix.sync.aligned.m8n8.x4.shared.b16 {%0,%1,%2,%3}, [%4];"
        : "=r"(r[0]), "=r"(r[1]), "=r"(r[2]), "=r"(r[3]) : "r"(a));
}
__device__ __forceinline__ void ldsm_x4t(uint32_t r[4], uint32_t a) {
    asm volatile("ldmatrix.sync.aligned.m8n8.x4.trans.shared.b16 {%0,%1,%2,%3}, [%4];"
        : "=r"(r[0]), "=r"(r[1]), "=r"(r[2]), "=r"(r[3]) : "r"(a));
}
__device__ __forceinline__ float fixv(float v) {
    if (isnan(v)) return 0.f;
    if (isinf(v)) return v > 0.f ? 1.f : -1.f;
    return v;
}

// =====================================================================
// qk_mma: D[128m(64q|64k)][128n] = Wqk @ x, K=512. grid(32,16), 256 thr
// fp16, ldmatrix x4 (A) + x4.trans (B), 1 sync/iter, double-buffered.
// smem: A(s)=s*10240 (128x40 halfs), B(s)=20480+s*8704 (32x136 halfs)
// epilogue Cs at 0 (128*133*4=68096); bias 68096, inq 68608, ink 69120
// =====================================================================
#define QK_A(s)  ((s) * 10240)
#define QK_B(s)  (20480 + (s) * 8704)
#define QK_CS 0
#define QK_BIAS 68096
#define QK_INQ 68608
#define QK_INK 69120
#define QK_BYTES 69632

__global__ __launch_bounds__(256, 1) void qk_mma(
    const float* __restrict__ x,  const float* __restrict__ Wq,
    const float* __restrict__ bq, const float* __restrict__ Wk,
    const float* __restrict__ bk) {
    extern __shared__ __align__(16) char sm[];
    const int t = threadIdx.x, lane = t & 31, wid = t >> 5;
    const int b = blockIdx.y, n0 = blockIdx.x * 128;
    const float* xb = x + (size_t)b * C_ * N_;
    float* bias = (float*)(sm + QK_BIAS);
    float* inq  = (float*)(sm + QK_INQ);
    float* ink  = (float*)(sm + QK_INK);
    if (t < 128) bias[t] = (t < 64) ? bq[t] : bk[t - 64];

    const int m0 = (wid >> 2) * 64, nw = (wid & 3) * 32;
    const int r = lane >> 2, kq = (lane & 3) * 2;
    float acc[4][4][4] = {};

    float4 aR[4], xR[4];
#pragma unroll
    for (int i = 0; i < 4; i++) {
        int idx = t + i * 256, row = idx >> 3, g = idx & 7;
        aR[i] = (row < 64) ? *(const float4*)(Wq + (size_t)row * C_ + 4*g)
                           : *(const float4*)(Wk + (size_t)(row - 64) * C_ + 4*g);
    }
#pragma unroll
    for (int i = 0; i < 4; i++) {
        int idx = t + i * 256, kk = idx >> 5, g = idx & 31;
        xR[i] = *(const float4*)(xb + (size_t)kk * N_ + n0 + 4*g);
    }

    for (int p = 0; p < 16; ++p) {
        const int s = p & 1;
        __half* Ah = (__half*)(sm + QK_A(s));
        __half* Bh = (__half*)(sm + QK_B(s));
#pragma unroll
        for (int i = 0; i < 4; i++) {   // A rows (m), 32 k, pitch 40
            int idx = t + i * 256, row = idx >> 3, g = idx & 7;
            *(uint2*)(Ah + row * 40 + 4*g) = pk4(aR[i]);
        }
#pragma unroll
        for (int i = 0; i < 4; i++) {   // B k-major: 32 k-rows x 128 n, pitch 136
            int idx = t + i * 256, kk = idx >> 5, g = idx & 31;
            *(uint2*)(Bh + kk * 136 + 4*g) = pk4(xR[i]);
        }
        __syncthreads();
        if (p < 15) {   // prefetch next k-step
            const int k0 = (p + 1) * 32;
#pragma unroll
            for (int i = 0; i < 4; i++) {
                int idx = t + i * 256, row = idx >> 3, g = idx & 7;
                aR[i] = (row < 64) ? *(const float4*)(Wq + (size_t)row * C_ + k0 + 4*g)
                                   : *(const float4*)(Wk + (size_t)(row - 64) * C_ + k0 + 4*g);
            }
#pragma unroll
            for (int i = 0; i < 4; i++) {
                int idx = t + i * 256, kk = idx >> 5, g = idx & 31;
                xR[i] = *(const float4*)(xb + (size_t)(k0 + kk) * N_ + n0 + 4*g);
            }
        }
        const uint32_t Ab = smem_u32(Ah), Bb = smem_u32(Bh);
#pragma unroll
        for (int kc = 0; kc < 32; kc += 16) {
            uint32_t ah[4][4], bh[4][2];
#pragma unroll
            for (int mf = 0; mf < 4; mf++)
                ldsm_x4(ah[mf], Ab + ((m0 + mf*16 + (lane & 15)) * 40 + kc + (lane >> 4) * 8) * 2);
#pragma unroll
            for (int nf = 0; nf < 4; nf += 2) {
                uint32_t rr[4];
                ldsm_x4t(rr, Bb + ((kc + (lane & 15)) * 136 + nw + nf*8 + (lane >> 4) * 8) * 2);
                bh[nf][0] = rr[0]; bh[nf][1] = rr[1];
                bh[nf+1][0] = rr[2]; bh[nf+1][1] = rr[3];
            }
#pragma unroll
            for (int mf = 0; mf < 4; mf++)
#pragma unroll
                for (int nf = 0; nf < 4; nf++) mma_f16(acc[mf][nf], ah[mf], bh[nf]);
        }
    }
    __syncthreads();   // panels dead; reuse smem as Cs

    float* Cs = (float*)(sm + QK_CS);
#pragma unroll
    for (int mf = 0; mf < 4; mf++) {
        int mA = m0 + mf*16 + r, mB = mA + 8;
        float bA = bias[mA], bB = bias[mB];
#pragma unroll
        for (int nf = 0; nf < 4; nf++) {
            int n = nw + nf*8 + kq;
            Cs[mA * 133 + n    ] = acc[mf][nf][0] + bA;
            Cs[mA * 133 + n + 1] = acc[mf][nf][1] + bA;
            Cs[mB * 133 + n    ] = acc[mf][nf][2] + bB;
            Cs[mB * 133 + n + 1] = acc[mf][nf][3] + bB;
        }
    }
    __syncthreads();
    {   // per-column L2 norms
        int n = t & 127, part = t >> 7, base = part * 64;
        float s = 0.f;
#pragma unroll 8
        for (int m = 0; m < 64; m++) {
            float v = Cs[(base + m) * 133 + n]; s = fmaf(v, v, s);
        }
        float inv = 1.f / fmaxf(sqrtf(s), 1e-6f);
        if (part == 0) inq[n] = inv; else ink[n] = inv;
    }
    __syncthreads();
    // write Kn16[m][n] (fp16) + Knsum partials
#pragma unroll
    for (int i = 0; i < 8; i++) {
        int idx = t + i * 256, m = idx >> 5, g = idx & 31;
        float4 v;
        v.x = Cs[(64 + m) * 133 + 4*g + 0] * ink[4*g + 0];
        v.y = Cs[(64 + m) * 133 + 4*g + 1] * ink[4*g + 1];
        v.z = Cs[(64 + m) * 133 + 4*g + 2] * ink[4*g + 2];
        v.w = Cs[(64 + m) * 133 + 4*g + 3] * ink[4*g + 3];
        *(uint2*)(g_Kn16 + ((size_t)b * M_ + m) * N_ + n0 + 4*g) = pk4(v);
        float rs = v.x + v.y + v.z + v.w;
#pragma unroll
        for (int o = 16; o; o >>= 1) rs += __shfl_xor_sync(0xffffffffu, rs, o);
        if (lane == 0) g_Knp[((size_t)b * 32 + blockIdx.x) * M_ + m] = rs;
    }
    // write QnT16[n][m] (fp16)
#pragma unroll
    for (int i = 0; i < 8; i++) {
        int idx = t + i * 256, n = idx >> 4, g = idx & 15;
        float iq = inq[n];
        float4 v;
        v.x = Cs[(4*g + 0) * 133 + n] * iq;
        v.y = Cs[(4*g + 1) * 133 + n] * iq;
        v.z = Cs[(4*g + 2) * 133 + n] * iq;
        v.w = Cs[(4*g + 3) * 133 + n] * iq;
        *(uint2*)(g_QnT16 + ((size_t)b * N_ + n0 + n) * M_ + 4*g) = pk4(v);
    }
}

// tiny: fold 32 n-tile partials into Knsum. grid(16), 64 thr
__global__ void rowsum_Kp() {
    int b = blockIdx.x, m = threadIdx.x;
    float s = 0.f;
#pragma unroll
    for (int i = 0; i < 32; i++) s += g_Knp[((size_t)b * 32 + i) * M_ + m];
    g_Knsum[b * M_ + m] = s;
}

// =====================================================================
// kx_mma: D[64m][128c] = Kn @ x^T over k-slice of 1024 (fp16, ldmatrix).
// grid (4, 16, 4), 256 thr. smem: A(s)=s*5120, B(s)=10240+s*10240; Cs 0
// =====================================================================
#define KX_A(s) ((s) * 5120)
#define KX_B(s) (10240 + (s) * 10240)
#define KX_CS 0
#define KX_BYTES 33792

__global__ __launch_bounds__(256, 1) void kx_mma(const float* __restrict__ x) {
    __shared__ __align__(16) char sm[KX_BYTES];
    const int t = threadIdx.x, lane = t & 31, wid = t >> 5;
    const int b = blockIdx.y, c0 = blockIdx.x * 128, ks = blockIdx.z;
    const __half* Kb = g_Kn16 + (size_t)b * M_ * N_;
    const float* xb = x + (size_t)b * C_ * N_ + (size_t)c0 * N_;
    const int m0 = (wid >> 2) * 32, cw = (wid & 3) * 32;
    const int r = lane >> 2, kq = (lane & 3) * 2;
    float acc[2][4][4] = {};
    float xs[4] = {0.f, 0.f, 0.f, 0.f};

    uint4 aR;
    float4 bR[4];
    {   // prologue: load step 0
        const int k0 = ks * 1024;
        { int row = t >> 2, g = t & 3;
          aR = *(const uint4*)(Kb + (size_t)row * N_ + k0 + 8*g); }
#pragma unroll
        for (int i = 0; i < 4; i++) {
            int idx = t + i * 256, row = idx >> 3, g = idx & 7;
            bR[i] = *(const float4*)(xb + (size_t)row * N_ + k0 + 4*g);
        }
    }

    for (int p = 0; p < 32; ++p) {
        const int s = p & 1;
        __half* Ah = (__half*)(sm + KX_A(s));
        __half* Bh = (__half*)(sm + KX_B(s));
        { int row = t >> 2, g = t & 3;
          *(uint4*)(Ah + row * 40 + 8*g) = aR; }
#pragma unroll
        for (int i = 0; i < 4; i++) {
            int idx = t + i * 256, row = idx >> 3, g = idx & 7;
            xs[i] += bR[i].x + bR[i].y + bR[i].z + bR[i].w;
            *(uint2*)(Bh + row * 40 + 4*g) = pk4(bR[i]);
        }
        __syncthreads();
        if (p < 31) {   // prefetch next step
            const int k0 = ks * 1024 + (p + 1) * 32;
            { int row = t >> 2, g = t & 3;
              aR = *(const uint4*)(Kb + (size_t)row * N_ + k0 + 8*g); }
#pragma unroll
            for (int i = 0; i < 4; i++) {
                int idx = t + i * 256, row = idx >> 3, g = idx & 7;
                bR[i] = *(const float4*)(xb + (size_t)row * N_ + k0 + 4*g);
            }
        }
        const uint32_t Ab = smem_u32(Ah), Bb = smem_u32(Bh);
#pragma unroll
        for (int kc = 0; kc < 32; kc += 16) {
            uint32_t ah[2][4], bh[4][2];
#pragma unroll
            for (int mf = 0; mf < 2; mf++)
                ldsm_x4(ah[mf], Ab + ((m0 + mf*16 + (lane & 15)) * 40 + kc + (lane >> 4) * 8) * 2);
#pragma unroll
            for (int nf = 0; nf < 4; nf += 2) {
                uint32_t rr[4];
                ldsm_x4(rr, Bb + ((cw + nf*8 + (lane & 7) + ((lane >> 4) << 3)) * 40
                                  + kc + ((lane >> 3) & 1) * 8) * 2);
                bh[nf][0] = rr[0]; bh[nf][1] = rr[1];
                bh[nf+1][0] = rr[2]; bh[nf+1][1] = rr[3];
            }
#pragma unroll
            for (int mf = 0; mf < 2; mf++)
#pragma unroll
                for (int nf = 0; nf < 4; nf++) mma_f16(acc[mf][nf], ah[mf], bh[nf]);
        }
    }

    // xsum partial: reduce over 8 column-group threads per row
#pragma unroll
    for (int i = 0; i < 4; i++) {
        float v = xs[i];
        v += __shfl_xor_sync(0xffffffffu, v, 1);
        v += __shfl_xor_sync(0xffffffffu, v, 2);
        v += __shfl_xor_sync(0xffffffffu, v, 4);
        if ((t & 7) == 0)
            g_xsump[ks][b * C_ + c0 + (t >> 3) + 32 * i] = v;
    }
    __syncthreads();

    float* Cs = (float*)(sm + KX_CS);
#pragma unroll
    for (int mf = 0; mf < 2; mf++) {
        int mA = m0 + mf*16 + r, mB = mA + 8;
#pragma unroll
        for (int nf = 0; nf < 4; nf++) {
            int c = cw + nf*8 + kq;
            Cs[mA * 132 + c    ] = acc[mf][nf][0];
            Cs[mA * 132 + c + 1] = acc[mf][nf][1];
            Cs[mB * 132 + c    ] = acc[mf][nf][2];
            Cs[mB * 132 + c + 1] = acc[mf][nf][3];
        }
    }
    __syncthreads();
#pragma unroll
    for (int i = 0; i < 8; i++) {
        int idx = t + i * 256, m = idx >> 5, g = idx & 31;
        float4 v = *(float4*)(Cs + m * 132 + 4*g);
        *(float4*)(g_KXp[ks] + ((size_t)b * M_ + m) * C_ + c0 + 4*g) = v;
    }
}

// fold xsum partials. grid(32), 256 thr
__global__ void xsum_fold() {
    int i = blockIdx.x * 256 + threadIdx.x;   // 8192 elems
    g_xsum[i] = g_xsump[0][i] + g_xsump[1][i] + g_xsump[2][i] + g_xsump[3][i];
}

// vsum: Vsum[b][c] = Wv[c,:].xsum[b,:] + N*bv[c]. grid(128, 16), 128 thr.
__global__ void vsum_kernel(const float* __restrict__ Wv, const float* __restrict__ bv) {
    int b = blockIdx.y;
    int c = blockIdx.x * 4 + (threadIdx.x >> 5);
    int lane = threadIdx.x & 31;
    const float* w  = Wv + (size_t)c * C_;
    const float* xs = g_xsum + b * C_;
    float s = 0.f;
#pragma unroll 4
    for (int i = lane; i < C_; i += 32) s = fmaf(w[i], xs[i], s);
#pragma unroll
    for (int o = 16; o; o >>= 1) s += __shfl_xor_sync(0xffffffffu, s, o);
    if (lane == 0) g_Vsum[b * C_ + c] = s + (float)N_ * bv[c];
}

// mat: D[m][c] = sum_k (sum_ks KXp)[m][k] Wv[c][k]; matT16[c][m] fp16 out
__global__ void mat_gemm(const float* __restrict__ Wv, const float* __restrict__ bv) {
    __shared__ float As[64][65];
    __shared__ float Bs[64][65];
    int b = blockIdx.y, c0 = blockIdx.x * 64, t = threadIdx.x;
    int tm = t >> 4, tc = t & 15;
    float acc[4][4] = {};
    const float* A0 = g_KXp[0] + (size_t)b * M_ * C_;
    const float* A1 = g_KXp[1] + (size_t)b * M_ * C_;
    const float* A2 = g_KXp[2] + (size_t)b * M_ * C_;
    const float* A3 = g_KXp[3] + (size_t)b * M_ * C_;
    const float* Bm = Wv + (size_t)c0 * C_;
    for (int k0 = 0; k0 < C_; k0 += 64) {
#pragma unroll
        for (int i = 0; i < 16; i++) {
            int idx = t + i * 256, rr = idx >> 6, kk = idx & 63;
            size_t off = (size_t)rr * C_ + k0 + kk;
            As[rr][kk] = A0[off] + A1[off] + A2[off] + A3[off];
            Bs[rr][kk] = Bm[off];
        }
        __syncthreads();
#pragma unroll
        for (int kk = 0; kk < 64; kk++) {
            float a[4], bb[4];
#pragma unroll
            for (int i = 0; i < 4; i++) a[i]  = As[tm + 16*i][kk];
#pragma unroll
            for (int j = 0; j < 4; j++) bb[j] = Bs[tc + 16*j][kk];
#pragma unroll
            for (int i = 0; i < 4; i++)
#pragma unroll
                for (int j = 0; j < 4; j++) acc[i][j] = fmaf(a[i], bb[j], acc[i][j]);
        }
        __syncthreads();
    }
#pragma unroll
    for (int i = 0; i < 4; i++) {
        int m = tm + 16*i;
        float kn = g_Knsum[b * M_ + m];
#pragma unroll
        for (int j = 0; j < 4; j++) {
            int c = c0 + tc + 16*j;
            g_matT16[((size_t)b * C_ + c) * M_ + m] = __float2half_rn(acc[i][j] + bv[c] * kn);
        }
    }
}

// =====================================================================
// final_mma: D[128c][128n] = matT @ QnT^T, K=64, fused tailor, ldmatrix.
// grid (32 n, 4 c, 16 b), 256 thr.
// =====================================================================
#define FN_AH 0
#define FN_BH 18432
#define FN_CS 0
#define FN_TL 67584
#define FN_VS 68096
#define FN_KS 68608
#define FN_BYTES 68864

__global__ __launch_bounds__(256, 1) void final_mma(float* __restrict__ out,
                                                    const float* __restrict__ gamma) {
    extern __shared__ __align__(16) char sm[];
    const int t = threadIdx.x, lane = t & 31, wid = t >> 5;
    const int b = blockIdx.z, c0 = blockIdx.y * 128, n0 = blockIdx.x * 128;
    float* tl = (float*)(sm + FN_TL);
    float* vs = (float*)(sm + FN_VS);
    float* ks = (float*)(sm + FN_KS);
    if (t < 128) vs[t] = g_Vsum[b * C_ + c0 + t];
    if (t < 64)  ks[t] = g_Knsum[b * M_ + t];
    __half* Ah = (__half*)(sm + FN_AH);
    __half* Bh = (__half*)(sm + FN_BH);
#pragma unroll
    for (int i = 0; i < 4; i++) {       // A: matT16 rows (c), 64 k
        int idx = t + i * 256, row = idx >> 3, g = idx & 7;
        uint4 v = *(const uint4*)(g_matT16 + ((size_t)b * C_ + c0 + row) * M_ + 8*g);
        *(uint4*)(Ah + row * 72 + 8*g) = v;
    }
#pragma unroll
    for (int i = 0; i < 4; i++) {       // B: QnT16 rows (n), 64 k
        int idx = t + i * 256, row = idx >> 3, g = idx & 7;
        uint4 v = *(const uint4*)(g_QnT16 + ((size_t)b * N_ + n0 + row) * M_ + 8*g);
        *(uint4*)(Bh + row * 72 + 8*g) = v;
    }
    __syncthreads();

    // fused tailor: tl[n] = 1/max(N + Qn[n,:].Knsum, 1e-6)
    if (t < 128) {
        float d = (float)N_;
#pragma unroll
        for (int m = 0; m < 64; m++) d += __half2float(Bh[t * 72 + m]) * ks[m];
        tl[t] = 1.f / fmaxf(d, 1e-6f);
    }

    const int cw = (wid >> 2) * 64, nw = (wid & 3) * 32;
    const int r = lane >> 2, kq = (lane & 3) * 2;
    const uint32_t Ab = smem_u32(Ah), Bb = smem_u32(Bh);
    float acc[4][4][4] = {};
#pragma unroll
    for (int kc = 0; kc < 64; kc += 16) {
        uint32_t ah[4][4], bh[4][2];
#pragma unroll
        for (int mf = 0; mf < 4; mf++)
            ldsm_x4(ah[mf], Ab + ((cw + mf*16 + (lane & 15)) * 72 + kc + (lane >> 4) * 8) * 2);
#pragma unroll
        for (int nf = 0; nf < 4; nf += 2) {
            uint32_t rr[4];
            ldsm_x4(rr, Bb + ((nw + nf*8 + (lane & 7) + ((lane >> 4) << 3)) * 72
                              + kc + ((lane >> 3) & 1) * 8) * 2);
            bh[nf][0] = rr[0]; bh[nf][1] = rr[1];
            bh[nf+1][0] = rr[2]; bh[nf+1][1] = rr[3];
        }
#pragma unroll
        for (int mf = 0; mf < 4; mf++)
#pragma unroll
            for (int nf = 0; nf < 4; nf++) mma_f16(acc[mf][nf], ah[mf], bh[nf]);
    }
    __syncthreads();

    float* Cs = (float*)(sm + FN_CS);
    float gm = gamma[0];
#pragma unroll
    for (int mf = 0; mf < 4; mf++) {
        int cA = cw + mf*16 + r, cB = cA + 8;
        float vA = vs[cA], vB = vs[cB];
#pragma unroll
        for (int nf = 0; nf < 4; nf++) {
            int n = nw + nf*8 + kq;
            Cs[cA * 132 + n    ] = fixv(gm * tl[n    ] * (vA + acc[mf][nf][0]));
            Cs[cA * 132 + n + 1] = fixv(gm * tl[n + 1] * (vA + acc[mf][nf][1]));
            Cs[cB * 132 + n    ] = fixv(gm * tl[n    ] * (vB + acc[mf][nf][2]));
            Cs[cB * 132 + n + 1] = fixv(gm * tl[n + 1] * (vB + acc[mf][nf][3]));
        }
    }
    __syncthreads();
#pragma unroll
    for (int i = 0; i < 16; i++) {
        int idx = t + i * 256, c = idx >> 5, g = idx & 31;
        float4 v = *(float4*)(Cs + c * 132 + 4*g);
        *(float4*)(out + ((size_t)b * C_ + c0 + c) * N_ + n0 + 4*g) = v;
    }
}

// ---------------------------------------------------------------
extern "C" void kernel_launch(void* const* d_in, const int* in_sizes, int n_in,
                              void* d_out, int out_size) {
    const float* x     = (const float*)d_in[0];
    const float* Wq    = (const float*)d_in[1];
    const float* bq    = (const float*)d_in[2];
    const float* Wk    = (const float*)d_in[3];
    const float* bk    = (const float*)d_in[4];
    const float* Wv    = (const float*)d_in[5];
    const float* bv    = (const float*)d_in[6];
    const float* gamma = (const float*)d_in[7];
    float* out = (float*)d_out;

    cudaFuncSetAttribute(qk_mma,    cudaFuncAttributeMaxDynamicSharedMemorySize, QK_BYTES);
    cudaFuncSetAttribute(final_mma, cudaFuncAttributeMaxDynamicSharedMemorySize, FN_BYTES);

    qk_mma     <<<dim3(32, 16), 256, QK_BYTES>>>(x, Wq, bq, Wk, bk);
    rowsum_Kp  <<<16, 64>>>();
    kx_mma     <<<dim3(4, 16, 4), 256>>>(x);
    xsum_fold  <<<32, 256>>>();
    vsum_kernel<<<dim3(128, 16), 128>>>(Wv, bv);
    mat_gemm   <<<dim3(8, 16), 256>>>(Wv, bv);
    final_mma  <<<dim3(32, 4, 16), 256, FN_BYTES>>>(out, gamma);
}

// round 10
// speedup vs baseline: 1.5670x; 1.1295x over previous
#include <cuda_runtime.h>
#include <cuda_fp16.h>
#include <cstdint>
#include <math.h>

#define B_ 16
#define C_ 512
#define N_ 4096
#define M_ 64

// ---------------- scratch (static device globals) ----------------
__device__ __align__(128) __half g_x16 [B_*C_*N_];    // fp16 copy of x (written by qk)
__device__ __align__(128) __half g_QnT16[B_*N_*M_];   // [b][n][m] fp16
__device__ __align__(128) __half g_Kn16 [B_*M_*N_];   // [b][m][n] fp16
__device__ __align__(128) __half g_matT16[B_*C_*M_];  // [b][c][m] fp16
__device__ __align__(128) float g_KXp[4][B_*M_*C_];   // k-split partials
__device__ __align__(128) float g_Knp[B_*32*M_];      // Knsum partials per n-tile
__device__ __align__(128) float g_Knsum[B_*M_];
__device__ __align__(128) float g_xsump[4][B_*C_];    // xsum k-split partials
__device__ __align__(128) float g_Vsum[B_*C_];

// ---------------- fp16 pack helpers ----------------
__device__ __forceinline__ uint32_t hpk2(float a, float b) {
    __half2 t = __floats2half2_rn(a, b);
    return *reinterpret_cast<uint32_t*>(&t);
}
__device__ __forceinline__ uint2 pk4(float4 v) {
    uint2 r; r.x = hpk2(v.x, v.y); r.y = hpk2(v.z, v.w); return r;
}
__device__ __forceinline__ uint32_t smem_u32(const void* p) {
    uint32_t a;
    asm("{ .reg .u64 t; cvta.to.shared.u64 t, %1; cvt.u32.u64 %0, t; }" : "=r"(a) : "l"(p));
    return a;
}

// ---------------- mma / ldmatrix helpers ----------------
__device__ __forceinline__ void mma_f16(float c[4], const uint32_t a[4], const uint32_t b[2]) {
    asm volatile("mma.sync.aligned.m16n8k16.row.col.f32.f16.f16.f32 "
        "{%0,%1,%2,%3}, {%4,%5,%6,%7}, {%8,%9}, {%0,%1,%2,%3};"
        : "+f"(c[0]), "+f"(c[1]), "+f"(c[2]), "+f"(c[3])
        : "r"(a[0]), "r"(a[1]), "r"(a[2]), "r"(a[3]), "r"(b[0]), "r"(b[1]));
}
__device__ __forceinline__ void ldsm_x4(uint32_t r[4], uint32_t a) {
    asm volatile("ldmatrix.sync.aligned.m8n8.x4.shared.b16 {%0,%1,%2,%3}, [%4];"
        : "=r"(r[0]), "=r"(r[1]), "=r"(r[2]), "=r"(r[3]) : "r"(a));
}
__device__ __forceinline__ void ldsm_x4t(uint32_t r[4], uint32_t a) {
    asm volatile("ldmatrix.sync.aligned.m8n8.x4.trans.shared.b16 {%0,%1,%2,%3}, [%4];"
        : "=r"(r[0]), "=r"(r[1]), "=r"(r[2]), "=r"(r[3]) : "r"(a));
}
__device__ __forceinline__ float fixv(float v) {
    if (isnan(v)) return 0.f;
    if (isinf(v)) return v > 0.f ? 1.f : -1.f;
    return v;
}

// =====================================================================
// qk_mma: D[128m(64q|64k)][128n] = Wqk @ x, K=512. grid(32,16), 256 thr
// fp16, ldmatrix x4 (A) + x4.trans (B), 1 sync/iter, double-buffered.
// Also writes g_x16 (fp16 copy of x) from the already-packed B values.
// =====================================================================
#define QK_A(s)  ((s) * 10240)
#define QK_B(s)  (20480 + (s) * 8704)
#define QK_CS 0
#define QK_BIAS 68096
#define QK_INQ 68608
#define QK_INK 69120
#define QK_BYTES 69632

__global__ __launch_bounds__(256, 1) void qk_mma(
    const float* __restrict__ x,  const float* __restrict__ Wq,
    const float* __restrict__ bq, const float* __restrict__ Wk,
    const float* __restrict__ bk) {
    extern __shared__ __align__(16) char sm[];
    const int t = threadIdx.x, lane = t & 31, wid = t >> 5;
    const int b = blockIdx.y, n0 = blockIdx.x * 128;
    const float* xb = x + (size_t)b * C_ * N_;
    float* bias = (float*)(sm + QK_BIAS);
    float* inq  = (float*)(sm + QK_INQ);
    float* ink  = (float*)(sm + QK_INK);
    if (t < 128) bias[t] = (t < 64) ? bq[t] : bk[t - 64];

    const int m0 = (wid >> 2) * 64, nw = (wid & 3) * 32;
    const int r = lane >> 2, kq = (lane & 3) * 2;
    float acc[4][4][4] = {};

    float4 aR[4], xR[4];
#pragma unroll
    for (int i = 0; i < 4; i++) {
        int idx = t + i * 256, row = idx >> 3, g = idx & 7;
        aR[i] = (row < 64) ? *(const float4*)(Wq + (size_t)row * C_ + 4*g)
                           : *(const float4*)(Wk + (size_t)(row - 64) * C_ + 4*g);
    }
#pragma unroll
    for (int i = 0; i < 4; i++) {
        int idx = t + i * 256, kk = idx >> 5, g = idx & 31;
        xR[i] = *(const float4*)(xb + (size_t)kk * N_ + n0 + 4*g);
    }

    for (int p = 0; p < 16; ++p) {
        const int s = p & 1;
        __half* Ah = (__half*)(sm + QK_A(s));
        __half* Bh = (__half*)(sm + QK_B(s));
#pragma unroll
        for (int i = 0; i < 4; i++) {   // A rows (m), 32 k, pitch 40
            int idx = t + i * 256, row = idx >> 3, g = idx & 7;
            *(uint2*)(Ah + row * 40 + 4*g) = pk4(aR[i]);
        }
#pragma unroll
        for (int i = 0; i < 4; i++) {   // B k-major + x16 writeout
            int idx = t + i * 256, kk = idx >> 5, g = idx & 31;
            uint2 h = pk4(xR[i]);
            *(uint2*)(Bh + kk * 136 + 4*g) = h;
            *(uint2*)(g_x16 + ((size_t)(b * C_ + p * 32 + kk)) * N_ + n0 + 4*g) = h;
        }
        __syncthreads();
        if (p < 15) {   // prefetch next k-step
            const int k0 = (p + 1) * 32;
#pragma unroll
            for (int i = 0; i < 4; i++) {
                int idx = t + i * 256, row = idx >> 3, g = idx & 7;
                aR[i] = (row < 64) ? *(const float4*)(Wq + (size_t)row * C_ + k0 + 4*g)
                                   : *(const float4*)(Wk + (size_t)(row - 64) * C_ + k0 + 4*g);
            }
#pragma unroll
            for (int i = 0; i < 4; i++) {
                int idx = t + i * 256, kk = idx >> 5, g = idx & 31;
                xR[i] = *(const float4*)(xb + (size_t)(k0 + kk) * N_ + n0 + 4*g);
            }
        }
        const uint32_t Ab = smem_u32(Ah), Bb = smem_u32(Bh);
#pragma unroll
        for (int kc = 0; kc < 32; kc += 16) {
            uint32_t ah[4][4], bh[4][2];
#pragma unroll
            for (int mf = 0; mf < 4; mf++)
                ldsm_x4(ah[mf], Ab + ((m0 + mf*16 + (lane & 15)) * 40 + kc + (lane >> 4) * 8) * 2);
#pragma unroll
            for (int nf = 0; nf < 4; nf += 2) {
                uint32_t rr[4];
                ldsm_x4t(rr, Bb + ((kc + (lane & 15)) * 136 + nw + nf*8 + (lane >> 4) * 8) * 2);
                bh[nf][0] = rr[0]; bh[nf][1] = rr[1];
                bh[nf+1][0] = rr[2]; bh[nf+1][1] = rr[3];
            }
#pragma unroll
            for (int mf = 0; mf < 4; mf++)
#pragma unroll
                for (int nf = 0; nf < 4; nf++) mma_f16(acc[mf][nf], ah[mf], bh[nf]);
        }
    }
    __syncthreads();   // panels dead; reuse smem as Cs

    float* Cs = (float*)(sm + QK_CS);
#pragma unroll
    for (int mf = 0; mf < 4; mf++) {
        int mA = m0 + mf*16 + r, mB = mA + 8;
        float bA = bias[mA], bB = bias[mB];
#pragma unroll
        for (int nf = 0; nf < 4; nf++) {
            int n = nw + nf*8 + kq;
            Cs[mA * 133 + n    ] = acc[mf][nf][0] + bA;
            Cs[mA * 133 + n + 1] = acc[mf][nf][1] + bA;
            Cs[mB * 133 + n    ] = acc[mf][nf][2] + bB;
            Cs[mB * 133 + n + 1] = acc[mf][nf][3] + bB;
        }
    }
    __syncthreads();
    {   // per-column L2 norms
        int n = t & 127, part = t >> 7, base = part * 64;
        float s = 0.f;
#pragma unroll 8
        for (int m = 0; m < 64; m++) {
            float v = Cs[(base + m) * 133 + n]; s = fmaf(v, v, s);
        }
        float inv = 1.f / fmaxf(sqrtf(s), 1e-6f);
        if (part == 0) inq[n] = inv; else ink[n] = inv;
    }
    __syncthreads();
    // write Kn16[m][n] (fp16) + Knsum partials
#pragma unroll
    for (int i = 0; i < 8; i++) {
        int idx = t + i * 256, m = idx >> 5, g = idx & 31;
        float4 v;
        v.x = Cs[(64 + m) * 133 + 4*g + 0] * ink[4*g + 0];
        v.y = Cs[(64 + m) * 133 + 4*g + 1] * ink[4*g + 1];
        v.z = Cs[(64 + m) * 133 + 4*g + 2] * ink[4*g + 2];
        v.w = Cs[(64 + m) * 133 + 4*g + 3] * ink[4*g + 3];
        *(uint2*)(g_Kn16 + ((size_t)b * M_ + m) * N_ + n0 + 4*g) = pk4(v);
        float rs = v.x + v.y + v.z + v.w;
#pragma unroll
        for (int o = 16; o; o >>= 1) rs += __shfl_xor_sync(0xffffffffu, rs, o);
        if (lane == 0) g_Knp[((size_t)b * 32 + blockIdx.x) * M_ + m] = rs;
    }
    // write QnT16[n][m] (fp16)
#pragma unroll
    for (int i = 0; i < 8; i++) {
        int idx = t + i * 256, n = idx >> 4, g = idx & 15;
        float iq = inq[n];
        float4 v;
        v.x = Cs[(4*g + 0) * 133 + n] * iq;
        v.y = Cs[(4*g + 1) * 133 + n] * iq;
        v.z = Cs[(4*g + 2) * 133 + n] * iq;
        v.w = Cs[(4*g + 3) * 133 + n] * iq;
        *(uint2*)(g_QnT16 + ((size_t)b * N_ + n0 + n) * M_ + 4*g) = pk4(v);
    }
}

// =====================================================================
// kx_mma: D[64m][128c] = Kn @ x16^T over k-slice of 1024. All-fp16 loads,
// no conversions. grid (4, 16, 4), 256 thr, 2 CTAs/SM.
// smem: A(s)=s*5120 (64x40 halfs), B(s)=10240+s*10240 (128x40); Cs at 0
// =====================================================================
#define KX_A(s) ((s) * 5120)
#define KX_B(s) (10240 + (s) * 10240)
#define KX_CS 0
#define KX_BYTES 33792

__global__ __launch_bounds__(256, 2) void kx_mma() {
    __shared__ __align__(16) char sm[KX_BYTES];
    const int t = threadIdx.x, lane = t & 31, wid = t >> 5;
    const int b = blockIdx.y, c0 = blockIdx.x * 128, ks = blockIdx.z;
    const __half* Kb  = g_Kn16 + (size_t)b * M_ * N_;
    const __half* xb16 = g_x16 + ((size_t)b * C_ + c0) * N_;
    const int m0 = (wid >> 2) * 32, cw = (wid & 3) * 32;
    const int r = lane >> 2, kq = (lane & 3) * 2;
    float acc[2][4][4] = {};
    float xs[2] = {0.f, 0.f};

    uint4 aR, bRx[2];
    {   // prologue: load step 0
        const int k0 = ks * 1024;
        { int row = t >> 2, g = t & 3;
          aR = *(const uint4*)(Kb + (size_t)row * N_ + k0 + 8*g); }
#pragma unroll
        for (int i = 0; i < 2; i++) {
            int idx = t + i * 256, row = idx >> 2, g = idx & 3;
            bRx[i] = *(const uint4*)(xb16 + (size_t)row * N_ + k0 + 8*g);
        }
    }

    for (int p = 0; p < 32; ++p) {
        const int s = p & 1;
        __half* Ah = (__half*)(sm + KX_A(s));
        __half* Bh = (__half*)(sm + KX_B(s));
        { int row = t >> 2, g = t & 3;
          *(uint4*)(Ah + row * 40 + 8*g) = aR; }
#pragma unroll
        for (int i = 0; i < 2; i++) {
            int idx = t + i * 256, row = idx >> 2, g = idx & 3;
            const __half2* hp = (const __half2*)&bRx[i];
#pragma unroll
            for (int j = 0; j < 4; j++) {
                float2 f = __half22float2(hp[j]);
                xs[i] += f.x + f.y;
            }
            *(uint4*)(Bh + row * 40 + 8*g) = bRx[i];
        }
        __syncthreads();
        if (p < 31) {   // prefetch next step
            const int k0 = ks * 1024 + (p + 1) * 32;
            { int row = t >> 2, g = t & 3;
              aR = *(const uint4*)(Kb + (size_t)row * N_ + k0 + 8*g); }
#pragma unroll
            for (int i = 0; i < 2; i++) {
                int idx = t + i * 256, row = idx >> 2, g = idx & 3;
                bRx[i] = *(const uint4*)(xb16 + (size_t)row * N_ + k0 + 8*g);
            }
        }
        const uint32_t Ab = smem_u32(Ah), Bb = smem_u32(Bh);
#pragma unroll
        for (int kc = 0; kc < 32; kc += 16) {
            uint32_t ah[2][4], bh[4][2];
#pragma unroll
            for (int mf = 0; mf < 2; mf++)
                ldsm_x4(ah[mf], Ab + ((m0 + mf*16 + (lane & 15)) * 40 + kc + (lane >> 4) * 8) * 2);
#pragma unroll
            for (int nf = 0; nf < 4; nf += 2) {
                uint32_t rr[4];
                ldsm_x4(rr, Bb + ((cw + nf*8 + (lane & 7) + ((lane >> 4) << 3)) * 40
                                  + kc + ((lane >> 3) & 1) * 8) * 2);
                bh[nf][0] = rr[0]; bh[nf][1] = rr[1];
                bh[nf+1][0] = rr[2]; bh[nf+1][1] = rr[3];
            }
#pragma unroll
            for (int mf = 0; mf < 2; mf++)
#pragma unroll
                for (int nf = 0; nf < 4; nf++) mma_f16(acc[mf][nf], ah[mf], bh[nf]);
        }
    }

    // xsum partial: reduce over 4 column-group threads per row
#pragma unroll
    for (int i = 0; i < 2; i++) {
        float v = xs[i];
        v += __shfl_xor_sync(0xffffffffu, v, 1);
        v += __shfl_xor_sync(0xffffffffu, v, 2);
        if ((t & 3) == 0)
            g_xsump[ks][b * C_ + c0 + (t >> 2) + 64 * i] = v;
    }
    __syncthreads();

    float* Cs = (float*)(sm + KX_CS);
#pragma unroll
    for (int mf = 0; mf < 2; mf++) {
        int mA = m0 + mf*16 + r, mB = mA + 8;
#pragma unroll
        for (int nf = 0; nf < 4; nf++) {
            int c = cw + nf*8 + kq;
            Cs[mA * 132 + c    ] = acc[mf][nf][0];
            Cs[mA * 132 + c + 1] = acc[mf][nf][1];
            Cs[mB * 132 + c    ] = acc[mf][nf][2];
            Cs[mB * 132 + c + 1] = acc[mf][nf][3];
        }
    }
    __syncthreads();
#pragma unroll
    for (int i = 0; i < 8; i++) {
        int idx = t + i * 256, m = idx >> 5, g = idx & 31;
        float4 v = *(float4*)(Cs + m * 132 + 4*g);
        *(float4*)(g_KXp[ks] + ((size_t)b * M_ + m) * C_ + c0 + 4*g) = v;
    }
}

// =====================================================================
// vsum (fused xsum fold): Vsum[b][c] = Wv[c,:].xsum[b,:] + N*bv[c].
// grid(128, 16), 128 thr.
// =====================================================================
__global__ void vsum_kernel(const float* __restrict__ Wv, const float* __restrict__ bv) {
    __shared__ float xss[C_];
    int b = blockIdx.y;
    for (int i = threadIdx.x; i < C_; i += 128)
        xss[i] = g_xsump[0][b * C_ + i] + g_xsump[1][b * C_ + i]
               + g_xsump[2][b * C_ + i] + g_xsump[3][b * C_ + i];
    __syncthreads();
    int c = blockIdx.x * 4 + (threadIdx.x >> 5);
    int lane = threadIdx.x & 31;
    const float* w = Wv + (size_t)c * C_;
    float s = 0.f;
#pragma unroll 4
    for (int i = lane; i < C_; i += 32) s = fmaf(w[i], xss[i], s);
#pragma unroll
    for (int o = 16; o; o >>= 1) s += __shfl_xor_sync(0xffffffffu, s, o);
    if (lane == 0) g_Vsum[b * C_ + c] = s + (float)N_ * bv[c];
}

// mat: D[m][c] = sum_k (sum_ks KXp)[m][k] Wv[c][k]; computes Knsum inline.
__global__ void mat_gemm(const float* __restrict__ Wv, const float* __restrict__ bv) {
    __shared__ float As[64][65];
    __shared__ float Bs[64][65];
    __shared__ float ksm[64];
    int b = blockIdx.y, c0 = blockIdx.x * 64, t = threadIdx.x;
    if (t < 64) {
        float s = 0.f;
#pragma unroll
        for (int i = 0; i < 32; i++) s += g_Knp[((size_t)b * 32 + i) * M_ + t];
        ksm[t] = s;
        if (blockIdx.x == 0) g_Knsum[b * M_ + t] = s;
    }
    int tm = t >> 4, tc = t & 15;
    float acc[4][4] = {};
    const float* A0 = g_KXp[0] + (size_t)b * M_ * C_;
    const float* A1 = g_KXp[1] + (size_t)b * M_ * C_;
    const float* A2 = g_KXp[2] + (size_t)b * M_ * C_;
    const float* A3 = g_KXp[3] + (size_t)b * M_ * C_;
    const float* Bm = Wv + (size_t)c0 * C_;
    for (int k0 = 0; k0 < C_; k0 += 64) {
#pragma unroll
        for (int i = 0; i < 16; i++) {
            int idx = t + i * 256, rr = idx >> 6, kk = idx & 63;
            size_t off = (size_t)rr * C_ + k0 + kk;
            As[rr][kk] = A0[off] + A1[off] + A2[off] + A3[off];
            Bs[rr][kk] = Bm[off];
        }
        __syncthreads();
#pragma unroll
        for (int kk = 0; kk < 64; kk++) {
            float a[4], bb[4];
#pragma unroll
            for (int i = 0; i < 4; i++) a[i]  = As[tm + 16*i][kk];
#pragma unroll
            for (int j = 0; j < 4; j++) bb[j] = Bs[tc + 16*j][kk];
#pragma unroll
            for (int i = 0; i < 4; i++)
#pragma unroll
                for (int j = 0; j < 4; j++) acc[i][j] = fmaf(a[i], bb[j], acc[i][j]);
        }
        __syncthreads();
    }
#pragma unroll
    for (int i = 0; i < 4; i++) {
        int m = tm + 16*i;
        float kn = ksm[m];
#pragma unroll
        for (int j = 0; j < 4; j++) {
            int c = c0 + tc + 16*j;
            g_matT16[((size_t)b * C_ + c) * M_ + m] = __float2half_rn(acc[i][j] + bv[c] * kn);
        }
    }
}

// =====================================================================
// final_mma: D[128c][128n] = matT @ QnT^T, K=64, fused tailor, ldmatrix.
// grid (32 n, 4 c, 16 b), 256 thr, 2 CTAs/SM.
// =====================================================================
#define FN_AH 0
#define FN_BH 18432
#define FN_CS 0
#define FN_TL 67584
#define FN_VS 68096
#define FN_KS 68608
#define FN_BYTES 68864

__global__ __launch_bounds__(256, 2) void final_mma(float* __restrict__ out,
                                                    const float* __restrict__ gamma) {
    extern __shared__ __align__(16) char sm[];
    const int t = threadIdx.x, lane = t & 31, wid = t >> 5;
    const int b = blockIdx.z, c0 = blockIdx.y * 128, n0 = blockIdx.x * 128;
    float* tl = (float*)(sm + FN_TL);
    float* vs = (float*)(sm + FN_VS);
    float* ks = (float*)(sm + FN_KS);
    if (t < 128) vs[t] = g_Vsum[b * C_ + c0 + t];
    if (t < 64)  ks[t] = g_Knsum[b * M_ + t];
    __half* Ah = (__half*)(sm + FN_AH);
    __half* Bh = (__half*)(sm + FN_BH);
#pragma unroll
    for (int i = 0; i < 4; i++) {       // A: matT16 rows (c), 64 k
        int idx = t + i * 256, row = idx >> 3, g = idx & 7;
        uint4 v = *(const uint4*)(g_matT16 + ((size_t)b * C_ + c0 + row) * M_ + 8*g);
        *(uint4*)(Ah + row * 72 + 8*g) = v;
    }
#pragma unroll
    for (int i = 0; i < 4; i++) {       // B: QnT16 rows (n), 64 k
        int idx = t + i * 256, row = idx >> 3, g = idx & 7;
        uint4 v = *(const uint4*)(g_QnT16 + ((size_t)b * N_ + n0 + row) * M_ + 8*g);
        *(uint4*)(Bh + row * 72 + 8*g) = v;
    }
    __syncthreads();

    // fused tailor: tl[n] = 1/max(N + Qn[n,:].Knsum, 1e-6)
    if (t < 128) {
        float d = (float)N_;
#pragma unroll
        for (int m = 0; m < 64; m++) d += __half2float(Bh[t * 72 + m]) * ks[m];
        tl[t] = 1.f / fmaxf(d, 1e-6f);
    }

    const int cw = (wid >> 2) * 64, nw = (wid & 3) * 32;
    const int r = lane >> 2, kq = (lane & 3) * 2;
    const uint32_t Ab = smem_u32(Ah), Bb = smem_u32(Bh);
    float acc[4][4][4] = {};
#pragma unroll
    for (int kc = 0; kc < 64; kc += 16) {
        uint32_t ah[4][4], bh[4][2];
#pragma unroll
        for (int mf = 0; mf < 4; mf++)
            ldsm_x4(ah[mf], Ab + ((cw + mf*16 + (lane & 15)) * 72 + kc + (lane >> 4) * 8) * 2);
#pragma unroll
        for (int nf = 0; nf < 4; nf += 2) {
            uint32_t rr[4];
            ldsm_x4(rr, Bb + ((nw + nf*8 + (lane & 7) + ((lane >> 4) << 3)) * 72
                              + kc + ((lane >> 3) & 1) * 8) * 2);
            bh[nf][0] = rr[0]; bh[nf][1] = rr[1];
            bh[nf+1][0] = rr[2]; bh[nf+1][1] = rr[3];
        }
#pragma unroll
        for (int mf = 0; mf < 4; mf++)
#pragma unroll
            for (int nf = 0; nf < 4; nf++) mma_f16(acc[mf][nf], ah[mf], bh[nf]);
    }
    __syncthreads();

    float* Cs = (float*)(sm + FN_CS);
    float gm = gamma[0];
#pragma unroll
    for (int mf = 0; mf < 4; mf++) {
        int cA = cw + mf*16 + r, cB = cA + 8;
        float vA = vs[cA], vB = vs[cB];
#pragma unroll
        for (int nf = 0; nf < 4; nf++) {
            int n = nw + nf*8 + kq;
            Cs[cA * 132 + n    ] = fixv(gm * tl[n    ] * (vA + acc[mf][nf][0]));
            Cs[cA * 132 + n + 1] = fixv(gm * tl[n + 1] * (vA + acc[mf][nf][1]));
            Cs[cB * 132 + n    ] = fixv(gm * tl[n    ] * (vB + acc[mf][nf][2]));
            Cs[cB * 132 + n + 1] = fixv(gm * tl[n + 1] * (vB + acc[mf][nf][3]));
        }
    }
    __syncthreads();
#pragma unroll
    for (int i = 0; i < 16; i++) {
        int idx = t + i * 256, c = idx >> 5, g = idx & 31;
        float4 v = *(float4*)(Cs + c * 132 + 4*g);
        *(float4*)(out + ((size_t)b * C_ + c0 + c) * N_ + n0 + 4*g) = v;
    }
}

// ---------------------------------------------------------------
extern "C" void kernel_launch(void* const* d_in, const int* in_sizes, int n_in,
                              void* d_out, int out_size) {
    const float* x     = (const float*)d_in[0];
    const float* Wq    = (const float*)d_in[1];
    const float* bq    = (const float*)d_in[2];
    const float* Wk    = (const float*)d_in[3];
    const float* bk    = (const float*)d_in[4];
    const float* Wv    = (const float*)d_in[5];
    const float* bv    = (const float*)d_in[6];
    const float* gamma = (const float*)d_in[7];
    float* out = (float*)d_out;

    cudaFuncSetAttribute(qk_mma,    cudaFuncAttributeMaxDynamicSharedMemorySize, QK_BYTES);
    cudaFuncSetAttribute(final_mma, cudaFuncAttributeMaxDynamicSharedMemorySize, FN_BYTES);

    qk_mma     <<<dim3(32, 16), 256, QK_BYTES>>>(x, Wq, bq, Wk, bk);
    kx_mma     <<<dim3(4, 16, 4), 256>>>();
    vsum_kernel<<<dim3(128, 16), 128>>>(Wv, bv);
    mat_gemm   <<<dim3(8, 16), 256>>>(Wv, bv);
    final_mma  <<<dim3(32, 4, 16), 256, FN_BYTES>>>(out, gamma);
}

// round 11
// speedup vs baseline: 1.7427x; 1.1121x over previous
#include <cuda_runtime.h>
#include <cuda_fp16.h>
#include <cstdint>
#include <math.h>

#define B_ 16
#define C_ 512
#define N_ 4096
#define M_ 64

// ---------------- scratch (static device globals) ----------------
__device__ __align__(128) __half g_x16 [B_*C_*N_];    // fp16 copy of x (written by qk)
__device__ __align__(128) __half g_QnT16[B_*N_*M_];   // [b][n][m] fp16
__device__ __align__(128) __half g_Kn16 [B_*M_*N_];   // [b][m][n] fp16
__device__ __align__(128) __half g_matT16[B_*C_*M_];  // [b][c][m] fp16
__device__ __align__(128) float g_KXp[4][B_*M_*C_];   // k-split partials
__device__ __align__(128) float g_Knp[B_*32*M_];      // Knsum partials per n-tile
__device__ __align__(128) float g_Knsum[B_*M_];
__device__ __align__(128) float g_xsump[4][B_*C_];    // xsum k-split partials
__device__ __align__(128) float g_Vsum[B_*C_];

// ---------------- fp16 pack helpers ----------------
__device__ __forceinline__ uint32_t hpk2(float a, float b) {
    __half2 t = __floats2half2_rn(a, b);
    return *reinterpret_cast<uint32_t*>(&t);
}
__device__ __forceinline__ uint2 pk4(float4 v) {
    uint2 r; r.x = hpk2(v.x, v.y); r.y = hpk2(v.z, v.w); return r;
}
__device__ __forceinline__ uint32_t smem_u32(const void* p) {
    uint32_t a;
    asm("{ .reg .u64 t; cvta.to.shared.u64 t, %1; cvt.u32.u64 %0, t; }" : "=r"(a) : "l"(p));
    return a;
}

// ---------------- mma / ldmatrix helpers ----------------
__device__ __forceinline__ void mma_f16(float c[4], const uint32_t a[4], const uint32_t b[2]) {
    asm volatile("mma.sync.aligned.m16n8k16.row.col.f32.f16.f16.f32 "
        "{%0,%1,%2,%3}, {%4,%5,%6,%7}, {%8,%9}, {%0,%1,%2,%3};"
        : "+f"(c[0]), "+f"(c[1]), "+f"(c[2]), "+f"(c[3])
        : "r"(a[0]), "r"(a[1]), "r"(a[2]), "r"(a[3]), "r"(b[0]), "r"(b[1]));
}
__device__ __forceinline__ void ldsm_x4(uint32_t r[4], uint32_t a) {
    asm volatile("ldmatrix.sync.aligned.m8n8.x4.shared.b16 {%0,%1,%2,%3}, [%4];"
        : "=r"(r[0]), "=r"(r[1]), "=r"(r[2]), "=r"(r[3]) : "r"(a));
}
__device__ __forceinline__ void ldsm_x4t(uint32_t r[4], uint32_t a) {
    asm volatile("ldmatrix.sync.aligned.m8n8.x4.trans.shared.b16 {%0,%1,%2,%3}, [%4];"
        : "=r"(r[0]), "=r"(r[1]), "=r"(r[2]), "=r"(r[3]) : "r"(a));
}
__device__ __forceinline__ float fixv(float v) {
    if (isnan(v)) return 0.f;
    if (isinf(v)) return v > 0.f ? 1.f : -1.f;
    return v;
}

// =====================================================================
// qk_mma: D[128m(64q|64k)][128n] = Wqk @ x, K=512. grid(32,16), 256 thr
// fp16, ldmatrix x4 (A) + x4.trans (B), 1 sync/iter, double-buffered.
// Also writes g_x16 (fp16 copy of x) from the already-packed B values.
// =====================================================================
#define QK_A(s)  ((s) * 10240)
#define QK_B(s)  (20480 + (s) * 8704)
#define QK_CS 0
#define QK_BIAS 68096
#define QK_INQ 68608
#define QK_INK 69120
#define QK_BYTES 69632

__global__ __launch_bounds__(256, 1) void qk_mma(
    const float* __restrict__ x,  const float* __restrict__ Wq,
    const float* __restrict__ bq, const float* __restrict__ Wk,
    const float* __restrict__ bk) {
    extern __shared__ __align__(16) char sm[];
    const int t = threadIdx.x, lane = t & 31, wid = t >> 5;
    const int b = blockIdx.y, n0 = blockIdx.x * 128;
    const float* xb = x + (size_t)b * C_ * N_;
    float* bias = (float*)(sm + QK_BIAS);
    float* inq  = (float*)(sm + QK_INQ);
    float* ink  = (float*)(sm + QK_INK);
    if (t < 128) bias[t] = (t < 64) ? bq[t] : bk[t - 64];

    const int m0 = (wid >> 2) * 64, nw = (wid & 3) * 32;
    const int r = lane >> 2, kq = (lane & 3) * 2;
    float acc[4][4][4] = {};

    float4 aR[4], xR[4];
#pragma unroll
    for (int i = 0; i < 4; i++) {
        int idx = t + i * 256, row = idx >> 3, g = idx & 7;
        aR[i] = (row < 64) ? *(const float4*)(Wq + (size_t)row * C_ + 4*g)
                           : *(const float4*)(Wk + (size_t)(row - 64) * C_ + 4*g);
    }
#pragma unroll
    for (int i = 0; i < 4; i++) {
        int idx = t + i * 256, kk = idx >> 5, g = idx & 31;
        xR[i] = *(const float4*)(xb + (size_t)kk * N_ + n0 + 4*g);
    }

    for (int p = 0; p < 16; ++p) {
        const int s = p & 1;
        __half* Ah = (__half*)(sm + QK_A(s));
        __half* Bh = (__half*)(sm + QK_B(s));
#pragma unroll
        for (int i = 0; i < 4; i++) {   // A rows (m), 32 k, pitch 40
            int idx = t + i * 256, row = idx >> 3, g = idx & 7;
            *(uint2*)(Ah + row * 40 + 4*g) = pk4(aR[i]);
        }
#pragma unroll
        for (int i = 0; i < 4; i++) {   // B k-major + x16 writeout
            int idx = t + i * 256, kk = idx >> 5, g = idx & 31;
            uint2 h = pk4(xR[i]);
            *(uint2*)(Bh + kk * 136 + 4*g) = h;
            *(uint2*)(g_x16 + ((size_t)(b * C_ + p * 32 + kk)) * N_ + n0 + 4*g) = h;
        }
        __syncthreads();
        if (p < 15) {   // prefetch next k-step
            const int k0 = (p + 1) * 32;
#pragma unroll
            for (int i = 0; i < 4; i++) {
                int idx = t + i * 256, row = idx >> 3, g = idx & 7;
                aR[i] = (row < 64) ? *(const float4*)(Wq + (size_t)row * C_ + k0 + 4*g)
                                   : *(const float4*)(Wk + (size_t)(row - 64) * C_ + k0 + 4*g);
            }
#pragma unroll
            for (int i = 0; i < 4; i++) {
                int idx = t + i * 256, kk = idx >> 5, g = idx & 31;
                xR[i] = *(const float4*)(xb + (size_t)(k0 + kk) * N_ + n0 + 4*g);
            }
        }
        const uint32_t Ab = smem_u32(Ah), Bb = smem_u32(Bh);
#pragma unroll
        for (int kc = 0; kc < 32; kc += 16) {
            uint32_t ah[4][4], bh[4][2];
#pragma unroll
            for (int mf = 0; mf < 4; mf++)
                ldsm_x4(ah[mf], Ab + ((m0 + mf*16 + (lane & 15)) * 40 + kc + (lane >> 4) * 8) * 2);
#pragma unroll
            for (int nf = 0; nf < 4; nf += 2) {
                uint32_t rr[4];
                ldsm_x4t(rr, Bb + ((kc + (lane & 15)) * 136 + nw + nf*8 + (lane >> 4) * 8) * 2);
                bh[nf][0] = rr[0]; bh[nf][1] = rr[1];
                bh[nf+1][0] = rr[2]; bh[nf+1][1] = rr[3];
            }
#pragma unroll
            for (int mf = 0; mf < 4; mf++)
#pragma unroll
                for (int nf = 0; nf < 4; nf++) mma_f16(acc[mf][nf], ah[mf], bh[nf]);
        }
    }
    __syncthreads();   // panels dead; reuse smem as Cs

    float* Cs = (float*)(sm + QK_CS);
#pragma unroll
    for (int mf = 0; mf < 4; mf++) {
        int mA = m0 + mf*16 + r, mB = mA + 8;
        float bA = bias[mA], bB = bias[mB];
#pragma unroll
        for (int nf = 0; nf < 4; nf++) {
            int n = nw + nf*8 + kq;
            Cs[mA * 133 + n    ] = acc[mf][nf][0] + bA;
            Cs[mA * 133 + n + 1] = acc[mf][nf][1] + bA;
            Cs[mB * 133 + n    ] = acc[mf][nf][2] + bB;
            Cs[mB * 133 + n + 1] = acc[mf][nf][3] + bB;
        }
    }
    __syncthreads();
    {   // per-column L2 norms
        int n = t & 127, part = t >> 7, base = part * 64;
        float s = 0.f;
#pragma unroll 8
        for (int m = 0; m < 64; m++) {
            float v = Cs[(base + m) * 133 + n]; s = fmaf(v, v, s);
        }
        float inv = 1.f / fmaxf(sqrtf(s), 1e-6f);
        if (part == 0) inq[n] = inv; else ink[n] = inv;
    }
    __syncthreads();
    // write Kn16[m][n] (fp16) + Knsum partials
#pragma unroll
    for (int i = 0; i < 8; i++) {
        int idx = t + i * 256, m = idx >> 5, g = idx & 31;
        float4 v;
        v.x = Cs[(64 + m) * 133 + 4*g + 0] * ink[4*g + 0];
        v.y = Cs[(64 + m) * 133 + 4*g + 1] * ink[4*g + 1];
        v.z = Cs[(64 + m) * 133 + 4*g + 2] * ink[4*g + 2];
        v.w = Cs[(64 + m) * 133 + 4*g + 3] * ink[4*g + 3];
        *(uint2*)(g_Kn16 + ((size_t)b * M_ + m) * N_ + n0 + 4*g) = pk4(v);
        float rs = v.x + v.y + v.z + v.w;
#pragma unroll
        for (int o = 16; o; o >>= 1) rs += __shfl_xor_sync(0xffffffffu, rs, o);
        if (lane == 0) g_Knp[((size_t)b * 32 + blockIdx.x) * M_ + m] = rs;
    }
    // write QnT16[n][m] (fp16)
#pragma unroll
    for (int i = 0; i < 8; i++) {
        int idx = t + i * 256, n = idx >> 4, g = idx & 15;
        float iq = inq[n];
        float4 v;
        v.x = Cs[(4*g + 0) * 133 + n] * iq;
        v.y = Cs[(4*g + 1) * 133 + n] * iq;
        v.z = Cs[(4*g + 2) * 133 + n] * iq;
        v.w = Cs[(4*g + 3) * 133 + n] * iq;
        *(uint2*)(g_QnT16 + ((size_t)b * N_ + n0 + n) * M_ + 4*g) = pk4(v);
    }
}

// =====================================================================
// kx_mma: D[64m][128c] = Kn @ x16^T over k-slice of 1024. All-fp16 loads.
// grid (4, 16, 4), 256 thr, 2 CTAs/SM.
// =====================================================================
#define KX_A(s) ((s) * 5120)
#define KX_B(s) (10240 + (s) * 10240)
#define KX_CS 0
#define KX_BYTES 33792

__global__ __launch_bounds__(256, 2) void kx_mma() {
    __shared__ __align__(16) char sm[KX_BYTES];
    const int t = threadIdx.x, lane = t & 31, wid = t >> 5;
    const int b = blockIdx.y, c0 = blockIdx.x * 128, ks = blockIdx.z;
    const __half* Kb  = g_Kn16 + (size_t)b * M_ * N_;
    const __half* xb16 = g_x16 + ((size_t)b * C_ + c0) * N_;
    const int m0 = (wid >> 2) * 32, cw = (wid & 3) * 32;
    const int r = lane >> 2, kq = (lane & 3) * 2;
    float acc[2][4][4] = {};
    float xs[2] = {0.f, 0.f};

    uint4 aR, bRx[2];
    {   // prologue: load step 0
        const int k0 = ks * 1024;
        { int row = t >> 2, g = t & 3;
          aR = *(const uint4*)(Kb + (size_t)row * N_ + k0 + 8*g); }
#pragma unroll
        for (int i = 0; i < 2; i++) {
            int idx = t + i * 256, row = idx >> 2, g = idx & 3;
            bRx[i] = *(const uint4*)(xb16 + (size_t)row * N_ + k0 + 8*g);
        }
    }

    for (int p = 0; p < 32; ++p) {
        const int s = p & 1;
        __half* Ah = (__half*)(sm + KX_A(s));
        __half* Bh = (__half*)(sm + KX_B(s));
        { int row = t >> 2, g = t & 3;
          *(uint4*)(Ah + row * 40 + 8*g) = aR; }
#pragma unroll
        for (int i = 0; i < 2; i++) {
            int idx = t + i * 256, row = idx >> 2, g = idx & 3;
            const __half2* hp = (const __half2*)&bRx[i];
#pragma unroll
            for (int j = 0; j < 4; j++) {
                float2 f = __half22float2(hp[j]);
                xs[i] += f.x + f.y;
            }
            *(uint4*)(Bh + row * 40 + 8*g) = bRx[i];
        }
        __syncthreads();
        if (p < 31) {   // prefetch next step
            const int k0 = ks * 1024 + (p + 1) * 32;
            { int row = t >> 2, g = t & 3;
              aR = *(const uint4*)(Kb + (size_t)row * N_ + k0 + 8*g); }
#pragma unroll
            for (int i = 0; i < 2; i++) {
                int idx = t + i * 256, row = idx >> 2, g = idx & 3;
                bRx[i] = *(const uint4*)(xb16 + (size_t)row * N_ + k0 + 8*g);
            }
        }
        const uint32_t Ab = smem_u32(Ah), Bb = smem_u32(Bh);
#pragma unroll
        for (int kc = 0; kc < 32; kc += 16) {
            uint32_t ah[2][4], bh[4][2];
#pragma unroll
            for (int mf = 0; mf < 2; mf++)
                ldsm_x4(ah[mf], Ab + ((m0 + mf*16 + (lane & 15)) * 40 + kc + (lane >> 4) * 8) * 2);
#pragma unroll
            for (int nf = 0; nf < 4; nf += 2) {
                uint32_t rr[4];
                ldsm_x4(rr, Bb + ((cw + nf*8 + (lane & 7) + ((lane >> 4) << 3)) * 40
                                  + kc + ((lane >> 3) & 1) * 8) * 2);
                bh[nf][0] = rr[0]; bh[nf][1] = rr[1];
                bh[nf+1][0] = rr[2]; bh[nf+1][1] = rr[3];
            }
#pragma unroll
            for (int mf = 0; mf < 2; mf++)
#pragma unroll
                for (int nf = 0; nf < 4; nf++) mma_f16(acc[mf][nf], ah[mf], bh[nf]);
        }
    }

    // xsum partial: reduce over 4 column-group threads per row
#pragma unroll
    for (int i = 0; i < 2; i++) {
        float v = xs[i];
        v += __shfl_xor_sync(0xffffffffu, v, 1);
        v += __shfl_xor_sync(0xffffffffu, v, 2);
        if ((t & 3) == 0)
            g_xsump[ks][b * C_ + c0 + (t >> 2) + 64 * i] = v;
    }
    __syncthreads();

    float* Cs = (float*)(sm + KX_CS);
#pragma unroll
    for (int mf = 0; mf < 2; mf++) {
        int mA = m0 + mf*16 + r, mB = mA + 8;
#pragma unroll
        for (int nf = 0; nf < 4; nf++) {
            int c = cw + nf*8 + kq;
            Cs[mA * 132 + c    ] = acc[mf][nf][0];
            Cs[mA * 132 + c + 1] = acc[mf][nf][1];
            Cs[mB * 132 + c    ] = acc[mf][nf][2];
            Cs[mB * 132 + c + 1] = acc[mf][nf][3];
        }
    }
    __syncthreads();
#pragma unroll
    for (int i = 0; i < 8; i++) {
        int idx = t + i * 256, m = idx >> 5, g = idx & 31;
        float4 v = *(float4*)(Cs + m * 132 + 4*g);
        *(float4*)(g_KXp[ks] + ((size_t)b * M_ + m) * C_ + c0 + 4*g) = v;
    }
}

// =====================================================================
// vsum (fused xsum fold): Vsum[b][c] = Wv[c,:].xsum[b,:] + N*bv[c].
// grid(128, 16), 128 thr.
// =====================================================================
__global__ void vsum_kernel(const float* __restrict__ Wv, const float* __restrict__ bv) {
    __shared__ float xss[C_];
    int b = blockIdx.y;
    for (int i = threadIdx.x; i < C_; i += 128)
        xss[i] = g_xsump[0][b * C_ + i] + g_xsump[1][b * C_ + i]
               + g_xsump[2][b * C_ + i] + g_xsump[3][b * C_ + i];
    __syncthreads();
    int c = blockIdx.x * 4 + (threadIdx.x >> 5);
    int lane = threadIdx.x & 31;
    const float* w = Wv + (size_t)c * C_;
    float s = 0.f;
#pragma unroll 4
    for (int i = lane; i < C_; i += 32) s = fmaf(w[i], xss[i], s);
#pragma unroll
    for (int o = 16; o; o >>= 1) s += __shfl_xor_sync(0xffffffffu, s, o);
    if (lane == 0) g_Vsum[b * C_ + c] = s + (float)N_ * bv[c];
}

// =====================================================================
// mat_mma: matT[128c][64m] = Wv @ (sum KXp)^T, K=512. fp16 mma, ldmatrix,
// double-buffered, 1 sync/iter. grid (4 c-tiles, 16 b), 256 thr.
// smem: A(s)=s*10240 (128x40 halfs), B(s)=20480+s*5120 (64x40 halfs);
// epilogue Cs at 0 (128*68*4=34816); ksm 34816, bvs 35072 -> 35584
// =====================================================================
#define MT_A(s) ((s) * 10240)
#define MT_B(s) (20480 + (s) * 5120)
#define MT_CS 0
#define MT_KS 34816
#define MT_BV 35072
#define MT_BYTES 35584

__global__ __launch_bounds__(256, 1) void mat_mma(const float* __restrict__ Wv,
                                                  const float* __restrict__ bv) {
    __shared__ __align__(16) char sm[MT_BYTES];
    const int t = threadIdx.x, lane = t & 31, wid = t >> 5;
    const int b = blockIdx.y, c0 = blockIdx.x * 128;
    float* ksm = (float*)(sm + MT_KS);
    float* bvs = (float*)(sm + MT_BV);
    if (t < 64) {   // fold Knsum partials; publish for final_mma
        float s = 0.f;
#pragma unroll
        for (int i = 0; i < 32; i++) s += g_Knp[((size_t)b * 32 + i) * M_ + t];
        ksm[t] = s;
        if (blockIdx.x == 0) g_Knsum[b * M_ + t] = s;
    }
    if (t < 128) bvs[t] = bv[c0 + t];

    const float* A0 = g_KXp[0] + (size_t)b * M_ * C_;
    const float* A1 = g_KXp[1] + (size_t)b * M_ * C_;
    const float* A2 = g_KXp[2] + (size_t)b * M_ * C_;
    const float* A3 = g_KXp[3] + (size_t)b * M_ * C_;

    const int cw = (wid >> 2) * 64, nw = (wid & 3) * 16;
    const int r = lane >> 2, kq = (lane & 3) * 2;
    float acc[4][2][4] = {};

    float4 aR[4], bR[2];
    {   // prologue: k-step 0
#pragma unroll
        for (int i = 0; i < 4; i++) {   // Wv rows (c)
            int idx = t + i * 256, row = idx >> 3, g = idx & 7;
            aR[i] = *(const float4*)(Wv + (size_t)(c0 + row) * C_ + 4*g);
        }
#pragma unroll
        for (int i = 0; i < 2; i++) {   // KX fold rows (m)
            int idx = t + i * 256, row = idx >> 3, g = idx & 7;
            size_t off = (size_t)row * C_ + 4*g;
            float4 v0 = *(const float4*)(A0 + off), v1 = *(const float4*)(A1 + off);
            float4 v2 = *(const float4*)(A2 + off), v3 = *(const float4*)(A3 + off);
            bR[i] = make_float4(v0.x+v1.x+v2.x+v3.x, v0.y+v1.y+v2.y+v3.y,
                                v0.z+v1.z+v2.z+v3.z, v0.w+v1.w+v2.w+v3.w);
        }
    }

    for (int p = 0; p < 16; ++p) {
        const int s = p & 1;
        __half* Ah = (__half*)(sm + MT_A(s));
        __half* Bh = (__half*)(sm + MT_B(s));
#pragma unroll
        for (int i = 0; i < 4; i++) {
            int idx = t + i * 256, row = idx >> 3, g = idx & 7;
            *(uint2*)(Ah + row * 40 + 4*g) = pk4(aR[i]);
        }
#pragma unroll
        for (int i = 0; i < 2; i++) {
            int idx = t + i * 256, row = idx >> 3, g = idx & 7;
            *(uint2*)(Bh + row * 40 + 4*g) = pk4(bR[i]);
        }
        __syncthreads();
        if (p < 15) {   // prefetch next k-step
            const int k0 = (p + 1) * 32;
#pragma unroll
            for (int i = 0; i < 4; i++) {
                int idx = t + i * 256, row = idx >> 3, g = idx & 7;
                aR[i] = *(const float4*)(Wv + (size_t)(c0 + row) * C_ + k0 + 4*g);
            }
#pragma unroll
            for (int i = 0; i < 2; i++) {
                int idx = t + i * 256, row = idx >> 3, g = idx & 7;
                size_t off = (size_t)row * C_ + k0 + 4*g;
                float4 v0 = *(const float4*)(A0 + off), v1 = *(const float4*)(A1 + off);
                float4 v2 = *(const float4*)(A2 + off), v3 = *(const float4*)(A3 + off);
                bR[i] = make_float4(v0.x+v1.x+v2.x+v3.x, v0.y+v1.y+v2.y+v3.y,
                                    v0.z+v1.z+v2.z+v3.z, v0.w+v1.w+v2.w+v3.w);
            }
        }
        const uint32_t Ab = smem_u32(Ah), Bb = smem_u32(Bh);
#pragma unroll
        for (int kc = 0; kc < 32; kc += 16) {
            uint32_t ah[4][4], bh[2][2];
#pragma unroll
            for (int mf = 0; mf < 4; mf++)
                ldsm_x4(ah[mf], Ab + ((cw + mf*16 + (lane & 15)) * 40 + kc + (lane >> 4) * 8) * 2);
            {
                uint32_t rr[4];
                ldsm_x4(rr, Bb + ((nw + (lane & 7) + ((lane >> 4) << 3)) * 40
                                  + kc + ((lane >> 3) & 1) * 8) * 2);
                bh[0][0] = rr[0]; bh[0][1] = rr[1];
                bh[1][0] = rr[2]; bh[1][1] = rr[3];
            }
#pragma unroll
            for (int mf = 0; mf < 4; mf++)
#pragma unroll
                for (int nf = 0; nf < 2; nf++) mma_f16(acc[mf][nf], ah[mf], bh[nf]);
        }
    }
    __syncthreads();   // panels dead; reuse smem as Cs

    float* Cs = (float*)(sm + MT_CS);
#pragma unroll
    for (int mf = 0; mf < 4; mf++) {
        int cA = cw + mf*16 + r, cB = cA + 8;
        float bA = bvs[cA], bB = bvs[cB];
#pragma unroll
        for (int nf = 0; nf < 2; nf++) {
            int m = nw + nf*8 + kq;
            Cs[cA * 68 + m    ] = acc[mf][nf][0] + bA * ksm[m    ];
            Cs[cA * 68 + m + 1] = acc[mf][nf][1] + bA * ksm[m + 1];
            Cs[cB * 68 + m    ] = acc[mf][nf][2] + bB * ksm[m    ];
            Cs[cB * 68 + m + 1] = acc[mf][nf][3] + bB * ksm[m + 1];
        }
    }
    __syncthreads();
#pragma unroll
    for (int i = 0; i < 4; i++) {   // write matT16 [c][m], 8 halfs per task
        int idx = t + i * 256, row = idx >> 3, g = idx & 7;
        float4 v0 = *(float4*)(Cs + row * 68 + 8*g);
        float4 v1 = *(float4*)(Cs + row * 68 + 8*g + 4);
        uint2 h0 = pk4(v0), h1 = pk4(v1);
        uint4 o = make_uint4(h0.x, h0.y, h1.x, h1.y);
        *(uint4*)(g_matT16 + ((size_t)b * C_ + c0 + row) * M_ + 8*g) = o;
    }
}

// =====================================================================
// final_mma: D[128c][128n] = matT @ QnT^T, K=64, fused tailor, ldmatrix.
// grid (32 n, 4 c, 16 b), 256 thr, 2 CTAs/SM.
// =====================================================================
#define FN_AH 0
#define FN_BH 18432
#define FN_CS 0
#define FN_TL 67584
#define FN_VS 68096
#define FN_KS 68608
#define FN_BYTES 68864

__global__ __launch_bounds__(256, 2) void final_mma(float* __restrict__ out,
                                                    const float* __restrict__ gamma) {
    extern __shared__ __align__(16) char sm[];
    const int t = threadIdx.x, lane = t & 31, wid = t >> 5;
    const int b = blockIdx.z, c0 = blockIdx.y * 128, n0 = blockIdx.x * 128;
    float* tl = (float*)(sm + FN_TL);
    float* vs = (float*)(sm + FN_VS);
    float* ks = (float*)(sm + FN_KS);
    if (t < 128) vs[t] = g_Vsum[b * C_ + c0 + t];
    if (t < 64)  ks[t] = g_Knsum[b * M_ + t];
    __half* Ah = (__half*)(sm + FN_AH);
    __half* Bh = (__half*)(sm + FN_BH);
#pragma unroll
    for (int i = 0; i < 4; i++) {       // A: matT16 rows (c), 64 k
        int idx = t + i * 256, row = idx >> 3, g = idx & 7;
        uint4 v = *(const uint4*)(g_matT16 + ((size_t)b * C_ + c0 + row) * M_ + 8*g);
        *(uint4*)(Ah + row * 72 + 8*g) = v;
    }
#pragma unroll
    for (int i = 0; i < 4; i++) {       // B: QnT16 rows (n), 64 k
        int idx = t + i * 256, row = idx >> 3, g = idx & 7;
        uint4 v = *(const uint4*)(g_QnT16 + ((size_t)b * N_ + n0 + row) * M_ + 8*g);
        *(uint4*)(Bh + row * 72 + 8*g) = v;
    }
    __syncthreads();

    // fused tailor: tl[n] = 1/max(N + Qn[n,:].Knsum, 1e-6)
    if (t < 128) {
        float d = (float)N_;
#pragma unroll
        for (int m = 0; m < 64; m++) d += __half2float(Bh[t * 72 + m]) * ks[m];
        tl[t] = 1.f / fmaxf(d, 1e-6f);
    }

    const int cw = (wid >> 2) * 64, nw = (wid & 3) * 32;
    const int r = lane >> 2, kq = (lane & 3) * 2;
    const uint32_t Ab = smem_u32(Ah), Bb = smem_u32(Bh);
    float acc[4][4][4] = {};
#pragma unroll
    for (int kc = 0; kc < 64; kc += 16) {
        uint32_t ah[4][4], bh[4][2];
#pragma unroll
        for (int mf = 0; mf < 4; mf++)
            ldsm_x4(ah[mf], Ab + ((cw + mf*16 + (lane & 15)) * 72 + kc + (lane >> 4) * 8) * 2);
#pragma unroll
        for (int nf = 0; nf < 4; nf += 2) {
            uint32_t rr[4];
            ldsm_x4(rr, Bb + ((nw + nf*8 + (lane & 7) + ((lane >> 4) << 3)) * 72
                              + kc + ((lane >> 3) & 1) * 8) * 2);
            bh[nf][0] = rr[0]; bh[nf][1] = rr[1];
            bh[nf+1][0] = rr[2]; bh[nf+1][1] = rr[3];
        }
#pragma unroll
        for (int mf = 0; mf < 4; mf++)
#pragma unroll
            for (int nf = 0; nf < 4; nf++) mma_f16(acc[mf][nf], ah[mf], bh[nf]);
    }
    __syncthreads();

    float* Cs = (float*)(sm + FN_CS);
    float gm = gamma[0];
#pragma unroll
    for (int mf = 0; mf < 4; mf++) {
        int cA = cw + mf*16 + r, cB = cA + 8;
        float vA = vs[cA], vB = vs[cB];
#pragma unroll
        for (int nf = 0; nf < 4; nf++) {
            int n = nw + nf*8 + kq;
            Cs[cA * 132 + n    ] = fixv(gm * tl[n    ] * (vA + acc[mf][nf][0]));
            Cs[cA * 132 + n + 1] = fixv(gm * tl[n + 1] * (vA + acc[mf][nf][1]));
            Cs[cB * 132 + n    ] = fixv(gm * tl[n    ] * (vB + acc[mf][nf][2]));
            Cs[cB * 132 + n + 1] = fixv(gm * tl[n + 1] * (vB + acc[mf][nf][3]));
        }
    }
    __syncthreads();
#pragma unroll
    for (int i = 0; i < 16; i++) {
        int idx = t + i * 256, c = idx >> 5, g = idx & 31;
        float4 v = *(float4*)(Cs + c * 132 + 4*g);
        *(float4*)(out + ((size_t)b * C_ + c0 + c) * N_ + n0 + 4*g) = v;
    }
}

// ---------------------------------------------------------------
extern "C" void kernel_launch(void* const* d_in, const int* in_sizes, int n_in,
                              void* d_out, int out_size) {
    const float* x     = (const float*)d_in[0];
    const float* Wq    = (const float*)d_in[1];
    const float* bq    = (const float*)d_in[2];
    const float* Wk    = (const float*)d_in[3];
    const float* bk    = (const float*)d_in[4];
    const float* Wv    = (const float*)d_in[5];
    const float* bv    = (const float*)d_in[6];
    const float* gamma = (const float*)d_in[7];
    float* out = (float*)d_out;

    cudaFuncSetAttribute(qk_mma,    cudaFuncAttributeMaxDynamicSharedMemorySize, QK_BYTES);
    cudaFuncSetAttribute(final_mma, cudaFuncAttributeMaxDynamicSharedMemorySize, FN_BYTES);

    qk_mma     <<<dim3(32, 16), 256, QK_BYTES>>>(x, Wq, bq, Wk, bk);
    kx_mma     <<<dim3(4, 16, 4), 256>>>();
    vsum_kernel<<<dim3(128, 16), 128>>>(Wv, bv);
    mat_mma    <<<dim3(4, 16), 256>>>(Wv, bv);
    final_mma  <<<dim3(32, 4, 16), 256, FN_BYTES>>>(out, gamma);
}

// round 12
// speedup vs baseline: 1.7747x; 1.0183x over previous
#include <cuda_runtime.h>
#include <cuda_fp16.h>
#include <cstdint>
#include <math.h>

#define B_ 16
#define C_ 512
#define N_ 4096
#define M_ 64

// ---------------- scratch (static device globals) ----------------
__device__ __align__(128) __half g_x16 [B_*C_*N_];    // fp16 copy of x (written by qk)
__device__ __align__(128) __half g_QnT16[B_*N_*M_];   // [b][n][m] fp16
__device__ __align__(128) __half g_Kn16 [B_*M_*N_];   // [b][m][n] fp16
__device__ __align__(128) __half g_matT16[B_*C_*M_];  // [b][c][m] fp16
__device__ __align__(128) float g_KXp[4][B_*M_*C_];   // k-split partials
__device__ __align__(128) float g_Knp[B_*32*M_];      // Knsum partials per n-tile
__device__ __align__(128) float g_Knsum[B_*M_];
__device__ __align__(128) float g_xsump[4][B_*C_];    // xsum k-split partials
__device__ __align__(128) float g_Vsum[B_*C_];

// ---------------- fp16 pack helpers ----------------
__device__ __forceinline__ uint32_t hpk2(float a, float b) {
    __half2 t = __floats2half2_rn(a, b);
    return *reinterpret_cast<uint32_t*>(&t);
}
__device__ __forceinline__ uint2 pk4(float4 v) {
    uint2 r; r.x = hpk2(v.x, v.y); r.y = hpk2(v.z, v.w); return r;
}
__device__ __forceinline__ uint32_t smem_u32(const void* p) {
    uint32_t a;
    asm("{ .reg .u64 t; cvta.to.shared.u64 t, %1; cvt.u32.u64 %0, t; }" : "=r"(a) : "l"(p));
    return a;
}

// ---------------- mma / ldmatrix helpers ----------------
__device__ __forceinline__ void mma_f16(float c[4], const uint32_t a[4], const uint32_t b[2]) {
    asm volatile("mma.sync.aligned.m16n8k16.row.col.f32.f16.f16.f32 "
        "{%0,%1,%2,%3}, {%4,%5,%6,%7}, {%8,%9}, {%0,%1,%2,%3};"
        : "+f"(c[0]), "+f"(c[1]), "+f"(c[2]), "+f"(c[3])
        : "r"(a[0]), "r"(a[1]), "r"(a[2]), "r"(a[3]), "r"(b[0]), "r"(b[1]));
}
__device__ __forceinline__ void ldsm_x4(uint32_t r[4], uint32_t a) {
    asm volatile("ldmatrix.sync.aligned.m8n8.x4.shared.b16 {%0,%1,%2,%3}, [%4];"
        : "=r"(r[0]), "=r"(r[1]), "=r"(r[2]), "=r"(r[3]) : "r"(a));
}
__device__ __forceinline__ void ldsm_x4t(uint32_t r[4], uint32_t a) {
    asm volatile("ldmatrix.sync.aligned.m8n8.x4.trans.shared.b16 {%0,%1,%2,%3}, [%4];"
        : "=r"(r[0]), "=r"(r[1]), "=r"(r[2]), "=r"(r[3]) : "r"(a));
}
__device__ __forceinline__ float fixv(float v) {
    if (isnan(v)) return 0.f;
    if (isinf(v)) return v > 0.f ? 1.f : -1.f;
    return v;
}

// =====================================================================
// qk_mma: D[128m(64q|64k)][128n] = Wqk @ x, K=512. grid(32,16), 256 thr
// fp16, ldmatrix x4 (A) + x4.trans (B), 1 sync/iter, double-buffered.
// Also writes g_x16 (fp16 copy of x) from the already-packed B values.
// =====================================================================
#define QK_A(s)  ((s) * 10240)
#define QK_B(s)  (20480 + (s) * 8704)
#define QK_CS 0
#define QK_BIAS 68096
#define QK_INQ 68608
#define QK_INK 69120
#define QK_BYTES 69632

__global__ __launch_bounds__(256, 1) void qk_mma(
    const float* __restrict__ x,  const float* __restrict__ Wq,
    const float* __restrict__ bq, const float* __restrict__ Wk,
    const float* __restrict__ bk) {
    extern __shared__ __align__(16) char sm[];
    const int t = threadIdx.x, lane = t & 31, wid = t >> 5;
    const int b = blockIdx.y, n0 = blockIdx.x * 128;
    const float* xb = x + (size_t)b * C_ * N_;
    float* bias = (float*)(sm + QK_BIAS);
    float* inq  = (float*)(sm + QK_INQ);
    float* ink  = (float*)(sm + QK_INK);
    if (t < 128) bias[t] = (t < 64) ? bq[t] : bk[t - 64];

    const int m0 = (wid >> 2) * 64, nw = (wid & 3) * 32;
    const int r = lane >> 2, kq = (lane & 3) * 2;
    float acc[4][4][4] = {};

    float4 aR[4], xR[4];
#pragma unroll
    for (int i = 0; i < 4; i++) {
        int idx = t + i * 256, row = idx >> 3, g = idx & 7;
        aR[i] = (row < 64) ? *(const float4*)(Wq + (size_t)row * C_ + 4*g)
                           : *(const float4*)(Wk + (size_t)(row - 64) * C_ + 4*g);
    }
#pragma unroll
    for (int i = 0; i < 4; i++) {
        int idx = t + i * 256, kk = idx >> 5, g = idx & 31;
        xR[i] = *(const float4*)(xb + (size_t)kk * N_ + n0 + 4*g);
    }

    for (int p = 0; p < 16; ++p) {
        const int s = p & 1;
        __half* Ah = (__half*)(sm + QK_A(s));
        __half* Bh = (__half*)(sm + QK_B(s));
#pragma unroll
        for (int i = 0; i < 4; i++) {   // A rows (m), 32 k, pitch 40
            int idx = t + i * 256, row = idx >> 3, g = idx & 7;
            *(uint2*)(Ah + row * 40 + 4*g) = pk4(aR[i]);
        }
#pragma unroll
        for (int i = 0; i < 4; i++) {   // B k-major + x16 writeout
            int idx = t + i * 256, kk = idx >> 5, g = idx & 31;
            uint2 h = pk4(xR[i]);
            *(uint2*)(Bh + kk * 136 + 4*g) = h;
            *(uint2*)(g_x16 + ((size_t)(b * C_ + p * 32 + kk)) * N_ + n0 + 4*g) = h;
        }
        __syncthreads();
        if (p < 15) {   // prefetch next k-step
            const int k0 = (p + 1) * 32;
#pragma unroll
            for (int i = 0; i < 4; i++) {
                int idx = t + i * 256, row = idx >> 3, g = idx & 7;
                aR[i] = (row < 64) ? *(const float4*)(Wq + (size_t)row * C_ + k0 + 4*g)
                                   : *(const float4*)(Wk + (size_t)(row - 64) * C_ + k0 + 4*g);
            }
#pragma unroll
            for (int i = 0; i < 4; i++) {
                int idx = t + i * 256, kk = idx >> 5, g = idx & 31;
                xR[i] = *(const float4*)(xb + (size_t)(k0 + kk) * N_ + n0 + 4*g);
            }
        }
        const uint32_t Ab = smem_u32(Ah), Bb = smem_u32(Bh);
#pragma unroll
        for (int kc = 0; kc < 32; kc += 16) {
            uint32_t ah[4][4], bh[4][2];
#pragma unroll
            for (int mf = 0; mf < 4; mf++)
                ldsm_x4(ah[mf], Ab + ((m0 + mf*16 + (lane & 15)) * 40 + kc + (lane >> 4) * 8) * 2);
#pragma unroll
            for (int nf = 0; nf < 4; nf += 2) {
                uint32_t rr[4];
                ldsm_x4t(rr, Bb + ((kc + (lane & 15)) * 136 + nw + nf*8 + (lane >> 4) * 8) * 2);
                bh[nf][0] = rr[0]; bh[nf][1] = rr[1];
                bh[nf+1][0] = rr[2]; bh[nf+1][1] = rr[3];
            }
#pragma unroll
            for (int mf = 0; mf < 4; mf++)
#pragma unroll
                for (int nf = 0; nf < 4; nf++) mma_f16(acc[mf][nf], ah[mf], bh[nf]);
        }
    }
    __syncthreads();   // panels dead; reuse smem as Cs

    float* Cs = (float*)(sm + QK_CS);
#pragma unroll
    for (int mf = 0; mf < 4; mf++) {
        int mA = m0 + mf*16 + r, mB = mA + 8;
        float bA = bias[mA], bB = bias[mB];
#pragma unroll
        for (int nf = 0; nf < 4; nf++) {
            int n = nw + nf*8 + kq;
            Cs[mA * 133 + n    ] = acc[mf][nf][0] + bA;
            Cs[mA * 133 + n + 1] = acc[mf][nf][1] + bA;
            Cs[mB * 133 + n    ] = acc[mf][nf][2] + bB;
            Cs[mB * 133 + n + 1] = acc[mf][nf][3] + bB;
        }
    }
    __syncthreads();
    {   // per-column L2 norms
        int n = t & 127, part = t >> 7, base = part * 64;
        float s = 0.f;
#pragma unroll 8
        for (int m = 0; m < 64; m++) {
            float v = Cs[(base + m) * 133 + n]; s = fmaf(v, v, s);
        }
        float inv = 1.f / fmaxf(sqrtf(s), 1e-6f);
        if (part == 0) inq[n] = inv; else ink[n] = inv;
    }
    __syncthreads();
    // write Kn16[m][n] (fp16) + Knsum partials
#pragma unroll
    for (int i = 0; i < 8; i++) {
        int idx = t + i * 256, m = idx >> 5, g = idx & 31;
        float4 v;
        v.x = Cs[(64 + m) * 133 + 4*g + 0] * ink[4*g + 0];
        v.y = Cs[(64 + m) * 133 + 4*g + 1] * ink[4*g + 1];
        v.z = Cs[(64 + m) * 133 + 4*g + 2] * ink[4*g + 2];
        v.w = Cs[(64 + m) * 133 + 4*g + 3] * ink[4*g + 3];
        *(uint2*)(g_Kn16 + ((size_t)b * M_ + m) * N_ + n0 + 4*g) = pk4(v);
        float rs = v.x + v.y + v.z + v.w;
#pragma unroll
        for (int o = 16; o; o >>= 1) rs += __shfl_xor_sync(0xffffffffu, rs, o);
        if (lane == 0) g_Knp[((size_t)b * 32 + blockIdx.x) * M_ + m] = rs;
    }
    // write QnT16[n][m] (fp16)
#pragma unroll
    for (int i = 0; i < 8; i++) {
        int idx = t + i * 256, n = idx >> 4, g = idx & 15;
        float iq = inq[n];
        float4 v;
        v.x = Cs[(4*g + 0) * 133 + n] * iq;
        v.y = Cs[(4*g + 1) * 133 + n] * iq;
        v.z = Cs[(4*g + 2) * 133 + n] * iq;
        v.w = Cs[(4*g + 3) * 133 + n] * iq;
        *(uint2*)(g_QnT16 + ((size_t)b * N_ + n0 + n) * M_ + 4*g) = pk4(v);
    }
}

// =====================================================================
// kx_mma: D[64m][128c] = Kn @ x16^T over k-slice of 1024. All-fp16 loads.
// grid (4, 16, 4), 256 thr, 2 CTAs/SM.
// =====================================================================
#define KX_A(s) ((s) * 5120)
#define KX_B(s) (10240 + (s) * 10240)
#define KX_CS 0
#define KX_BYTES 33792

__global__ __launch_bounds__(256, 2) void kx_mma() {
    __shared__ __align__(16) char sm[KX_BYTES];
    const int t = threadIdx.x, lane = t & 31, wid = t >> 5;
    const int b = blockIdx.y, c0 = blockIdx.x * 128, ks = blockIdx.z;
    const __half* Kb  = g_Kn16 + (size_t)b * M_ * N_;
    const __half* xb16 = g_x16 + ((size_t)b * C_ + c0) * N_;
    const int m0 = (wid >> 2) * 32, cw = (wid & 3) * 32;
    const int r = lane >> 2, kq = (lane & 3) * 2;
    float acc[2][4][4] = {};
    float xs[2] = {0.f, 0.f};

    uint4 aR, bRx[2];
    {   // prologue: load step 0
        const int k0 = ks * 1024;
        { int row = t >> 2, g = t & 3;
          aR = *(const uint4*)(Kb + (size_t)row * N_ + k0 + 8*g); }
#pragma unroll
        for (int i = 0; i < 2; i++) {
            int idx = t + i * 256, row = idx >> 2, g = idx & 3;
            bRx[i] = *(const uint4*)(xb16 + (size_t)row * N_ + k0 + 8*g);
        }
    }

    for (int p = 0; p < 32; ++p) {
        const int s = p & 1;
        __half* Ah = (__half*)(sm + KX_A(s));
        __half* Bh = (__half*)(sm + KX_B(s));
        { int row = t >> 2, g = t & 3;
          *(uint4*)(Ah + row * 40 + 8*g) = aR; }
#pragma unroll
        for (int i = 0; i < 2; i++) {
            int idx = t + i * 256, row = idx >> 2, g = idx & 3;
            const __half2* hp = (const __half2*)&bRx[i];
#pragma unroll
            for (int j = 0; j < 4; j++) {
                float2 f = __half22float2(hp[j]);
                xs[i] += f.x + f.y;
            }
            *(uint4*)(Bh + row * 40 + 8*g) = bRx[i];
        }
        __syncthreads();
        if (p < 31) {   // prefetch next step
            const int k0 = ks * 1024 + (p + 1) * 32;
            { int row = t >> 2, g = t & 3;
              aR = *(const uint4*)(Kb + (size_t)row * N_ + k0 + 8*g); }
#pragma unroll
            for (int i = 0; i < 2; i++) {
                int idx = t + i * 256, row = idx >> 2, g = idx & 3;
                bRx[i] = *(const uint4*)(xb16 + (size_t)row * N_ + k0 + 8*g);
            }
        }
        const uint32_t Ab = smem_u32(Ah), Bb = smem_u32(Bh);
#pragma unroll
        for (int kc = 0; kc < 32; kc += 16) {
            uint32_t ah[2][4], bh[4][2];
#pragma unroll
            for (int mf = 0; mf < 2; mf++)
                ldsm_x4(ah[mf], Ab + ((m0 + mf*16 + (lane & 15)) * 40 + kc + (lane >> 4) * 8) * 2);
#pragma unroll
            for (int nf = 0; nf < 4; nf += 2) {
                uint32_t rr[4];
                ldsm_x4(rr, Bb + ((cw + nf*8 + (lane & 7) + ((lane >> 4) << 3)) * 40
                                  + kc + ((lane >> 3) & 1) * 8) * 2);
                bh[nf][0] = rr[0]; bh[nf][1] = rr[1];
                bh[nf+1][0] = rr[2]; bh[nf+1][1] = rr[3];
            }
#pragma unroll
            for (int mf = 0; mf < 2; mf++)
#pragma unroll
                for (int nf = 0; nf < 4; nf++) mma_f16(acc[mf][nf], ah[mf], bh[nf]);
        }
    }

    // xsum partial: reduce over 4 column-group threads per row
#pragma unroll
    for (int i = 0; i < 2; i++) {
        float v = xs[i];
        v += __shfl_xor_sync(0xffffffffu, v, 1);
        v += __shfl_xor_sync(0xffffffffu, v, 2);
        if ((t & 3) == 0)
            g_xsump[ks][b * C_ + c0 + (t >> 2) + 64 * i] = v;
    }
    __syncthreads();

    float* Cs = (float*)(sm + KX_CS);
#pragma unroll
    for (int mf = 0; mf < 2; mf++) {
        int mA = m0 + mf*16 + r, mB = mA + 8;
#pragma unroll
        for (int nf = 0; nf < 4; nf++) {
            int c = cw + nf*8 + kq;
            Cs[mA * 132 + c    ] = acc[mf][nf][0];
            Cs[mA * 132 + c + 1] = acc[mf][nf][1];
            Cs[mB * 132 + c    ] = acc[mf][nf][2];
            Cs[mB * 132 + c + 1] = acc[mf][nf][3];
        }
    }
    __syncthreads();
#pragma unroll
    for (int i = 0; i < 8; i++) {
        int idx = t + i * 256, m = idx >> 5, g = idx & 31;
        float4 v = *(float4*)(Cs + m * 132 + 4*g);
        *(float4*)(g_KXp[ks] + ((size_t)b * M_ + m) * C_ + c0 + 4*g) = v;
    }
}

// =====================================================================
// mat_mma: matT[64c][64m] = Wv @ (sum KXp)^T, K=512. fp16 mma, ldmatrix,
// double-buffered, 1 sync/iter. Fuses: Knsum fold (publish), Vsum
// (Wv . xsum during A loads). grid (8 c-tiles, 16 b), 256 thr, 2 CTAs/SM.
// smem: A(s)=s*5120 (64x40 halfs), B(s)=10240+s*5120 (64x40);
// Cs at 0 (64*68*4=17408); ksm 20480, bvs 20736, xss 20992 -> 23040
// =====================================================================
#define MT_A(s) ((s) * 5120)
#define MT_B(s) (10240 + (s) * 5120)
#define MT_CS 0
#define MT_KS 20480
#define MT_BV 20736
#define MT_XS 20992
#define MT_BYTES 23040

__global__ __launch_bounds__(256, 2) void mat_mma(const float* __restrict__ Wv,
                                                  const float* __restrict__ bv) {
    __shared__ __align__(16) char sm[MT_BYTES];
    const int t = threadIdx.x, lane = t & 31, wid = t >> 5;
    const int b = blockIdx.y, c0 = blockIdx.x * 64;
    float* ksm = (float*)(sm + MT_KS);
    float* bvs = (float*)(sm + MT_BV);
    float* xss = (float*)(sm + MT_XS);
    if (t < 64) {   // fold Knsum partials; publish for final_mma
        float s = 0.f;
#pragma unroll
        for (int i = 0; i < 32; i++) s += g_Knp[((size_t)b * 32 + i) * M_ + t];
        ksm[t] = s;
        if (blockIdx.x == 0) g_Knsum[b * M_ + t] = s;
        bvs[t] = bv[c0 + t];
    }
    for (int i = t; i < C_; i += 256)   // folded xsum
        xss[i] = g_xsump[0][b * C_ + i] + g_xsump[1][b * C_ + i]
               + g_xsump[2][b * C_ + i] + g_xsump[3][b * C_ + i];
    __syncthreads();

    const float* A0 = g_KXp[0] + (size_t)b * M_ * C_;
    const float* A1 = g_KXp[1] + (size_t)b * M_ * C_;
    const float* A2 = g_KXp[2] + (size_t)b * M_ * C_;
    const float* A3 = g_KXp[3] + (size_t)b * M_ * C_;

    const int cw = (wid >> 2) * 32, nw = (wid & 3) * 16;
    const int r = lane >> 2, kq = (lane & 3) * 2;
    float acc[2][2][4] = {};
    float vacc[2] = {0.f, 0.f};   // Wv . xsum accumulators (2 rows per thread)

    float4 aR[2], bR[2];
    {   // prologue: k-step 0
#pragma unroll
        for (int i = 0; i < 2; i++) {   // Wv rows (c)
            int idx = t + i * 256, row = idx >> 3, g = idx & 7;
            aR[i] = *(const float4*)(Wv + (size_t)(c0 + row) * C_ + 4*g);
            vacc[i] = fmaf(aR[i].x, xss[4*g + 0],
                      fmaf(aR[i].y, xss[4*g + 1],
                      fmaf(aR[i].z, xss[4*g + 2],
                      fmaf(aR[i].w, xss[4*g + 3], vacc[i]))));
        }
#pragma unroll
        for (int i = 0; i < 2; i++) {   // KX fold rows (m)
            int idx = t + i * 256, row = idx >> 3, g = idx & 7;
            size_t off = (size_t)row * C_ + 4*g;
            float4 v0 = *(const float4*)(A0 + off), v1 = *(const float4*)(A1 + off);
            float4 v2 = *(const float4*)(A2 + off), v3 = *(const float4*)(A3 + off);
            bR[i] = make_float4(v0.x+v1.x+v2.x+v3.x, v0.y+v1.y+v2.y+v3.y,
                                v0.z+v1.z+v2.z+v3.z, v0.w+v1.w+v2.w+v3.w);
        }
    }

    for (int p = 0; p < 16; ++p) {
        const int s = p & 1;
        __half* Ah = (__half*)(sm + MT_A(s));
        __half* Bh = (__half*)(sm + MT_B(s));
#pragma unroll
        for (int i = 0; i < 2; i++) {
            int idx = t + i * 256, row = idx >> 3, g = idx & 7;
            *(uint2*)(Ah + row * 40 + 4*g) = pk4(aR[i]);
        }
#pragma unroll
        for (int i = 0; i < 2; i++) {
            int idx = t + i * 256, row = idx >> 3, g = idx & 7;
            *(uint2*)(Bh + row * 40 + 4*g) = pk4(bR[i]);
        }
        __syncthreads();
        if (p < 15) {   // prefetch next k-step (+ vsum accumulation)
            const int k0 = (p + 1) * 32;
#pragma unroll
            for (int i = 0; i < 2; i++) {
                int idx = t + i * 256, row = idx >> 3, g = idx & 7;
                aR[i] = *(const float4*)(Wv + (size_t)(c0 + row) * C_ + k0 + 4*g);
                vacc[i] = fmaf(aR[i].x, xss[k0 + 4*g + 0],
                          fmaf(aR[i].y, xss[k0 + 4*g + 1],
                          fmaf(aR[i].z, xss[k0 + 4*g + 2],
                          fmaf(aR[i].w, xss[k0 + 4*g + 3], vacc[i]))));
            }
#pragma unroll
            for (int i = 0; i < 2; i++) {
                int idx = t + i * 256, row = idx >> 3, g = idx & 7;
                size_t off = (size_t)row * C_ + k0 + 4*g;
                float4 v0 = *(const float4*)(A0 + off), v1 = *(const float4*)(A1 + off);
                float4 v2 = *(const float4*)(A2 + off), v3 = *(const float4*)(A3 + off);
                bR[i] = make_float4(v0.x+v1.x+v2.x+v3.x, v0.y+v1.y+v2.y+v3.y,
                                    v0.z+v1.z+v2.z+v3.z, v0.w+v1.w+v2.w+v3.w);
            }
        }
        const uint32_t Ab = smem_u32(Ah), Bb = smem_u32(Bh);
#pragma unroll
        for (int kc = 0; kc < 32; kc += 16) {
            uint32_t ah[2][4], bh[2][2];
#pragma unroll
            for (int mf = 0; mf < 2; mf++)
                ldsm_x4(ah[mf], Ab + ((cw + mf*16 + (lane & 15)) * 40 + kc + (lane >> 4) * 8) * 2);
            {
                uint32_t rr[4];
                ldsm_x4(rr, Bb + ((nw + (lane & 7) + ((lane >> 4) << 3)) * 40
                                  + kc + ((lane >> 3) & 1) * 8) * 2);
                bh[0][0] = rr[0]; bh[0][1] = rr[1];
                bh[1][0] = rr[2]; bh[1][1] = rr[3];
            }
#pragma unroll
            for (int mf = 0; mf < 2; mf++)
#pragma unroll
                for (int nf = 0; nf < 2; nf++) mma_f16(acc[mf][nf], ah[mf], bh[nf]);
        }
    }

    // Vsum: reduce vacc over the 8 loader-lanes per row, add N*bv
#pragma unroll
    for (int i = 0; i < 2; i++) {
        float v = vacc[i];
        v += __shfl_xor_sync(0xffffffffu, v, 1);
        v += __shfl_xor_sync(0xffffffffu, v, 2);
        v += __shfl_xor_sync(0xffffffffu, v, 4);
        int idx = t + i * 256, row = idx >> 3;
        if ((t & 7) == 0)
            g_Vsum[b * C_ + c0 + row] = v + (float)N_ * bvs[row];
    }
    __syncthreads();   // panels dead; reuse smem as Cs

    float* Cs = (float*)(sm + MT_CS);
#pragma unroll
    for (int mf = 0; mf < 2; mf++) {
        int cA = cw + mf*16 + r, cB = cA + 8;
        float bA = bvs[cA], bB = bvs[cB];
#pragma unroll
        for (int nf = 0; nf < 2; nf++) {
            int m = nw + nf*8 + kq;
            Cs[cA * 68 + m    ] = acc[mf][nf][0] + bA * ksm[m    ];
            Cs[cA * 68 + m + 1] = acc[mf][nf][1] + bA * ksm[m + 1];
            Cs[cB * 68 + m    ] = acc[mf][nf][2] + bB * ksm[m    ];
            Cs[cB * 68 + m + 1] = acc[mf][nf][3] + bB * ksm[m + 1];
        }
    }
    __syncthreads();
#pragma unroll
    for (int i = 0; i < 2; i++) {   // write matT16 [c][m], 8 halfs per task
        int idx = t + i * 256, row = idx >> 3, g = idx & 7;
        float4 v0 = *(float4*)(Cs + row * 68 + 8*g);
        float4 v1 = *(float4*)(Cs + row * 68 + 8*g + 4);
        uint2 h0 = pk4(v0), h1 = pk4(v1);
        uint4 o = make_uint4(h0.x, h0.y, h1.x, h1.y);
        *(uint4*)(g_matT16 + ((size_t)b * C_ + c0 + row) * M_ + 8*g) = o;
    }
}

// =====================================================================
// final_mma: D[128c][128n] = matT @ QnT^T, K=64, fused tailor, ldmatrix.
// grid (32 n, 4 c, 16 b), 256 thr, 2 CTAs/SM.
// =====================================================================
#define FN_AH 0
#define FN_BH 18432
#define FN_CS 0
#define FN_TL 67584
#define FN_VS 68096
#define FN_KS 68608
#define FN_BYTES 68864

__global__ __launch_bounds__(256, 2) void final_mma(float* __restrict__ out,
                                                    const float* __restrict__ gamma) {
    extern __shared__ __align__(16) char sm[];
    const int t = threadIdx.x, lane = t & 31, wid = t >> 5;
    const int b = blockIdx.z, c0 = blockIdx.y * 128, n0 = blockIdx.x * 128;
    float* tl = (float*)(sm + FN_TL);
    float* vs = (float*)(sm + FN_VS);
    float* ks = (float*)(sm + FN_KS);
    if (t < 128) vs[t] = g_Vsum[b * C_ + c0 + t];
    if (t < 64)  ks[t] = g_Knsum[b * M_ + t];
    __half* Ah = (__half*)(sm + FN_AH);
    __half* Bh = (__half*)(sm + FN_BH);
#pragma unroll
    for (int i = 0; i < 4; i++) {       // A: matT16 rows (c), 64 k
        int idx = t + i * 256, row = idx >> 3, g = idx & 7;
        uint4 v = *(const uint4*)(g_matT16 + ((size_t)b * C_ + c0 + row) * M_ + 8*g);
        *(uint4*)(Ah + row * 72 + 8*g) = v;
    }
#pragma unroll
    for (int i = 0; i < 4; i++) {       // B: QnT16 rows (n), 64 k
        int idx = t + i * 256, row = idx >> 3, g = idx & 7;
        uint4 v = *(const uint4*)(g_QnT16 + ((size_t)b * N_ + n0 + row) * M_ + 8*g);
        *(uint4*)(Bh + row * 72 + 8*g) = v;
    }
    __syncthreads();

    // fused tailor: tl[n] = 1/max(N + Qn[n,:].Knsum, 1e-6)
    if (t < 128) {
        float d = (float)N_;
#pragma unroll
        for (int m = 0; m < 64; m++) d += __half2float(Bh[t * 72 + m]) * ks[m];
        tl[t] = 1.f / fmaxf(d, 1e-6f);
    }

    const int cw = (wid >> 2) * 64, nw = (wid & 3) * 32;
    const int r = lane >> 2, kq = (lane & 3) * 2;
    const uint32_t Ab = smem_u32(Ah), Bb = smem_u32(Bh);
    float acc[4][4][4] = {};
#pragma unroll
    for (int kc = 0; kc < 64; kc += 16) {
        uint32_t ah[4][4], bh[4][2];
#pragma unroll
        for (int mf = 0; mf < 4; mf++)
            ldsm_x4(ah[mf], Ab + ((cw + mf*16 + (lane & 15)) * 72 + kc + (lane >> 4) * 8) * 2);
#pragma unroll
        for (int nf = 0; nf < 4; nf += 2) {
            uint32_t rr[4];
            ldsm_x4(rr, Bb + ((nw + nf*8 + (lane & 7) + ((lane >> 4) << 3)) * 72
                              + kc + ((lane >> 3) & 1) * 8) * 2);
            bh[nf][0] = rr[0]; bh[nf][1] = rr[1];
            bh[nf+1][0] = rr[2]; bh[nf+1][1] = rr[3];
        }
#pragma unroll
        for (int mf = 0; mf < 4; mf++)
#pragma unroll
            for (int nf = 0; nf < 4; nf++) mma_f16(acc[mf][nf], ah[mf], bh[nf]);
    }
    __syncthreads();

    float* Cs = (float*)(sm + FN_CS);
    float gm = gamma[0];
#pragma unroll
    for (int mf = 0; mf < 4; mf++) {
        int cA = cw + mf*16 + r, cB = cA + 8;
        float vA = vs[cA], vB = vs[cB];
#pragma unroll
        for (int nf = 0; nf < 4; nf++) {
            int n = nw + nf*8 + kq;
            Cs[cA * 132 + n    ] = fixv(gm * tl[n    ] * (vA + acc[mf][nf][0]));
            Cs[cA * 132 + n + 1] = fixv(gm * tl[n + 1] * (vA + acc[mf][nf][1]));
            Cs[cB * 132 + n    ] = fixv(gm * tl[n    ] * (vB + acc[mf][nf][2]));
            Cs[cB * 132 + n + 1] = fixv(gm * tl[n + 1] * (vB + acc[mf][nf][3]));
        }
    }
    __syncthreads();
#pragma unroll
    for (int i = 0; i < 16; i++) {
        int idx = t + i * 256, c = idx >> 5, g = idx & 31;
        float4 v = *(float4*)(Cs + c * 132 + 4*g);
        *(float4*)(out + ((size_t)b * C_ + c0 + c) * N_ + n0 + 4*g) = v;
    }
}

// ---------------------------------------------------------------
extern "C" void kernel_launch(void* const* d_in, const int* in_sizes, int n_in,
                              void* d_out, int out_size) {
    const float* x     = (const float*)d_in[0];
    const float* Wq    = (const float*)d_in[1];
    const float* bq    = (const float*)d_in[2];
    const float* Wk    = (const float*)d_in[3];
    const float* bk    = (const float*)d_in[4];
    const float* Wv    = (const float*)d_in[5];
    const float* bv    = (const float*)d_in[6];
    const float* gamma = (const float*)d_in[7];
    float* out = (float*)d_out;

    cudaFuncSetAttribute(qk_mma,    cudaFuncAttributeMaxDynamicSharedMemorySize, QK_BYTES);
    cudaFuncSetAttribute(final_mma, cudaFuncAttributeMaxDynamicSharedMemorySize, FN_BYTES);

    qk_mma   <<<dim3(32, 16), 256, QK_BYTES>>>(x, Wq, bq, Wk, bk);
    kx_mma   <<<dim3(4, 16, 4), 256>>>();
    mat_mma  <<<dim3(8, 16), 256>>>(Wv, bv);
    final_mma<<<dim3(32, 4, 16), 256, FN_BYTES>>>(out, gamma);
}

// round 13
// speedup vs baseline: 2.1946x; 1.2366x over previous
#include <cuda_runtime.h>
#include <cuda_fp16.h>
#include <cstdint>
#include <math.h>

#define B_ 16
#define C_ 512
#define N_ 4096
#define M_ 64

// ---------------- scratch (static device globals) ----------------
__device__ __align__(128) __half g_x16 [B_*C_*N_];    // fp16 copy of x (written by qk)
__device__ __align__(128) __half g_QnT16[B_*N_*M_];   // [b][n][m] fp16
__device__ __align__(128) __half g_Kn16 [B_*M_*N_];   // [b][m][n] fp16
__device__ __align__(128) __half g_matT16[B_*C_*M_];  // [b][c][m] fp16
__device__ __align__(128) float g_KXp[4][B_*M_*C_];   // k-split partials
__device__ __align__(128) float g_Knp[B_*32*M_];      // Knsum partials per n-tile
__device__ __align__(128) float g_Knsum[B_*M_];
__device__ __align__(128) float g_xsump[4][B_*C_];    // xsum k-split partials
__device__ __align__(128) float g_Vsum[B_*C_];

// ---------------- fp16 pack helpers ----------------
__device__ __forceinline__ uint32_t hpk2(float a, float b) {
    __half2 t = __floats2half2_rn(a, b);
    return *reinterpret_cast<uint32_t*>(&t);
}
__device__ __forceinline__ uint2 pk4(float4 v) {
    uint2 r; r.x = hpk2(v.x, v.y); r.y = hpk2(v.z, v.w); return r;
}
__device__ __forceinline__ uint32_t smem_u32(const void* p) {
    uint32_t a;
    asm("{ .reg .u64 t; cvta.to.shared.u64 t, %1; cvt.u32.u64 %0, t; }" : "=r"(a) : "l"(p));
    return a;
}

// ---------------- mma / ldmatrix helpers ----------------
__device__ __forceinline__ void mma_f16(float c[4], const uint32_t a[4], const uint32_t b[2]) {
    asm volatile("mma.sync.aligned.m16n8k16.row.col.f32.f16.f16.f32 "
        "{%0,%1,%2,%3}, {%4,%5,%6,%7}, {%8,%9}, {%0,%1,%2,%3};"
        : "+f"(c[0]), "+f"(c[1]), "+f"(c[2]), "+f"(c[3])
        : "r"(a[0]), "r"(a[1]), "r"(a[2]), "r"(a[3]), "r"(b[0]), "r"(b[1]));
}
__device__ __forceinline__ void ldsm_x4(uint32_t r[4], uint32_t a) {
    asm volatile("ldmatrix.sync.aligned.m8n8.x4.shared.b16 {%0,%1,%2,%3}, [%4];"
        : "=r"(r[0]), "=r"(r[1]), "=r"(r[2]), "=r"(r[3]) : "r"(a));
}
__device__ __forceinline__ void ldsm_x4t(uint32_t r[4], uint32_t a) {
    asm volatile("ldmatrix.sync.aligned.m8n8.x4.trans.shared.b16 {%0,%1,%2,%3}, [%4];"
        : "=r"(r[0]), "=r"(r[1]), "=r"(r[2]), "=r"(r[3]) : "r"(a));
}
__device__ __forceinline__ float fixv(float v) {
    if (isnan(v)) return 0.f;
    if (isinf(v)) return v > 0.f ? 1.f : -1.f;
    return v;
}

// =====================================================================
// qk_mma: D[128m(64q|64k)][128n] = Wqk @ x, K=512. grid(32,16), 256 thr,
// 2 CTAs/SM. fp16, ldmatrix x4 (A) + x4.trans (B), 1 sync/iter,
// double-buffered. Writes g_x16 (streaming) from the packed B values.
// =====================================================================
#define QK_A(s)  ((s) * 10240)
#define QK_B(s)  (20480 + (s) * 8704)
#define QK_CS 0
#define QK_BIAS 68096
#define QK_INQ 68608
#define QK_INK 69120
#define QK_BYTES 69632

__global__ __launch_bounds__(256, 2) void qk_mma(
    const float* __restrict__ x,  const float* __restrict__ Wq,
    const float* __restrict__ bq, const float* __restrict__ Wk,
    const float* __restrict__ bk) {
    extern __shared__ __align__(16) char sm[];
    const int t = threadIdx.x, lane = t & 31, wid = t >> 5;
    const int b = blockIdx.y, n0 = blockIdx.x * 128;
    const float* xb = x + (size_t)b * C_ * N_;
    float* bias = (float*)(sm + QK_BIAS);
    float* inq  = (float*)(sm + QK_INQ);
    float* ink  = (float*)(sm + QK_INK);
    if (t < 128) bias[t] = (t < 64) ? bq[t] : bk[t - 64];

    const int m0 = (wid >> 2) * 64, nw = (wid & 3) * 32;
    const int r = lane >> 2, kq = (lane & 3) * 2;
    float acc[4][4][4] = {};

    float4 aR[4], xR[4];
#pragma unroll
    for (int i = 0; i < 4; i++) {
        int idx = t + i * 256, row = idx >> 3, g = idx & 7;
        aR[i] = (row < 64) ? *(const float4*)(Wq + (size_t)row * C_ + 4*g)
                           : *(const float4*)(Wk + (size_t)(row - 64) * C_ + 4*g);
    }
#pragma unroll
    for (int i = 0; i < 4; i++) {
        int idx = t + i * 256, kk = idx >> 5, g = idx & 31;
        xR[i] = __ldcs((const float4*)(xb + (size_t)kk * N_ + n0 + 4*g));
    }

    for (int p = 0; p < 16; ++p) {
        const int s = p & 1;
        __half* Ah = (__half*)(sm + QK_A(s));
        __half* Bh = (__half*)(sm + QK_B(s));
#pragma unroll
        for (int i = 0; i < 4; i++) {   // A rows (m), 32 k, pitch 40
            int idx = t + i * 256, row = idx >> 3, g = idx & 7;
            *(uint2*)(Ah + row * 40 + 4*g) = pk4(aR[i]);
        }
#pragma unroll
        for (int i = 0; i < 4; i++) {   // B k-major + streaming x16 writeout
            int idx = t + i * 256, kk = idx >> 5, g = idx & 31;
            uint2 h = pk4(xR[i]);
            *(uint2*)(Bh + kk * 136 + 4*g) = h;
            __stcs((uint2*)(g_x16 + ((size_t)(b * C_ + p * 32 + kk)) * N_ + n0 + 4*g), h);
        }
        __syncthreads();
        if (p < 15) {   // prefetch next k-step
            const int k0 = (p + 1) * 32;
#pragma unroll
            for (int i = 0; i < 4; i++) {
                int idx = t + i * 256, row = idx >> 3, g = idx & 7;
                aR[i] = (row < 64) ? *(const float4*)(Wq + (size_t)row * C_ + k0 + 4*g)
                                   : *(const float4*)(Wk + (size_t)(row - 64) * C_ + k0 + 4*g);
            }
#pragma unroll
            for (int i = 0; i < 4; i++) {
                int idx = t + i * 256, kk = idx >> 5, g = idx & 31;
                xR[i] = __ldcs((const float4*)(xb + (size_t)(k0 + kk) * N_ + n0 + 4*g));
            }
        }
        const uint32_t Ab = smem_u32(Ah), Bb = smem_u32(Bh);
#pragma unroll
        for (int kc = 0; kc < 32; kc += 16) {
            uint32_t ah[4][4], bh[4][2];
#pragma unroll
            for (int mf = 0; mf < 4; mf++)
                ldsm_x4(ah[mf], Ab + ((m0 + mf*16 + (lane & 15)) * 40 + kc + (lane >> 4) * 8) * 2);
#pragma unroll
            for (int nf = 0; nf < 4; nf += 2) {
                uint32_t rr[4];
                ldsm_x4t(rr, Bb + ((kc + (lane & 15)) * 136 + nw + nf*8 + (lane >> 4) * 8) * 2);
                bh[nf][0] = rr[0]; bh[nf][1] = rr[1];
                bh[nf+1][0] = rr[2]; bh[nf+1][1] = rr[3];
            }
#pragma unroll
            for (int mf = 0; mf < 4; mf++)
#pragma unroll
                for (int nf = 0; nf < 4; nf++) mma_f16(acc[mf][nf], ah[mf], bh[nf]);
        }
    }
    __syncthreads();   // panels dead; reuse smem as Cs

    float* Cs = (float*)(sm + QK_CS);
#pragma unroll
    for (int mf = 0; mf < 4; mf++) {
        int mA = m0 + mf*16 + r, mB = mA + 8;
        float bA = bias[mA], bB = bias[mB];
#pragma unroll
        for (int nf = 0; nf < 4; nf++) {
            int n = nw + nf*8 + kq;
            Cs[mA * 133 + n    ] = acc[mf][nf][0] + bA;
            Cs[mA * 133 + n + 1] = acc[mf][nf][1] + bA;
            Cs[mB * 133 + n    ] = acc[mf][nf][2] + bB;
            Cs[mB * 133 + n + 1] = acc[mf][nf][3] + bB;
        }
    }
    __syncthreads();
    {   // per-column L2 norms
        int n = t & 127, part = t >> 7, base = part * 64;
        float s = 0.f;
#pragma unroll 8
        for (int m = 0; m < 64; m++) {
            float v = Cs[(base + m) * 133 + n]; s = fmaf(v, v, s);
        }
        float inv = 1.f / fmaxf(sqrtf(s), 1e-6f);
        if (part == 0) inq[n] = inv; else ink[n] = inv;
    }
    __syncthreads();
    // write Kn16[m][n] (fp16) + Knsum partials
#pragma unroll
    for (int i = 0; i < 8; i++) {
        int idx = t + i * 256, m = idx >> 5, g = idx & 31;
        float4 v;
        v.x = Cs[(64 + m) * 133 + 4*g + 0] * ink[4*g + 0];
        v.y = Cs[(64 + m) * 133 + 4*g + 1] * ink[4*g + 1];
        v.z = Cs[(64 + m) * 133 + 4*g + 2] * ink[4*g + 2];
        v.w = Cs[(64 + m) * 133 + 4*g + 3] * ink[4*g + 3];
        *(uint2*)(g_Kn16 + ((size_t)b * M_ + m) * N_ + n0 + 4*g) = pk4(v);
        float rs = v.x + v.y + v.z + v.w;
#pragma unroll
        for (int o = 16; o; o >>= 1) rs += __shfl_xor_sync(0xffffffffu, rs, o);
        if (lane == 0) g_Knp[((size_t)b * 32 + blockIdx.x) * M_ + m] = rs;
    }
    // write QnT16[n][m] (fp16)
#pragma unroll
    for (int i = 0; i < 8; i++) {
        int idx = t + i * 256, n = idx >> 4, g = idx & 15;
        float iq = inq[n];
        float4 v;
        v.x = Cs[(4*g + 0) * 133 + n] * iq;
        v.y = Cs[(4*g + 1) * 133 + n] * iq;
        v.z = Cs[(4*g + 2) * 133 + n] * iq;
        v.w = Cs[(4*g + 3) * 133 + n] * iq;
        *(uint2*)(g_QnT16 + ((size_t)b * N_ + n0 + n) * M_ + 4*g) = pk4(v);
    }
}

// =====================================================================
// kx_mma: D[64m][128c] = Kn @ x16^T over k-slice of 1024. All-fp16 loads.
// grid (4, 16, 4), 256 thr, 2 CTAs/SM.
// =====================================================================
#define KX_A(s) ((s) * 5120)
#define KX_B(s) (10240 + (s) * 10240)
#define KX_CS 0
#define KX_BYTES 33792

__global__ __launch_bounds__(256, 2) void kx_mma() {
    __shared__ __align__(16) char sm[KX_BYTES];
    const int t = threadIdx.x, lane = t & 31, wid = t >> 5;
    const int b = blockIdx.y, c0 = blockIdx.x * 128, ks = blockIdx.z;
    const __half* Kb  = g_Kn16 + (size_t)b * M_ * N_;
    const __half* xb16 = g_x16 + ((size_t)b * C_ + c0) * N_;
    const int m0 = (wid >> 2) * 32, cw = (wid & 3) * 32;
    const int r = lane >> 2, kq = (lane & 3) * 2;
    float acc[2][4][4] = {};
    float xs[2] = {0.f, 0.f};

    uint4 aR, bRx[2];
    {   // prologue: load step 0
        const int k0 = ks * 1024;
        { int row = t >> 2, g = t & 3;
          aR = *(const uint4*)(Kb + (size_t)row * N_ + k0 + 8*g); }
#pragma unroll
        for (int i = 0; i < 2; i++) {
            int idx = t + i * 256, row = idx >> 2, g = idx & 3;
            bRx[i] = __ldcs((const uint4*)(xb16 + (size_t)row * N_ + k0 + 8*g));
        }
    }

    for (int p = 0; p < 32; ++p) {
        const int s = p & 1;
        __half* Ah = (__half*)(sm + KX_A(s));
        __half* Bh = (__half*)(sm + KX_B(s));
        { int row = t >> 2, g = t & 3;
          *(uint4*)(Ah + row * 40 + 8*g) = aR; }
#pragma unroll
        for (int i = 0; i < 2; i++) {
            int idx = t + i * 256, row = idx >> 2, g = idx & 3;
            const __half2* hp = (const __half2*)&bRx[i];
#pragma unroll
            for (int j = 0; j < 4; j++) {
                float2 f = __half22float2(hp[j]);
                xs[i] += f.x + f.y;
            }
            *(uint4*)(Bh + row * 40 + 8*g) = bRx[i];
        }
        __syncthreads();
        if (p < 31) {   // prefetch next step
            const int k0 = ks * 1024 + (p + 1) * 32;
            { int row = t >> 2, g = t & 3;
              aR = *(const uint4*)(Kb + (size_t)row * N_ + k0 + 8*g); }
#pragma unroll
            for (int i = 0; i < 2; i++) {
                int idx = t + i * 256, row = idx >> 2, g = idx & 3;
                bRx[i] = __ldcs((const uint4*)(xb16 + (size_t)row * N_ + k0 + 8*g));
            }
        }
        const uint32_t Ab = smem_u32(Ah), Bb = smem_u32(Bh);
#pragma unroll
        for (int kc = 0; kc < 32; kc += 16) {
            uint32_t ah[2][4], bh[4][2];
#pragma unroll
            for (int mf = 0; mf < 2; mf++)
                ldsm_x4(ah[mf], Ab + ((m0 + mf*16 + (lane & 15)) * 40 + kc + (lane >> 4) * 8) * 2);
#pragma unroll
            for (int nf = 0; nf < 4; nf += 2) {
                uint32_t rr[4];
                ldsm_x4(rr, Bb + ((cw + nf*8 + (lane & 7) + ((lane >> 4) << 3)) * 40
                                  + kc + ((lane >> 3) & 1) * 8) * 2);
                bh[nf][0] = rr[0]; bh[nf][1] = rr[1];
                bh[nf+1][0] = rr[2]; bh[nf+1][1] = rr[3];
            }
#pragma unroll
            for (int mf = 0; mf < 2; mf++)
#pragma unroll
                for (int nf = 0; nf < 4; nf++) mma_f16(acc[mf][nf], ah[mf], bh[nf]);
        }
    }

    // xsum partial: reduce over 4 column-group threads per row
#pragma unroll
    for (int i = 0; i < 2; i++) {
        float v = xs[i];
        v += __shfl_xor_sync(0xffffffffu, v, 1);
        v += __shfl_xor_sync(0xffffffffu, v, 2);
        if ((t & 3) == 0)
            g_xsump[ks][b * C_ + c0 + (t >> 2) + 64 * i] = v;
    }
    __syncthreads();

    float* Cs = (float*)(sm + KX_CS);
#pragma unroll
    for (int mf = 0; mf < 2; mf++) {
        int mA = m0 + mf*16 + r, mB = mA + 8;
#pragma unroll
        for (int nf = 0; nf < 4; nf++) {
            int c = cw + nf*8 + kq;
            Cs[mA * 132 + c    ] = acc[mf][nf][0];
            Cs[mA * 132 + c + 1] = acc[mf][nf][1];
            Cs[mB * 132 + c    ] = acc[mf][nf][2];
            Cs[mB * 132 + c + 1] = acc[mf][nf][3];
        }
    }
    __syncthreads();
#pragma unroll
    for (int i = 0; i < 8; i++) {
        int idx = t + i * 256, m = idx >> 5, g = idx & 31;
        float4 v = *(float4*)(Cs + m * 132 + 4*g);
        *(float4*)(g_KXp[ks] + ((size_t)b * M_ + m) * C_ + c0 + 4*g) = v;
    }
}

// =====================================================================
// mat_mma: matT[64c][64m] = Wv @ (sum KXp)^T, K=512. fp16 mma, ldmatrix,
// double-buffered, 1 sync/iter. Fuses: Knsum fold (publish), Vsum.
// grid (8 c-tiles, 16 b), 256 thr, 2 CTAs/SM.
// =====================================================================
#define MT_A(s) ((s) * 5120)
#define MT_B(s) (10240 + (s) * 5120)
#define MT_CS 0
#define MT_KS 20480
#define MT_BV 20736
#define MT_XS 20992
#define MT_BYTES 23040

__global__ __launch_bounds__(256, 2) void mat_mma(const float* __restrict__ Wv,
                                                  const float* __restrict__ bv) {
    __shared__ __align__(16) char sm[MT_BYTES];
    const int t = threadIdx.x, lane = t & 31, wid = t >> 5;
    const int b = blockIdx.y, c0 = blockIdx.x * 64;
    float* ksm = (float*)(sm + MT_KS);
    float* bvs = (float*)(sm + MT_BV);
    float* xss = (float*)(sm + MT_XS);
    if (t < 64) {   // fold Knsum partials; publish for final_mma
        float s = 0.f;
#pragma unroll
        for (int i = 0; i < 32; i++) s += g_Knp[((size_t)b * 32 + i) * M_ + t];
        ksm[t] = s;
        if (blockIdx.x == 0) g_Knsum[b * M_ + t] = s;
        bvs[t] = bv[c0 + t];
    }
    for (int i = t; i < C_; i += 256)   // folded xsum
        xss[i] = g_xsump[0][b * C_ + i] + g_xsump[1][b * C_ + i]
               + g_xsump[2][b * C_ + i] + g_xsump[3][b * C_ + i];
    __syncthreads();

    const float* A0 = g_KXp[0] + (size_t)b * M_ * C_;
    const float* A1 = g_KXp[1] + (size_t)b * M_ * C_;
    const float* A2 = g_KXp[2] + (size_t)b * M_ * C_;
    const float* A3 = g_KXp[3] + (size_t)b * M_ * C_;

    const int cw = (wid >> 2) * 32, nw = (wid & 3) * 16;
    const int r = lane >> 2, kq = (lane & 3) * 2;
    float acc[2][2][4] = {};
    float vacc[2] = {0.f, 0.f};

    float4 aR[2], bR[2];
    {   // prologue: k-step 0
#pragma unroll
        for (int i = 0; i < 2; i++) {   // Wv rows (c)
            int idx = t + i * 256, row = idx >> 3, g = idx & 7;
            aR[i] = *(const float4*)(Wv + (size_t)(c0 + row) * C_ + 4*g);
            vacc[i] = fmaf(aR[i].x, xss[4*g + 0],
                      fmaf(aR[i].y, xss[4*g + 1],
                      fmaf(aR[i].z, xss[4*g + 2],
                      fmaf(aR[i].w, xss[4*g + 3], vacc[i]))));
        }
#pragma unroll
        for (int i = 0; i < 2; i++) {   // KX fold rows (m)
            int idx = t + i * 256, row = idx >> 3, g = idx & 7;
            size_t off = (size_t)row * C_ + 4*g;
            float4 v0 = *(const float4*)(A0 + off), v1 = *(const float4*)(A1 + off);
            float4 v2 = *(const float4*)(A2 + off), v3 = *(const float4*)(A3 + off);
            bR[i] = make_float4(v0.x+v1.x+v2.x+v3.x, v0.y+v1.y+v2.y+v3.y,
                                v0.z+v1.z+v2.z+v3.z, v0.w+v1.w+v2.w+v3.w);
        }
    }

    for (int p = 0; p < 16; ++p) {
        const int s = p & 1;
        __half* Ah = (__half*)(sm + MT_A(s));
        __half* Bh = (__half*)(sm + MT_B(s));
#pragma unroll
        for (int i = 0; i < 2; i++) {
            int idx = t + i * 256, row = idx >> 3, g = idx & 7;
            *(uint2*)(Ah + row * 40 + 4*g) = pk4(aR[i]);
        }
#pragma unroll
        for (int i = 0; i < 2; i++) {
            int idx = t + i * 256, row = idx >> 3, g = idx & 7;
            *(uint2*)(Bh + row * 40 + 4*g) = pk4(bR[i]);
        }
        __syncthreads();
        if (p < 15) {   // prefetch next k-step (+ vsum accumulation)
            const int k0 = (p + 1) * 32;
#pragma unroll
            for (int i = 0; i < 2; i++) {
                int idx = t + i * 256, row = idx >> 3, g = idx & 7;
                aR[i] = *(const float4*)(Wv + (size_t)(c0 + row) * C_ + k0 + 4*g);
                vacc[i] = fmaf(aR[i].x, xss[k0 + 4*g + 0],
                          fmaf(aR[i].y, xss[k0 + 4*g + 1],
                          fmaf(aR[i].z, xss[k0 + 4*g + 2],
                          fmaf(aR[i].w, xss[k0 + 4*g + 3], vacc[i]))));
            }
#pragma unroll
            for (int i = 0; i < 2; i++) {
                int idx = t + i * 256, row = idx >> 3, g = idx & 7;
                size_t off = (size_t)row * C_ + k0 + 4*g;
                float4 v0 = *(const float4*)(A0 + off), v1 = *(const float4*)(A1 + off);
                float4 v2 = *(const float4*)(A2 + off), v3 = *(const float4*)(A3 + off);
                bR[i] = make_float4(v0.x+v1.x+v2.x+v3.x, v0.y+v1.y+v2.y+v3.y,
                                    v0.z+v1.z+v2.z+v3.z, v0.w+v1.w+v2.w+v3.w);
            }
        }
        const uint32_t Ab = smem_u32(Ah), Bb = smem_u32(Bh);
#pragma unroll
        for (int kc = 0; kc < 32; kc += 16) {
            uint32_t ah[2][4], bh[2][2];
#pragma unroll
            for (int mf = 0; mf < 2; mf++)
                ldsm_x4(ah[mf], Ab + ((cw + mf*16 + (lane & 15)) * 40 + kc + (lane >> 4) * 8) * 2);
            {
                uint32_t rr[4];
                ldsm_x4(rr, Bb + ((nw + (lane & 7) + ((lane >> 4) << 3)) * 40
                                  + kc + ((lane >> 3) & 1) * 8) * 2);
                bh[0][0] = rr[0]; bh[0][1] = rr[1];
                bh[1][0] = rr[2]; bh[1][1] = rr[3];
            }
#pragma unroll
            for (int mf = 0; mf < 2; mf++)
#pragma unroll
                for (int nf = 0; nf < 2; nf++) mma_f16(acc[mf][nf], ah[mf], bh[nf]);
        }
    }

    // Vsum: reduce vacc over the 8 loader-lanes per row, add N*bv
#pragma unroll
    for (int i = 0; i < 2; i++) {
        float v = vacc[i];
        v += __shfl_xor_sync(0xffffffffu, v, 1);
        v += __shfl_xor_sync(0xffffffffu, v, 2);
        v += __shfl_xor_sync(0xffffffffu, v, 4);
        int idx = t + i * 256, row = idx >> 3;
        if ((t & 7) == 0)
            g_Vsum[b * C_ + c0 + row] = v + (float)N_ * bvs[row];
    }
    __syncthreads();   // panels dead; reuse smem as Cs

    float* Cs = (float*)(sm + MT_CS);
#pragma unroll
    for (int mf = 0; mf < 2; mf++) {
        int cA = cw + mf*16 + r, cB = cA + 8;
        float bA = bvs[cA], bB = bvs[cB];
#pragma unroll
        for (int nf = 0; nf < 2; nf++) {
            int m = nw + nf*8 + kq;
            Cs[cA * 68 + m    ] = acc[mf][nf][0] + bA * ksm[m    ];
            Cs[cA * 68 + m + 1] = acc[mf][nf][1] + bA * ksm[m + 1];
            Cs[cB * 68 + m    ] = acc[mf][nf][2] + bB * ksm[m    ];
            Cs[cB * 68 + m + 1] = acc[mf][nf][3] + bB * ksm[m + 1];
        }
    }
    __syncthreads();
#pragma unroll
    for (int i = 0; i < 2; i++) {   // write matT16 [c][m], 8 halfs per task
        int idx = t + i * 256, row = idx >> 3, g = idx & 7;
        float4 v0 = *(float4*)(Cs + row * 68 + 8*g);
        float4 v1 = *(float4*)(Cs + row * 68 + 8*g + 4);
        uint2 h0 = pk4(v0), h1 = pk4(v1);
        uint4 o = make_uint4(h0.x, h0.y, h1.x, h1.y);
        *(uint4*)(g_matT16 + ((size_t)b * C_ + c0 + row) * M_ + 8*g) = o;
    }
}

// =====================================================================
// final_mma: D[64c][128n] = matT @ QnT^T, K=64, fused tailor, ldmatrix.
// grid (32 n, 8 c, 16 b) = 4096 blocks, 256 thr, 3 CTAs/SM.
// smem: Ah 0 (64x72 halfs = 9216), Bh 9216 (128x72 = 18432) -> 27648;
// Cs union at 0 (64*132*4 = 33792); tl 33792, vs 34304, ks 34560 -> 34816
// =====================================================================
#define FN_AH 0
#define FN_BH 9216
#define FN_CS 0
#define FN_TL 33792
#define FN_VS 34304
#define FN_KS 34560
#define FN_BYTES 34816

__global__ __launch_bounds__(256, 3) void final_mma(float* __restrict__ out,
                                                    const float* __restrict__ gamma) {
    extern __shared__ __align__(16) char sm[];
    const int t = threadIdx.x, lane = t & 31, wid = t >> 5;
    const int b = blockIdx.z, c0 = blockIdx.y * 64, n0 = blockIdx.x * 128;
    float* tl = (float*)(sm + FN_TL);
    float* vs = (float*)(sm + FN_VS);
    float* ks = (float*)(sm + FN_KS);
    if (t < 64) {
        vs[t] = g_Vsum[b * C_ + c0 + t];
        ks[t] = g_Knsum[b * M_ + t];
    }
    __half* Ah = (__half*)(sm + FN_AH);
    __half* Bh = (__half*)(sm + FN_BH);
#pragma unroll
    for (int i = 0; i < 2; i++) {       // A: matT16 rows (c, 64), 64 k
        int idx = t + i * 256, row = idx >> 3, g = idx & 7;
        uint4 v = *(const uint4*)(g_matT16 + ((size_t)b * C_ + c0 + row) * M_ + 8*g);
        *(uint4*)(Ah + row * 72 + 8*g) = v;
    }
#pragma unroll
    for (int i = 0; i < 4; i++) {       // B: QnT16 rows (n, 128), 64 k
        int idx = t + i * 256, row = idx >> 3, g = idx & 7;
        uint4 v = *(const uint4*)(g_QnT16 + ((size_t)b * N_ + n0 + row) * M_ + 8*g);
        *(uint4*)(Bh + row * 72 + 8*g) = v;
    }
    __syncthreads();

    // fused tailor: tl[n] = 1/max(N + Qn[n,:].Knsum, 1e-6)
    if (t < 128) {
        float d = (float)N_;
#pragma unroll
        for (int m = 0; m < 64; m++) d += __half2float(Bh[t * 72 + m]) * ks[m];
        tl[t] = 1.f / fmaxf(d, 1e-6f);
    }

    const int cw = (wid >> 2) * 32, nw = (wid & 3) * 32;
    const int r = lane >> 2, kq = (lane & 3) * 2;
    const uint32_t Ab = smem_u32(Ah), Bb = smem_u32(Bh);
    float acc[2][4][4] = {};
#pragma unroll
    for (int kc = 0; kc < 64; kc += 16) {
        uint32_t ah[2][4], bh[4][2];
#pragma unroll
        for (int mf = 0; mf < 2; mf++)
            ldsm_x4(ah[mf], Ab + ((cw + mf*16 + (lane & 15)) * 72 + kc + (lane >> 4) * 8) * 2);
#pragma unroll
        for (int nf = 0; nf < 4; nf += 2) {
            uint32_t rr[4];
            ldsm_x4(rr, Bb + ((nw + nf*8 + (lane & 7) + ((lane >> 4) << 3)) * 72
                              + kc + ((lane >> 3) & 1) * 8) * 2);
            bh[nf][0] = rr[0]; bh[nf][1] = rr[1];
            bh[nf+1][0] = rr[2]; bh[nf+1][1] = rr[3];
        }
#pragma unroll
        for (int mf = 0; mf < 2; mf++)
#pragma unroll
            for (int nf = 0; nf < 4; nf++) mma_f16(acc[mf][nf], ah[mf], bh[nf]);
    }
    __syncthreads();

    float* Cs = (float*)(sm + FN_CS);
    float gm = gamma[0];
#pragma unroll
    for (int mf = 0; mf < 2; mf++) {
        int cA = cw + mf*16 + r, cB = cA + 8;
        float vA = vs[cA], vB = vs[cB];
#pragma unroll
        for (int nf = 0; nf < 4; nf++) {
            int n = nw + nf*8 + kq;
            Cs[cA * 132 + n    ] = fixv(gm * tl[n    ] * (vA + acc[mf][nf][0]));
            Cs[cA * 132 + n + 1] = fixv(gm * tl[n + 1] * (vA + acc[mf][nf][1]));
            Cs[cB * 132 + n    ] = fixv(gm * tl[n    ] * (vB + acc[mf][nf][2]));
            Cs[cB * 132 + n + 1] = fixv(gm * tl[n + 1] * (vB + acc[mf][nf][3]));
        }
    }
    __syncthreads();
#pragma unroll
    for (int i = 0; i < 8; i++) {       // streaming writeout (64 rows x 128 n)
        int idx = t + i * 256, c = idx >> 5, g = idx & 31;
        float4 v = *(float4*)(Cs + c * 132 + 4*g);
        __stcs((float4*)(out + ((size_t)b * C_ + c0 + c) * N_ + n0 + 4*g), v);
    }
}

// ---------------------------------------------------------------
extern "C" void kernel_launch(void* const* d_in, const int* in_sizes, int n_in,
                              void* d_out, int out_size) {
    const float* x     = (const float*)d_in[0];
    const float* Wq    = (const float*)d_in[1];
    const float* bq    = (const float*)d_in[2];
    const float* Wk    = (const float*)d_in[3];
    const float* bk    = (const float*)d_in[4];
    const float* Wv    = (const float*)d_in[5];
    const float* bv    = (const float*)d_in[6];
    const float* gamma = (const float*)d_in[7];
    float* out = (float*)d_out;

    cudaFuncSetAttribute(qk_mma,    cudaFuncAttributeMaxDynamicSharedMemorySize, QK_BYTES);
    cudaFuncSetAttribute(final_mma, cudaFuncAttributeMaxDynamicSharedMemorySize, FN_BYTES);

    qk_mma   <<<dim3(32, 16), 256, QK_BYTES>>>(x, Wq, bq, Wk, bk);
    kx_mma   <<<dim3(4, 16, 4), 256>>>();
    mat_mma  <<<dim3(8, 16), 256>>>(Wv, bv);
    final_mma<<<dim3(32, 8, 16), 256, FN_BYTES>>>(out, gamma);
}

// round 14
// speedup vs baseline: 2.3749x; 1.0822x over previous
#include <cuda_runtime.h>
#include <cuda_fp16.h>
#include <cstdint>
#include <math.h>

#define B_ 16
#define C_ 512
#define N_ 4096
#define M_ 64

// ---------------- scratch (static device globals) ----------------
__device__ __align__(128) __half g_x16 [B_*C_*N_];    // fp16 copy of x (written by qk)
__device__ __align__(128) __half g_QnT16[B_*N_*M_];   // [b][n][m] fp16
__device__ __align__(128) __half g_Kn16 [B_*M_*N_];   // [b][m][n] fp16
__device__ __align__(128) __half g_matT16[B_*C_*M_];  // [b][c][m] fp16
__device__ __align__(128) float g_KXp[4][B_*M_*C_];   // k-split partials
__device__ __align__(128) float g_Knp[B_*32*M_];      // Knsum partials per n-tile
__device__ __align__(128) float g_Knsum[B_*M_];
__device__ __align__(128) float g_xsump[4][B_*C_];    // xsum k-split partials
__device__ __align__(128) float g_Vsum[B_*C_];

// ---------------- fp16 pack helpers ----------------
__device__ __forceinline__ uint32_t hpk2(float a, float b) {
    __half2 t = __floats2half2_rn(a, b);
    return *reinterpret_cast<uint32_t*>(&t);
}
__device__ __forceinline__ uint2 pk4(float4 v) {
    uint2 r; r.x = hpk2(v.x, v.y); r.y = hpk2(v.z, v.w); return r;
}
__device__ __forceinline__ uint32_t smem_u32(const void* p) {
    uint32_t a;
    asm("{ .reg .u64 t; cvta.to.shared.u64 t, %1; cvt.u32.u64 %0, t; }" : "=r"(a) : "l"(p));
    return a;
}

// ---------------- mma / ldmatrix helpers ----------------
__device__ __forceinline__ void mma_f16(float c[4], const uint32_t a[4], const uint32_t b[2]) {
    asm volatile("mma.sync.aligned.m16n8k16.row.col.f32.f16.f16.f32 "
        "{%0,%1,%2,%3}, {%4,%5,%6,%7}, {%8,%9}, {%0,%1,%2,%3};"
        : "+f"(c[0]), "+f"(c[1]), "+f"(c[2]), "+f"(c[3])
        : "r"(a[0]), "r"(a[1]), "r"(a[2]), "r"(a[3]), "r"(b[0]), "r"(b[1]));
}
__device__ __forceinline__ void ldsm_x4(uint32_t r[4], uint32_t a) {
    asm volatile("ldmatrix.sync.aligned.m8n8.x4.shared.b16 {%0,%1,%2,%3}, [%4];"
        : "=r"(r[0]), "=r"(r[1]), "=r"(r[2]), "=r"(r[3]) : "r"(a));
}
__device__ __forceinline__ void ldsm_x4t(uint32_t r[4], uint32_t a) {
    asm volatile("ldmatrix.sync.aligned.m8n8.x4.trans.shared.b16 {%0,%1,%2,%3}, [%4];"
        : "=r"(r[0]), "=r"(r[1]), "=r"(r[2]), "=r"(r[3]) : "r"(a));
}
__device__ __forceinline__ float fixv(float v) {
    if (isnan(v)) return 0.f;
    if (isinf(v)) return v > 0.f ? 1.f : -1.f;
    return v;
}

// =====================================================================
// qk_mma: D[128m(64q|64k)][128n] = Wqk @ x, K=512. grid(32,16), 256 thr,
// 2 CTAs/SM. fp16, ldmatrix x4 (A) + x4.trans (B), 1 sync/iter,
// double-buffered. Writes g_x16 (streaming) from the packed B values.
// =====================================================================
#define QK_A(s)  ((s) * 10240)
#define QK_B(s)  (20480 + (s) * 8704)
#define QK_CS 0
#define QK_BIAS 68096
#define QK_INQ 68608
#define QK_INK 69120
#define QK_BYTES 69632

__global__ __launch_bounds__(256, 2) void qk_mma(
    const float* __restrict__ x,  const float* __restrict__ Wq,
    const float* __restrict__ bq, const float* __restrict__ Wk,
    const float* __restrict__ bk) {
    extern __shared__ __align__(16) char sm[];
    const int t = threadIdx.x, lane = t & 31, wid = t >> 5;
    const int b = blockIdx.y, n0 = blockIdx.x * 128;
    const float* xb = x + (size_t)b * C_ * N_;
    float* bias = (float*)(sm + QK_BIAS);
    float* inq  = (float*)(sm + QK_INQ);
    float* ink  = (float*)(sm + QK_INK);
    if (t < 128) bias[t] = (t < 64) ? bq[t] : bk[t - 64];

    const int m0 = (wid >> 2) * 64, nw = (wid & 3) * 32;
    const int r = lane >> 2, kq = (lane & 3) * 2;
    float acc[4][4][4] = {};

    float4 aR[4], xR[4];
#pragma unroll
    for (int i = 0; i < 4; i++) {
        int idx = t + i * 256, row = idx >> 3, g = idx & 7;
        aR[i] = (row < 64) ? *(const float4*)(Wq + (size_t)row * C_ + 4*g)
                           : *(const float4*)(Wk + (size_t)(row - 64) * C_ + 4*g);
    }
#pragma unroll
    for (int i = 0; i < 4; i++) {
        int idx = t + i * 256, kk = idx >> 5, g = idx & 31;
        xR[i] = __ldcs((const float4*)(xb + (size_t)kk * N_ + n0 + 4*g));
    }

    for (int p = 0; p < 16; ++p) {
        const int s = p & 1;
        __half* Ah = (__half*)(sm + QK_A(s));
        __half* Bh = (__half*)(sm + QK_B(s));
#pragma unroll
        for (int i = 0; i < 4; i++) {   // A rows (m), 32 k, pitch 40
            int idx = t + i * 256, row = idx >> 3, g = idx & 7;
            *(uint2*)(Ah + row * 40 + 4*g) = pk4(aR[i]);
        }
#pragma unroll
        for (int i = 0; i < 4; i++) {   // B k-major + streaming x16 writeout
            int idx = t + i * 256, kk = idx >> 5, g = idx & 31;
            uint2 h = pk4(xR[i]);
            *(uint2*)(Bh + kk * 136 + 4*g) = h;
            __stcs((uint2*)(g_x16 + ((size_t)(b * C_ + p * 32 + kk)) * N_ + n0 + 4*g), h);
        }
        __syncthreads();
        if (p < 15) {   // prefetch next k-step
            const int k0 = (p + 1) * 32;
#pragma unroll
            for (int i = 0; i < 4; i++) {
                int idx = t + i * 256, row = idx >> 3, g = idx & 7;
                aR[i] = (row < 64) ? *(const float4*)(Wq + (size_t)row * C_ + k0 + 4*g)
                                   : *(const float4*)(Wk + (size_t)(row - 64) * C_ + k0 + 4*g);
            }
#pragma unroll
            for (int i = 0; i < 4; i++) {
                int idx = t + i * 256, kk = idx >> 5, g = idx & 31;
                xR[i] = __ldcs((const float4*)(xb + (size_t)(k0 + kk) * N_ + n0 + 4*g));
            }
        }
        const uint32_t Ab = smem_u32(Ah), Bb = smem_u32(Bh);
#pragma unroll
        for (int kc = 0; kc < 32; kc += 16) {
            uint32_t ah[4][4], bh[4][2];
#pragma unroll
            for (int mf = 0; mf < 4; mf++)
                ldsm_x4(ah[mf], Ab + ((m0 + mf*16 + (lane & 15)) * 40 + kc + (lane >> 4) * 8) * 2);
#pragma unroll
            for (int nf = 0; nf < 4; nf += 2) {
                uint32_t rr[4];
                ldsm_x4t(rr, Bb + ((kc + (lane & 15)) * 136 + nw + nf*8 + (lane >> 4) * 8) * 2);
                bh[nf][0] = rr[0]; bh[nf][1] = rr[1];
                bh[nf+1][0] = rr[2]; bh[nf+1][1] = rr[3];
            }
#pragma unroll
            for (int mf = 0; mf < 4; mf++)
#pragma unroll
                for (int nf = 0; nf < 4; nf++) mma_f16(acc[mf][nf], ah[mf], bh[nf]);
        }
    }
    __syncthreads();   // panels dead; reuse smem as Cs

    float* Cs = (float*)(sm + QK_CS);
#pragma unroll
    for (int mf = 0; mf < 4; mf++) {
        int mA = m0 + mf*16 + r, mB = mA + 8;
        float bA = bias[mA], bB = bias[mB];
#pragma unroll
        for (int nf = 0; nf < 4; nf++) {
            int n = nw + nf*8 + kq;
            Cs[mA * 133 + n    ] = acc[mf][nf][0] + bA;
            Cs[mA * 133 + n + 1] = acc[mf][nf][1] + bA;
            Cs[mB * 133 + n    ] = acc[mf][nf][2] + bB;
            Cs[mB * 133 + n + 1] = acc[mf][nf][3] + bB;
        }
    }
    __syncthreads();
    {   // per-column L2 norms
        int n = t & 127, part = t >> 7, base = part * 64;
        float s = 0.f;
#pragma unroll 8
        for (int m = 0; m < 64; m++) {
            float v = Cs[(base + m) * 133 + n]; s = fmaf(v, v, s);
        }
        float inv = 1.f / fmaxf(sqrtf(s), 1e-6f);
        if (part == 0) inq[n] = inv; else ink[n] = inv;
    }
    __syncthreads();
    // write Kn16[m][n] (fp16) + Knsum partials
#pragma unroll
    for (int i = 0; i < 8; i++) {
        int idx = t + i * 256, m = idx >> 5, g = idx & 31;
        float4 v;
        v.x = Cs[(64 + m) * 133 + 4*g + 0] * ink[4*g + 0];
        v.y = Cs[(64 + m) * 133 + 4*g + 1] * ink[4*g + 1];
        v.z = Cs[(64 + m) * 133 + 4*g + 2] * ink[4*g + 2];
        v.w = Cs[(64 + m) * 133 + 4*g + 3] * ink[4*g + 3];
        *(uint2*)(g_Kn16 + ((size_t)b * M_ + m) * N_ + n0 + 4*g) = pk4(v);
        float rs = v.x + v.y + v.z + v.w;
#pragma unroll
        for (int o = 16; o; o >>= 1) rs += __shfl_xor_sync(0xffffffffu, rs, o);
        if (lane == 0) g_Knp[((size_t)b * 32 + blockIdx.x) * M_ + m] = rs;
    }
    // write QnT16[n][m] (fp16)
#pragma unroll
    for (int i = 0; i < 8; i++) {
        int idx = t + i * 256, n = idx >> 4, g = idx & 15;
        float iq = inq[n];
        float4 v;
        v.x = Cs[(4*g + 0) * 133 + n] * iq;
        v.y = Cs[(4*g + 1) * 133 + n] * iq;
        v.z = Cs[(4*g + 2) * 133 + n] * iq;
        v.w = Cs[(4*g + 3) * 133 + n] * iq;
        *(uint2*)(g_QnT16 + ((size_t)b * N_ + n0 + n) * M_ + 4*g) = pk4(v);
    }
}

// =====================================================================
// kx_mma: D[64m][128c] = Kn @ x16^T over k-slice of 1024. All-fp16 loads.
// Direct-register epilogue (float2 stores, 32B sectors). grid (4, 16, 4),
// 256 thr, 2 CTAs/SM.
// =====================================================================
#define KX_A(s) ((s) * 5120)
#define KX_B(s) (10240 + (s) * 10240)
#define KX_BYTES 30720

__global__ __launch_bounds__(256, 2) void kx_mma() {
    __shared__ __align__(16) char sm[KX_BYTES];
    const int t = threadIdx.x, lane = t & 31, wid = t >> 5;
    const int b = blockIdx.y, c0 = blockIdx.x * 128, ks = blockIdx.z;
    const __half* Kb  = g_Kn16 + (size_t)b * M_ * N_;
    const __half* xb16 = g_x16 + ((size_t)b * C_ + c0) * N_;
    const int m0 = (wid >> 2) * 32, cw = (wid & 3) * 32;
    const int r = lane >> 2, kq = (lane & 3) * 2;
    float acc[2][4][4] = {};
    float xs[2] = {0.f, 0.f};

    uint4 aR, bRx[2];
    {   // prologue: load step 0
        const int k0 = ks * 1024;
        { int row = t >> 2, g = t & 3;
          aR = *(const uint4*)(Kb + (size_t)row * N_ + k0 + 8*g); }
#pragma unroll
        for (int i = 0; i < 2; i++) {
            int idx = t + i * 256, row = idx >> 2, g = idx & 3;
            bRx[i] = __ldcs((const uint4*)(xb16 + (size_t)row * N_ + k0 + 8*g));
        }
    }

    for (int p = 0; p < 32; ++p) {
        const int s = p & 1;
        __half* Ah = (__half*)(sm + KX_A(s));
        __half* Bh = (__half*)(sm + KX_B(s));
        { int row = t >> 2, g = t & 3;
          *(uint4*)(Ah + row * 40 + 8*g) = aR; }
#pragma unroll
        for (int i = 0; i < 2; i++) {
            int idx = t + i * 256, row = idx >> 2, g = idx & 3;
            const __half2* hp = (const __half2*)&bRx[i];
#pragma unroll
            for (int j = 0; j < 4; j++) {
                float2 f = __half22float2(hp[j]);
                xs[i] += f.x + f.y;
            }
            *(uint4*)(Bh + row * 40 + 8*g) = bRx[i];
        }
        __syncthreads();
        if (p < 31) {   // prefetch next step
            const int k0 = ks * 1024 + (p + 1) * 32;
            { int row = t >> 2, g = t & 3;
              aR = *(const uint4*)(Kb + (size_t)row * N_ + k0 + 8*g); }
#pragma unroll
            for (int i = 0; i < 2; i++) {
                int idx = t + i * 256, row = idx >> 2, g = idx & 3;
                bRx[i] = __ldcs((const uint4*)(xb16 + (size_t)row * N_ + k0 + 8*g));
            }
        }
        const uint32_t Ab = smem_u32(Ah), Bb = smem_u32(Bh);
#pragma unroll
        for (int kc = 0; kc < 32; kc += 16) {
            uint32_t ah[2][4], bh[4][2];
#pragma unroll
            for (int mf = 0; mf < 2; mf++)
                ldsm_x4(ah[mf], Ab + ((m0 + mf*16 + (lane & 15)) * 40 + kc + (lane >> 4) * 8) * 2);
#pragma unroll
            for (int nf = 0; nf < 4; nf += 2) {
                uint32_t rr[4];
                ldsm_x4(rr, Bb + ((cw + nf*8 + (lane & 7) + ((lane >> 4) << 3)) * 40
                                  + kc + ((lane >> 3) & 1) * 8) * 2);
                bh[nf][0] = rr[0]; bh[nf][1] = rr[1];
                bh[nf+1][0] = rr[2]; bh[nf+1][1] = rr[3];
            }
#pragma unroll
            for (int mf = 0; mf < 2; mf++)
#pragma unroll
                for (int nf = 0; nf < 4; nf++) mma_f16(acc[mf][nf], ah[mf], bh[nf]);
        }
    }

    // xsum partial: reduce over 4 column-group threads per row
#pragma unroll
    for (int i = 0; i < 2; i++) {
        float v = xs[i];
        v += __shfl_xor_sync(0xffffffffu, v, 1);
        v += __shfl_xor_sync(0xffffffffu, v, 2);
        if ((t & 3) == 0)
            g_xsump[ks][b * C_ + c0 + (t >> 2) + 64 * i] = v;
    }

    // direct-register epilogue: float2 stores (4 lanes = 32B sector)
    float* KX = g_KXp[ks] + (size_t)b * M_ * C_ + c0;
#pragma unroll
    for (int mf = 0; mf < 2; mf++) {
        int mA = m0 + mf*16 + r, mB = mA + 8;
#pragma unroll
        for (int nf = 0; nf < 4; nf++) {
            int c = cw + nf*8 + kq;
            *(float2*)(KX + (size_t)mA * C_ + c) = make_float2(acc[mf][nf][0], acc[mf][nf][1]);
            *(float2*)(KX + (size_t)mB * C_ + c) = make_float2(acc[mf][nf][2], acc[mf][nf][3]);
        }
    }
}

// =====================================================================
// mat_mma: matT[64c][64m] = Wv @ (sum KXp)^T, K=512. fp16 mma, ldmatrix,
// double-buffered, 1 sync/iter. Fuses: Knsum fold (publish), Vsum.
// grid (8 c-tiles, 16 b), 256 thr, 2 CTAs/SM.
// =====================================================================
#define MT_A(s) ((s) * 5120)
#define MT_B(s) (10240 + (s) * 5120)
#define MT_CS 0
#define MT_KS 20480
#define MT_BV 20736
#define MT_XS 20992
#define MT_BYTES 23040

__global__ __launch_bounds__(256, 2) void mat_mma(const float* __restrict__ Wv,
                                                  const float* __restrict__ bv) {
    __shared__ __align__(16) char sm[MT_BYTES];
    const int t = threadIdx.x, lane = t & 31, wid = t >> 5;
    const int b = blockIdx.y, c0 = blockIdx.x * 64;
    float* ksm = (float*)(sm + MT_KS);
    float* bvs = (float*)(sm + MT_BV);
    float* xss = (float*)(sm + MT_XS);
    if (t < 64) {   // fold Knsum partials; publish for final_mma
        float s = 0.f;
#pragma unroll
        for (int i = 0; i < 32; i++) s += g_Knp[((size_t)b * 32 + i) * M_ + t];
        ksm[t] = s;
        if (blockIdx.x == 0) g_Knsum[b * M_ + t] = s;
        bvs[t] = bv[c0 + t];
    }
    for (int i = t; i < C_; i += 256)   // folded xsum
        xss[i] = g_xsump[0][b * C_ + i] + g_xsump[1][b * C_ + i]
               + g_xsump[2][b * C_ + i] + g_xsump[3][b * C_ + i];
    __syncthreads();

    const float* A0 = g_KXp[0] + (size_t)b * M_ * C_;
    const float* A1 = g_KXp[1] + (size_t)b * M_ * C_;
    const float* A2 = g_KXp[2] + (size_t)b * M_ * C_;
    const float* A3 = g_KXp[3] + (size_t)b * M_ * C_;

    const int cw = (wid >> 2) * 32, nw = (wid & 3) * 16;
    const int r = lane >> 2, kq = (lane & 3) * 2;
    float acc[2][2][4] = {};
    float vacc[2] = {0.f, 0.f};

    float4 aR[2], bR[2];
    {   // prologue: k-step 0
#pragma unroll
        for (int i = 0; i < 2; i++) {   // Wv rows (c)
            int idx = t + i * 256, row = idx >> 3, g = idx & 7;
            aR[i] = *(const float4*)(Wv + (size_t)(c0 + row) * C_ + 4*g);
            vacc[i] = fmaf(aR[i].x, xss[4*g + 0],
                      fmaf(aR[i].y, xss[4*g + 1],
                      fmaf(aR[i].z, xss[4*g + 2],
                      fmaf(aR[i].w, xss[4*g + 3], vacc[i]))));
        }
#pragma unroll
        for (int i = 0; i < 2; i++) {   // KX fold rows (m)
            int idx = t + i * 256, row = idx >> 3, g = idx & 7;
            size_t off = (size_t)row * C_ + 4*g;
            float4 v0 = *(const float4*)(A0 + off), v1 = *(const float4*)(A1 + off);
            float4 v2 = *(const float4*)(A2 + off), v3 = *(const float4*)(A3 + off);
            bR[i] = make_float4(v0.x+v1.x+v2.x+v3.x, v0.y+v1.y+v2.y+v3.y,
                                v0.z+v1.z+v2.z+v3.z, v0.w+v1.w+v2.w+v3.w);
        }
    }

    for (int p = 0; p < 16; ++p) {
        const int s = p & 1;
        __half* Ah = (__half*)(sm + MT_A(s));
        __half* Bh = (__half*)(sm + MT_B(s));
#pragma unroll
        for (int i = 0; i < 2; i++) {
            int idx = t + i * 256, row = idx >> 3, g = idx & 7;
            *(uint2*)(Ah + row * 40 + 4*g) = pk4(aR[i]);
        }
#pragma unroll
        for (int i = 0; i < 2; i++) {
            int idx = t + i * 256, row = idx >> 3, g = idx & 7;
            *(uint2*)(Bh + row * 40 + 4*g) = pk4(bR[i]);
        }
        __syncthreads();
        if (p < 15) {   // prefetch next k-step (+ vsum accumulation)
            const int k0 = (p + 1) * 32;
#pragma unroll
            for (int i = 0; i < 2; i++) {
                int idx = t + i * 256, row = idx >> 3, g = idx & 7;
                aR[i] = *(const float4*)(Wv + (size_t)(c0 + row) * C_ + k0 + 4*g);
                vacc[i] = fmaf(aR[i].x, xss[k0 + 4*g + 0],
                          fmaf(aR[i].y, xss[k0 + 4*g + 1],
                          fmaf(aR[i].z, xss[k0 + 4*g + 2],
                          fmaf(aR[i].w, xss[k0 + 4*g + 3], vacc[i]))));
            }
#pragma unroll
            for (int i = 0; i < 2; i++) {
                int idx = t + i * 256, row = idx >> 3, g = idx & 7;
                size_t off = (size_t)row * C_ + k0 + 4*g;
                float4 v0 = *(const float4*)(A0 + off), v1 = *(const float4*)(A1 + off);
                float4 v2 = *(const float4*)(A2 + off), v3 = *(const float4*)(A3 + off);
                bR[i] = make_float4(v0.x+v1.x+v2.x+v3.x, v0.y+v1.y+v2.y+v3.y,
                                    v0.z+v1.z+v2.z+v3.z, v0.w+v1.w+v2.w+v3.w);
            }
        }
        const uint32_t Ab = smem_u32(Ah), Bb = smem_u32(Bh);
#pragma unroll
        for (int kc = 0; kc < 32; kc += 16) {
            uint32_t ah[2][4], bh[2][2];
#pragma unroll
            for (int mf = 0; mf < 2; mf++)
                ldsm_x4(ah[mf], Ab + ((cw + mf*16 + (lane & 15)) * 40 + kc + (lane >> 4) * 8) * 2);
            {
                uint32_t rr[4];
                ldsm_x4(rr, Bb + ((nw + (lane & 7) + ((lane >> 4) << 3)) * 40
                                  + kc + ((lane >> 3) & 1) * 8) * 2);
                bh[0][0] = rr[0]; bh[0][1] = rr[1];
                bh[1][0] = rr[2]; bh[1][1] = rr[3];
            }
#pragma unroll
            for (int mf = 0; mf < 2; mf++)
#pragma unroll
                for (int nf = 0; nf < 2; nf++) mma_f16(acc[mf][nf], ah[mf], bh[nf]);
        }
    }

    // Vsum: reduce vacc over the 8 loader-lanes per row, add N*bv
#pragma unroll
    for (int i = 0; i < 2; i++) {
        float v = vacc[i];
        v += __shfl_xor_sync(0xffffffffu, v, 1);
        v += __shfl_xor_sync(0xffffffffu, v, 2);
        v += __shfl_xor_sync(0xffffffffu, v, 4);
        int idx = t + i * 256, row = idx >> 3;
        if ((t & 7) == 0)
            g_Vsum[b * C_ + c0 + row] = v + (float)N_ * bvs[row];
    }
    __syncthreads();   // panels dead; reuse smem as Cs

    float* Cs = (float*)(sm + MT_CS);
#pragma unroll
    for (int mf = 0; mf < 2; mf++) {
        int cA = cw + mf*16 + r, cB = cA + 8;
        float bA = bvs[cA], bB = bvs[cB];
#pragma unroll
        for (int nf = 0; nf < 2; nf++) {
            int m = nw + nf*8 + kq;
            Cs[cA * 68 + m    ] = acc[mf][nf][0] + bA * ksm[m    ];
            Cs[cA * 68 + m + 1] = acc[mf][nf][1] + bA * ksm[m + 1];
            Cs[cB * 68 + m    ] = acc[mf][nf][2] + bB * ksm[m    ];
            Cs[cB * 68 + m + 1] = acc[mf][nf][3] + bB * ksm[m + 1];
        }
    }
    __syncthreads();
#pragma unroll
    for (int i = 0; i < 2; i++) {   // write matT16 [c][m], 8 halfs per task
        int idx = t + i * 256, row = idx >> 3, g = idx & 7;
        float4 v0 = *(float4*)(Cs + row * 68 + 8*g);
        float4 v1 = *(float4*)(Cs + row * 68 + 8*g + 4);
        uint2 h0 = pk4(v0), h1 = pk4(v1);
        uint4 o = make_uint4(h0.x, h0.y, h1.x, h1.y);
        *(uint4*)(g_matT16 + ((size_t)b * C_ + c0 + row) * M_ + 8*g) = o;
    }
}

// =====================================================================
// final_mma: D[64c][128n] = matT @ QnT^T, K=64, fused tailor, ldmatrix,
// direct-register epilogue. grid (32 n, 8 c, 16 b), 256 thr, 3 CTAs/SM.
// smem: Ah 0 (9216), Bh 9216 (18432) -> 27648; tl 27648, vs 28160,
// ks 28416 -> 28672
// =====================================================================
#define FN_AH 0
#define FN_BH 9216
#define FN_TL 27648
#define FN_VS 28160
#define FN_KS 28416
#define FN_BYTES 28672

__global__ __launch_bounds__(256, 3) void final_mma(float* __restrict__ out,
                                                    const float* __restrict__ gamma) {
    extern __shared__ __align__(16) char sm[];
    const int t = threadIdx.x, lane = t & 31, wid = t >> 5;
    const int b = blockIdx.z, c0 = blockIdx.y * 64, n0 = blockIdx.x * 128;
    float* tl = (float*)(sm + FN_TL);
    float* vs = (float*)(sm + FN_VS);
    float* ks = (float*)(sm + FN_KS);
    if (t < 64) {
        vs[t] = g_Vsum[b * C_ + c0 + t];
        ks[t] = g_Knsum[b * M_ + t];
    }
    __half* Ah = (__half*)(sm + FN_AH);
    __half* Bh = (__half*)(sm + FN_BH);
#pragma unroll
    for (int i = 0; i < 2; i++) {       // A: matT16 rows (c, 64), 64 k
        int idx = t + i * 256, row = idx >> 3, g = idx & 7;
        uint4 v = *(const uint4*)(g_matT16 + ((size_t)b * C_ + c0 + row) * M_ + 8*g);
        *(uint4*)(Ah + row * 72 + 8*g) = v;
    }
#pragma unroll
    for (int i = 0; i < 4; i++) {       // B: QnT16 rows (n, 128), 64 k
        int idx = t + i * 256, row = idx >> 3, g = idx & 7;
        uint4 v = *(const uint4*)(g_QnT16 + ((size_t)b * N_ + n0 + row) * M_ + 8*g);
        *(uint4*)(Bh + row * 72 + 8*g) = v;
    }
    __syncthreads();

    // fused tailor: tl[n] = 1/max(N + Qn[n,:].Knsum, 1e-6)
    if (t < 128) {
        float d = (float)N_;
#pragma unroll
        for (int m = 0; m < 64; m++) d += __half2float(Bh[t * 72 + m]) * ks[m];
        tl[t] = 1.f / fmaxf(d, 1e-6f);
    }

    const int cw = (wid >> 2) * 32, nw = (wid & 3) * 32;
    const int r = lane >> 2, kq = (lane & 3) * 2;
    const uint32_t Ab = smem_u32(Ah), Bb = smem_u32(Bh);
    uint32_t aAddr[2], bAddr;
#pragma unroll
    for (int mf = 0; mf < 2; mf++)
        aAddr[mf] = Ab + ((cw + mf*16 + (lane & 15)) * 72 + (lane >> 4) * 8) * 2;
    bAddr = Bb + ((nw + (lane & 7) + ((lane >> 4) << 3)) * 72 + ((lane >> 3) & 1) * 8) * 2;

    float acc[2][4][4] = {};
#pragma unroll
    for (int kc = 0; kc < 64; kc += 16) {
        uint32_t ah[2][4], bh[4][2];
#pragma unroll
        for (int mf = 0; mf < 2; mf++) ldsm_x4(ah[mf], aAddr[mf] + kc * 2);
#pragma unroll
        for (int nf = 0; nf < 4; nf += 2) {
            uint32_t rr[4];
            ldsm_x4(rr, bAddr + (nf * 8 * 72 + kc) * 2);
            bh[nf][0] = rr[0]; bh[nf][1] = rr[1];
            bh[nf+1][0] = rr[2]; bh[nf+1][1] = rr[3];
        }
#pragma unroll
        for (int mf = 0; mf < 2; mf++)
#pragma unroll
            for (int nf = 0; nf < 4; nf++) mma_f16(acc[mf][nf], ah[mf], bh[nf]);
    }
    __syncthreads();   // tl complete before epilogue reads

    // direct-register epilogue: per-thread float2 stores (32B sectors)
    float gm = gamma[0];
    float tlv[4][2];
#pragma unroll
    for (int nf = 0; nf < 4; nf++) {
        int n = nw + nf*8 + kq;
        tlv[nf][0] = gm * tl[n];
        tlv[nf][1] = gm * tl[n + 1];
    }
#pragma unroll
    for (int mf = 0; mf < 2; mf++) {
        int cA = cw + mf*16 + r, cB = cA + 8;
        float vA = vs[cA], vB = vs[cB];
        float* rowA = out + ((size_t)b * C_ + c0 + cA) * N_ + n0;
        float* rowB = out + ((size_t)b * C_ + c0 + cB) * N_ + n0;
#pragma unroll
        for (int nf = 0; nf < 4; nf++) {
            int n = nw + nf*8 + kq;
            float2 oA = make_float2(fixv(tlv[nf][0] * (vA + acc[mf][nf][0])),
                                    fixv(tlv[nf][1] * (vA + acc[mf][nf][1])));
            float2 oB = make_float2(fixv(tlv[nf][0] * (vB + acc[mf][nf][2])),
                                    fixv(tlv[nf][1] * (vB + acc[mf][nf][3])));
            __stcs((float2*)(rowA + n), oA);
            __stcs((float2*)(rowB + n), oB);
        }
    }
}

// ---------------------------------------------------------------
extern "C" void kernel_launch(void* const* d_in, const int* in_sizes, int n_in,
                              void* d_out, int out_size) {
    const float* x     = (const float*)d_in[0];
    const float* Wq    = (const float*)d_in[1];
    const float* bq    = (const float*)d_in[2];
    const float* Wk    = (const float*)d_in[3];
    const float* bk    = (const float*)d_in[4];
    const float* Wv    = (const float*)d_in[5];
    const float* bv    = (const float*)d_in[6];
    const float* gamma = (const float*)d_in[7];
    float* out = (float*)d_out;

    cudaFuncSetAttribute(qk_mma,    cudaFuncAttributeMaxDynamicSharedMemorySize, QK_BYTES);
    cudaFuncSetAttribute(final_mma, cudaFuncAttributeMaxDynamicSharedMemorySize, FN_BYTES);

    qk_mma   <<<dim3(32, 16), 256, QK_BYTES>>>(x, Wq, bq, Wk, bk);
    kx_mma   <<<dim3(4, 16, 4), 256>>>();
    mat_mma  <<<dim3(8, 16), 256>>>(Wv, bv);
    final_mma<<<dim3(32, 8, 16), 256, FN_BYTES>>>(out, gamma);
}

// round 15
// speedup vs baseline: 2.4759x; 1.0425x over previous
#include <cuda_runtime.h>
#include <cuda_fp16.h>
#include <cstdint>
#include <math.h>

#define B_ 16
#define C_ 512
#define N_ 4096
#define M_ 64

// ---------------- scratch (static device globals) ----------------
__device__ __align__(128) __half g_x16 [B_*C_*N_];    // fp16 copy of x (written by qk)
__device__ __align__(128) __half g_QnT16[B_*N_*M_];   // [b][n][m] fp16
__device__ __align__(128) __half g_Kn16 [B_*M_*N_];   // [b][m][n] fp16
__device__ __align__(128) __half g_matT16[B_*C_*M_];  // [b][c][m] fp16
__device__ __align__(128) float g_KXp[4][B_*M_*C_];   // k-split partials
__device__ __align__(128) float g_Knp[B_*32*M_];      // Knsum partials per n-tile
__device__ __align__(128) float g_Knsum[B_*M_];
__device__ __align__(128) float g_xsump[4][B_*C_];    // xsum k-split partials
__device__ __align__(128) float g_Vsum[B_*C_];
__device__ __align__(128) float g_tailor[B_*N_];

// ---------------- fp16 pack helpers ----------------
__device__ __forceinline__ uint32_t hpk2(float a, float b) {
    __half2 t = __floats2half2_rn(a, b);
    return *reinterpret_cast<uint32_t*>(&t);
}
__device__ __forceinline__ uint2 pk4(float4 v) {
    uint2 r; r.x = hpk2(v.x, v.y); r.y = hpk2(v.z, v.w); return r;
}
__device__ __forceinline__ uint32_t smem_u32(const void* p) {
    uint32_t a;
    asm("{ .reg .u64 t; cvta.to.shared.u64 t, %1; cvt.u32.u64 %0, t; }" : "=r"(a) : "l"(p));
    return a;
}

// ---------------- mma / ldmatrix helpers ----------------
__device__ __forceinline__ void mma_f16(float c[4], const uint32_t a[4], const uint32_t b[2]) {
    asm volatile("mma.sync.aligned.m16n8k16.row.col.f32.f16.f16.f32 "
        "{%0,%1,%2,%3}, {%4,%5,%6,%7}, {%8,%9}, {%0,%1,%2,%3};"
        : "+f"(c[0]), "+f"(c[1]), "+f"(c[2]), "+f"(c[3])
        : "r"(a[0]), "r"(a[1]), "r"(a[2]), "r"(a[3]), "r"(b[0]), "r"(b[1]));
}
__device__ __forceinline__ void ldsm_x4(uint32_t r[4], uint32_t a) {
    asm volatile("ldmatrix.sync.aligned.m8n8.x4.shared.b16 {%0,%1,%2,%3}, [%4];"
        : "=r"(r[0]), "=r"(r[1]), "=r"(r[2]), "=r"(r[3]) : "r"(a));
}
__device__ __forceinline__ void ldsm_x4t(uint32_t r[4], uint32_t a) {
    asm volatile("ldmatrix.sync.aligned.m8n8.x4.trans.shared.b16 {%0,%1,%2,%3}, [%4];"
        : "=r"(r[0]), "=r"(r[1]), "=r"(r[2]), "=r"(r[3]) : "r"(a));
}
__device__ __forceinline__ float fixv(float v) {
    if (isnan(v)) return 0.f;
    if (isinf(v)) return v > 0.f ? 1.f : -1.f;
    return v;
}

// =====================================================================
// qk_mma: D[128m(64q|64k)][128n] = Wqk @ x, K=512. grid(32,16), 256 thr,
// 2 CTAs/SM. fp16, ldmatrix x4 (A) + x4.trans (B), 1 sync/iter,
// double-buffered. Writes g_x16 (streaming) from the packed B values.
// =====================================================================
#define QK_A(s)  ((s) * 10240)
#define QK_B(s)  (20480 + (s) * 8704)
#define QK_CS 0
#define QK_BIAS 68096
#define QK_INQ 68608
#define QK_INK 69120
#define QK_BYTES 69632

__global__ __launch_bounds__(256, 2) void qk_mma(
    const float* __restrict__ x,  const float* __restrict__ Wq,
    const float* __restrict__ bq, const float* __restrict__ Wk,
    const float* __restrict__ bk) {
    extern __shared__ __align__(16) char sm[];
    const int t = threadIdx.x, lane = t & 31, wid = t >> 5;
    const int b = blockIdx.y, n0 = blockIdx.x * 128;
    const float* xb = x + (size_t)b * C_ * N_;
    float* bias = (float*)(sm + QK_BIAS);
    float* inq  = (float*)(sm + QK_INQ);
    float* ink  = (float*)(sm + QK_INK);
    if (t < 128) bias[t] = (t < 64) ? bq[t] : bk[t - 64];

    const int m0 = (wid >> 2) * 64, nw = (wid & 3) * 32;
    const int r = lane >> 2, kq = (lane & 3) * 2;
    float acc[4][4][4] = {};

    float4 aR[4], xR[4];
#pragma unroll
    for (int i = 0; i < 4; i++) {
        int idx = t + i * 256, row = idx >> 3, g = idx & 7;
        aR[i] = (row < 64) ? *(const float4*)(Wq + (size_t)row * C_ + 4*g)
                           : *(const float4*)(Wk + (size_t)(row - 64) * C_ + 4*g);
    }
#pragma unroll
    for (int i = 0; i < 4; i++) {
        int idx = t + i * 256, kk = idx >> 5, g = idx & 31;
        xR[i] = __ldcs((const float4*)(xb + (size_t)kk * N_ + n0 + 4*g));
    }

    for (int p = 0; p < 16; ++p) {
        const int s = p & 1;
        __half* Ah = (__half*)(sm + QK_A(s));
        __half* Bh = (__half*)(sm + QK_B(s));
#pragma unroll
        for (int i = 0; i < 4; i++) {   // A rows (m), 32 k, pitch 40
            int idx = t + i * 256, row = idx >> 3, g = idx & 7;
            *(uint2*)(Ah + row * 40 + 4*g) = pk4(aR[i]);
        }
#pragma unroll
        for (int i = 0; i < 4; i++) {   // B k-major + streaming x16 writeout
            int idx = t + i * 256, kk = idx >> 5, g = idx & 31;
            uint2 h = pk4(xR[i]);
            *(uint2*)(Bh + kk * 136 + 4*g) = h;
            __stcs((uint2*)(g_x16 + ((size_t)(b * C_ + p * 32 + kk)) * N_ + n0 + 4*g), h);
        }
        __syncthreads();
        if (p < 15) {   // prefetch next k-step
            const int k0 = (p + 1) * 32;
#pragma unroll
            for (int i = 0; i < 4; i++) {
                int idx = t + i * 256, row = idx >> 3, g = idx & 7;
                aR[i] = (row < 64) ? *(const float4*)(Wq + (size_t)row * C_ + k0 + 4*g)
                                   : *(const float4*)(Wk + (size_t)(row - 64) * C_ + k0 + 4*g);
            }
#pragma unroll
            for (int i = 0; i < 4; i++) {
                int idx = t + i * 256, kk = idx >> 5, g = idx & 31;
                xR[i] = __ldcs((const float4*)(xb + (size_t)(k0 + kk) * N_ + n0 + 4*g));
            }
        }
        const uint32_t Ab = smem_u32(Ah), Bb = smem_u32(Bh);
#pragma unroll
        for (int kc = 0; kc < 32; kc += 16) {
            uint32_t ah[4][4], bh[4][2];
#pragma unroll
            for (int mf = 0; mf < 4; mf++)
                ldsm_x4(ah[mf], Ab + ((m0 + mf*16 + (lane & 15)) * 40 + kc + (lane >> 4) * 8) * 2);
#pragma unroll
            for (int nf = 0; nf < 4; nf += 2) {
                uint32_t rr[4];
                ldsm_x4t(rr, Bb + ((kc + (lane & 15)) * 136 + nw + nf*8 + (lane >> 4) * 8) * 2);
                bh[nf][0] = rr[0]; bh[nf][1] = rr[1];
                bh[nf+1][0] = rr[2]; bh[nf+1][1] = rr[3];
            }
#pragma unroll
            for (int mf = 0; mf < 4; mf++)
#pragma unroll
                for (int nf = 0; nf < 4; nf++) mma_f16(acc[mf][nf], ah[mf], bh[nf]);
        }
    }
    __syncthreads();   // panels dead; reuse smem as Cs

    float* Cs = (float*)(sm + QK_CS);
#pragma unroll
    for (int mf = 0; mf < 4; mf++) {
        int mA = m0 + mf*16 + r, mB = mA + 8;
        float bA = bias[mA], bB = bias[mB];
#pragma unroll
        for (int nf = 0; nf < 4; nf++) {
            int n = nw + nf*8 + kq;
            Cs[mA * 133 + n    ] = acc[mf][nf][0] + bA;
            Cs[mA * 133 + n + 1] = acc[mf][nf][1] + bA;
            Cs[mB * 133 + n    ] = acc[mf][nf][2] + bB;
            Cs[mB * 133 + n + 1] = acc[mf][nf][3] + bB;
        }
    }
    __syncthreads();
    {   // per-column L2 norms
        int n = t & 127, part = t >> 7, base = part * 64;
        float s = 0.f;
#pragma unroll 8
        for (int m = 0; m < 64; m++) {
            float v = Cs[(base + m) * 133 + n]; s = fmaf(v, v, s);
        }
        float inv = 1.f / fmaxf(sqrtf(s), 1e-6f);
        if (part == 0) inq[n] = inv; else ink[n] = inv;
    }
    __syncthreads();
    // write Kn16[m][n] (fp16) + Knsum partials
#pragma unroll
    for (int i = 0; i < 8; i++) {
        int idx = t + i * 256, m = idx >> 5, g = idx & 31;
        float4 v;
        v.x = Cs[(64 + m) * 133 + 4*g + 0] * ink[4*g + 0];
        v.y = Cs[(64 + m) * 133 + 4*g + 1] * ink[4*g + 1];
        v.z = Cs[(64 + m) * 133 + 4*g + 2] * ink[4*g + 2];
        v.w = Cs[(64 + m) * 133 + 4*g + 3] * ink[4*g + 3];
        *(uint2*)(g_Kn16 + ((size_t)b * M_ + m) * N_ + n0 + 4*g) = pk4(v);
        float rs = v.x + v.y + v.z + v.w;
#pragma unroll
        for (int o = 16; o; o >>= 1) rs += __shfl_xor_sync(0xffffffffu, rs, o);
        if (lane == 0) g_Knp[((size_t)b * 32 + blockIdx.x) * M_ + m] = rs;
    }
    // write QnT16[n][m] (fp16)
#pragma unroll
    for (int i = 0; i < 8; i++) {
        int idx = t + i * 256, n = idx >> 4, g = idx & 15;
        float iq = inq[n];
        float4 v;
        v.x = Cs[(4*g + 0) * 133 + n] * iq;
        v.y = Cs[(4*g + 1) * 133 + n] * iq;
        v.z = Cs[(4*g + 2) * 133 + n] * iq;
        v.w = Cs[(4*g + 3) * 133 + n] * iq;
        *(uint2*)(g_QnT16 + ((size_t)b * N_ + n0 + n) * M_ + 4*g) = pk4(v);
    }
}

// =====================================================================
// kx_mma: D[64m][128c] = Kn @ x16^T over k-slice of 1024. All-fp16 loads.
// Direct-register epilogue. grid (4, 16, 4), 256 thr, 3 CTAs/SM.
// =====================================================================
#define KX_A(s) ((s) * 5120)
#define KX_B(s) (10240 + (s) * 10240)
#define KX_BYTES 30720

__global__ __launch_bounds__(256, 3) void kx_mma() {
    __shared__ __align__(16) char sm[KX_BYTES];
    const int t = threadIdx.x, lane = t & 31, wid = t >> 5;
    const int b = blockIdx.y, c0 = blockIdx.x * 128, ks = blockIdx.z;
    const __half* Kb  = g_Kn16 + (size_t)b * M_ * N_;
    const __half* xb16 = g_x16 + ((size_t)b * C_ + c0) * N_;
    const int m0 = (wid >> 2) * 32, cw = (wid & 3) * 32;
    const int r = lane >> 2, kq = (lane & 3) * 2;
    float acc[2][4][4] = {};
    float xs[2] = {0.f, 0.f};

    uint4 aR, bRx[2];
    {   // prologue: load step 0
        const int k0 = ks * 1024;
        { int row = t >> 2, g = t & 3;
          aR = *(const uint4*)(Kb + (size_t)row * N_ + k0 + 8*g); }
#pragma unroll
        for (int i = 0; i < 2; i++) {
            int idx = t + i * 256, row = idx >> 2, g = idx & 3;
            bRx[i] = __ldcs((const uint4*)(xb16 + (size_t)row * N_ + k0 + 8*g));
        }
    }

    for (int p = 0; p < 32; ++p) {
        const int s = p & 1;
        __half* Ah = (__half*)(sm + KX_A(s));
        __half* Bh = (__half*)(sm + KX_B(s));
        { int row = t >> 2, g = t & 3;
          *(uint4*)(Ah + row * 40 + 8*g) = aR; }
#pragma unroll
        for (int i = 0; i < 2; i++) {
            int idx = t + i * 256, row = idx >> 2, g = idx & 3;
            const __half2* hp = (const __half2*)&bRx[i];
#pragma unroll
            for (int j = 0; j < 4; j++) {
                float2 f = __half22float2(hp[j]);
                xs[i] += f.x + f.y;
            }
            *(uint4*)(Bh + row * 40 + 8*g) = bRx[i];
        }
        __syncthreads();
        if (p < 31) {   // prefetch next step
            const int k0 = ks * 1024 + (p + 1) * 32;
            { int row = t >> 2, g = t & 3;
              aR = *(const uint4*)(Kb + (size_t)row * N_ + k0 + 8*g); }
#pragma unroll
            for (int i = 0; i < 2; i++) {
                int idx = t + i * 256, row = idx >> 2, g = idx & 3;
                bRx[i] = __ldcs((const uint4*)(xb16 + (size_t)row * N_ + k0 + 8*g));
            }
        }
        const uint32_t Ab = smem_u32(Ah), Bb = smem_u32(Bh);
#pragma unroll
        for (int kc = 0; kc < 32; kc += 16) {
            uint32_t ah[2][4], bh[4][2];
#pragma unroll
            for (int mf = 0; mf < 2; mf++)
                ldsm_x4(ah[mf], Ab + ((m0 + mf*16 + (lane & 15)) * 40 + kc + (lane >> 4) * 8) * 2);
#pragma unroll
            for (int nf = 0; nf < 4; nf += 2) {
                uint32_t rr[4];
                ldsm_x4(rr, Bb + ((cw + nf*8 + (lane & 7) + ((lane >> 4) << 3)) * 40
                                  + kc + ((lane >> 3) & 1) * 8) * 2);
                bh[nf][0] = rr[0]; bh[nf][1] = rr[1];
                bh[nf+1][0] = rr[2]; bh[nf+1][1] = rr[3];
            }
#pragma unroll
            for (int mf = 0; mf < 2; mf++)
#pragma unroll
                for (int nf = 0; nf < 4; nf++) mma_f16(acc[mf][nf], ah[mf], bh[nf]);
        }
    }

    // xsum partial: reduce over 4 column-group threads per row
#pragma unroll
    for (int i = 0; i < 2; i++) {
        float v = xs[i];
        v += __shfl_xor_sync(0xffffffffu, v, 1);
        v += __shfl_xor_sync(0xffffffffu, v, 2);
        if ((t & 3) == 0)
            g_xsump[ks][b * C_ + c0 + (t >> 2) + 64 * i] = v;
    }

    // direct-register epilogue: float2 stores (4 lanes = 32B sector)
    float* KX = g_KXp[ks] + (size_t)b * M_ * C_ + c0;
#pragma unroll
    for (int mf = 0; mf < 2; mf++) {
        int mA = m0 + mf*16 + r, mB = mA + 8;
#pragma unroll
        for (int nf = 0; nf < 4; nf++) {
            int c = cw + nf*8 + kq;
            *(float2*)(KX + (size_t)mA * C_ + c) = make_float2(acc[mf][nf][0], acc[mf][nf][1]);
            *(float2*)(KX + (size_t)mB * C_ + c) = make_float2(acc[mf][nf][2], acc[mf][nf][3]);
        }
    }
}

// =====================================================================
// mat_mma: matT[64c][64m] = Wv @ (sum KXp)^T, K=512. fp16 mma, ldmatrix,
// double-buffered, 1 sync/iter. Fuses: Knsum fold (publish), Vsum.
// grid (8 c-tiles, 16 b), 256 thr, 2 CTAs/SM.
// =====================================================================
#define MT_A(s) ((s) * 5120)
#define MT_B(s) (10240 + (s) * 5120)
#define MT_CS 0
#define MT_KS 20480
#define MT_BV 20736
#define MT_XS 20992
#define MT_BYTES 23040

__global__ __launch_bounds__(256, 2) void mat_mma(const float* __restrict__ Wv,
                                                  const float* __restrict__ bv) {
    __shared__ __align__(16) char sm[MT_BYTES];
    const int t = threadIdx.x, lane = t & 31, wid = t >> 5;
    const int b = blockIdx.y, c0 = blockIdx.x * 64;
    float* ksm = (float*)(sm + MT_KS);
    float* bvs = (float*)(sm + MT_BV);
    float* xss = (float*)(sm + MT_XS);
    if (t < 64) {   // fold Knsum partials; publish for tailor_k/final
        float s = 0.f;
#pragma unroll
        for (int i = 0; i < 32; i++) s += g_Knp[((size_t)b * 32 + i) * M_ + t];
        ksm[t] = s;
        if (blockIdx.x == 0) g_Knsum[b * M_ + t] = s;
        bvs[t] = bv[c0 + t];
    }
    for (int i = t; i < C_; i += 256)   // folded xsum
        xss[i] = g_xsump[0][b * C_ + i] + g_xsump[1][b * C_ + i]
               + g_xsump[2][b * C_ + i] + g_xsump[3][b * C_ + i];
    __syncthreads();

    const float* A0 = g_KXp[0] + (size_t)b * M_ * C_;
    const float* A1 = g_KXp[1] + (size_t)b * M_ * C_;
    const float* A2 = g_KXp[2] + (size_t)b * M_ * C_;
    const float* A3 = g_KXp[3] + (size_t)b * M_ * C_;

    const int cw = (wid >> 2) * 32, nw = (wid & 3) * 16;
    const int r = lane >> 2, kq = (lane & 3) * 2;
    float acc[2][2][4] = {};
    float vacc[2] = {0.f, 0.f};

    float4 aR[2], bR[2];
    {   // prologue: k-step 0
#pragma unroll
        for (int i = 0; i < 2; i++) {   // Wv rows (c)
            int idx = t + i * 256, row = idx >> 3, g = idx & 7;
            aR[i] = *(const float4*)(Wv + (size_t)(c0 + row) * C_ + 4*g);
            vacc[i] = fmaf(aR[i].x, xss[4*g + 0],
                      fmaf(aR[i].y, xss[4*g + 1],
                      fmaf(aR[i].z, xss[4*g + 2],
                      fmaf(aR[i].w, xss[4*g + 3], vacc[i]))));
        }
#pragma unroll
        for (int i = 0; i < 2; i++) {   // KX fold rows (m)
            int idx = t + i * 256, row = idx >> 3, g = idx & 7;
            size_t off = (size_t)row * C_ + 4*g;
            float4 v0 = *(const float4*)(A0 + off), v1 = *(const float4*)(A1 + off);
            float4 v2 = *(const float4*)(A2 + off), v3 = *(const float4*)(A3 + off);
            bR[i] = make_float4(v0.x+v1.x+v2.x+v3.x, v0.y+v1.y+v2.y+v3.y,
                                v0.z+v1.z+v2.z+v3.z, v0.w+v1.w+v2.w+v3.w);
        }
    }

    for (int p = 0; p < 16; ++p) {
        const int s = p & 1;
        __half* Ah = (__half*)(sm + MT_A(s));
        __half* Bh = (__half*)(sm + MT_B(s));
#pragma unroll
        for (int i = 0; i < 2; i++) {
            int idx = t + i * 256, row = idx >> 3, g = idx & 7;
            *(uint2*)(Ah + row * 40 + 4*g) = pk4(aR[i]);
        }
#pragma unroll
        for (int i = 0; i < 2; i++) {
            int idx = t + i * 256, row = idx >> 3, g = idx & 7;
            *(uint2*)(Bh + row * 40 + 4*g) = pk4(bR[i]);
        }
        __syncthreads();
        if (p < 15) {   // prefetch next k-step (+ vsum accumulation)
            const int k0 = (p + 1) * 32;
#pragma unroll
            for (int i = 0; i < 2; i++) {
                int idx = t + i * 256, row = idx >> 3, g = idx & 7;
                aR[i] = *(const float4*)(Wv + (size_t)(c0 + row) * C_ + k0 + 4*g);
                vacc[i] = fmaf(aR[i].x, xss[k0 + 4*g + 0],
                          fmaf(aR[i].y, xss[k0 + 4*g + 1],
                          fmaf(aR[i].z, xss[k0 + 4*g + 2],
                          fmaf(aR[i].w, xss[k0 + 4*g + 3], vacc[i]))));
            }
#pragma unroll
            for (int i = 0; i < 2; i++) {
                int idx = t + i * 256, row = idx >> 3, g = idx & 7;
                size_t off = (size_t)row * C_ + k0 + 4*g;
                float4 v0 = *(const float4*)(A0 + off), v1 = *(const float4*)(A1 + off);
                float4 v2 = *(const float4*)(A2 + off), v3 = *(const float4*)(A3 + off);
                bR[i] = make_float4(v0.x+v1.x+v2.x+v3.x, v0.y+v1.y+v2.y+v3.y,
                                    v0.z+v1.z+v2.z+v3.z, v0.w+v1.w+v2.w+v3.w);
            }
        }
        const uint32_t Ab = smem_u32(Ah), Bb = smem_u32(Bh);
#pragma unroll
        for (int kc = 0; kc < 32; kc += 16) {
            uint32_t ah[2][4], bh[2][2];
#pragma unroll
            for (int mf = 0; mf < 2; mf++)
                ldsm_x4(ah[mf], Ab + ((cw + mf*16 + (lane & 15)) * 40 + kc + (lane >> 4) * 8) * 2);
            {
                uint32_t rr[4];
                ldsm_x4(rr, Bb + ((nw + (lane & 7) + ((lane >> 4) << 3)) * 40
                                  + kc + ((lane >> 3) & 1) * 8) * 2);
                bh[0][0] = rr[0]; bh[0][1] = rr[1];
                bh[1][0] = rr[2]; bh[1][1] = rr[3];
            }
#pragma unroll
            for (int mf = 0; mf < 2; mf++)
#pragma unroll
                for (int nf = 0; nf < 2; nf++) mma_f16(acc[mf][nf], ah[mf], bh[nf]);
        }
    }

    // Vsum: reduce vacc over the 8 loader-lanes per row, add N*bv
#pragma unroll
    for (int i = 0; i < 2; i++) {
        float v = vacc[i];
        v += __shfl_xor_sync(0xffffffffu, v, 1);
        v += __shfl_xor_sync(0xffffffffu, v, 2);
        v += __shfl_xor_sync(0xffffffffu, v, 4);
        int idx = t + i * 256, row = idx >> 3;
        if ((t & 7) == 0)
            g_Vsum[b * C_ + c0 + row] = v + (float)N_ * bvs[row];
    }
    __syncthreads();   // panels dead; reuse smem as Cs

    float* Cs = (float*)(sm + MT_CS);
#pragma unroll
    for (int mf = 0; mf < 2; mf++) {
        int cA = cw + mf*16 + r, cB = cA + 8;
        float bA = bvs[cA], bB = bvs[cB];
#pragma unroll
        for (int nf = 0; nf < 2; nf++) {
            int m = nw + nf*8 + kq;
            Cs[cA * 68 + m    ] = acc[mf][nf][0] + bA * ksm[m    ];
            Cs[cA * 68 + m + 1] = acc[mf][nf][1] + bA * ksm[m + 1];
            Cs[cB * 68 + m    ] = acc[mf][nf][2] + bB * ksm[m    ];
            Cs[cB * 68 + m + 1] = acc[mf][nf][3] + bB * ksm[m + 1];
        }
    }
    __syncthreads();
#pragma unroll
    for (int i = 0; i < 2; i++) {   // write matT16 [c][m], 8 halfs per task
        int idx = t + i * 256, row = idx >> 3, g = idx & 7;
        float4 v0 = *(float4*)(Cs + row * 68 + 8*g);
        float4 v1 = *(float4*)(Cs + row * 68 + 8*g + 4);
        uint2 h0 = pk4(v0), h1 = pk4(v1);
        uint4 o = make_uint4(h0.x, h0.y, h1.x, h1.y);
        *(uint4*)(g_matT16 + ((size_t)b * C_ + c0 + row) * M_ + 8*g) = o;
    }
}

// =====================================================================
// tailor_k: tl[b][n] = 1/max(N + Qn[n,:].Knsum, 1e-6). grid (16,16), 256 thr
// =====================================================================
__global__ __launch_bounds__(256, 4) void tailor_k() {
    __shared__ float ks[64];
    const int b = blockIdx.y, n = blockIdx.x * 256 + threadIdx.x;
    if (threadIdx.x < 64) ks[threadIdx.x] = g_Knsum[b * M_ + threadIdx.x];
    __syncthreads();
    const __half* q = g_QnT16 + ((size_t)b * N_ + n) * M_;
    float d = (float)N_;
#pragma unroll
    for (int g = 0; g < 8; g++) {
        uint4 v = *(const uint4*)(q + 8*g);
        const __half2* hp = (const __half2*)&v;
#pragma unroll
        for (int j = 0; j < 4; j++) {
            float2 f = __half22float2(hp[j]);
            d = fmaf(f.x, ks[8*g + 2*j], d);
            d = fmaf(f.y, ks[8*g + 2*j + 1], d);
        }
    }
    g_tailor[(size_t)b * N_ + n] = 1.f / fmaxf(d, 1e-6f);
}

// =====================================================================
// final_mma: D[64c][128n] = matT @ QnT^T, K=64, ldmatrix, tailor loaded
// from g_tailor, direct-register epilogue. grid (32 n, 8 c, 16 b),
// 256 thr, 3 CTAs/SM. smem: Ah 0 (9216), Bh 9216 (18432) -> 27648;
// tl 27648, vs 28160 -> 28416
// =====================================================================
#define FN_AH 0
#define FN_BH 9216
#define FN_TL 27648
#define FN_VS 28160
#define FN_BYTES 28416

__global__ __launch_bounds__(256, 3) void final_mma(float* __restrict__ out,
                                                    const float* __restrict__ gamma) {
    extern __shared__ __align__(16) char sm[];
    const int t = threadIdx.x, lane = t & 31, wid = t >> 5;
    const int b = blockIdx.z, c0 = blockIdx.y * 64, n0 = blockIdx.x * 128;
    float* tl = (float*)(sm + FN_TL);
    float* vs = (float*)(sm + FN_VS);
    if (t < 128) tl[t] = g_tailor[(size_t)b * N_ + n0 + t];
    else if (t < 192) vs[t - 128] = g_Vsum[b * C_ + c0 + (t - 128)];
    __half* Ah = (__half*)(sm + FN_AH);
    __half* Bh = (__half*)(sm + FN_BH);
#pragma unroll
    for (int i = 0; i < 2; i++) {       // A: matT16 rows (c, 64), 64 k
        int idx = t + i * 256, row = idx >> 3, g = idx & 7;
        uint4 v = *(const uint4*)(g_matT16 + ((size_t)b * C_ + c0 + row) * M_ + 8*g);
        *(uint4*)(Ah + row * 72 + 8*g) = v;
    }
#pragma unroll
    for (int i = 0; i < 4; i++) {       // B: QnT16 rows (n, 128), 64 k
        int idx = t + i * 256, row = idx >> 3, g = idx & 7;
        uint4 v = *(const uint4*)(g_QnT16 + ((size_t)b * N_ + n0 + row) * M_ + 8*g);
        *(uint4*)(Bh + row * 72 + 8*g) = v;
    }
    __syncthreads();

    const int cw = (wid >> 2) * 32, nw = (wid & 3) * 32;
    const int r = lane >> 2, kq = (lane & 3) * 2;
    const uint32_t Ab = smem_u32(Ah), Bb = smem_u32(Bh);
    uint32_t aAddr[2], bAddr;
#pragma unroll
    for (int mf = 0; mf < 2; mf++)
        aAddr[mf] = Ab + ((cw + mf*16 + (lane & 15)) * 72 + (lane >> 4) * 8) * 2;
    bAddr = Bb + ((nw + (lane & 7) + ((lane >> 4) << 3)) * 72 + ((lane >> 3) & 1) * 8) * 2;

    float acc[2][4][4] = {};
#pragma unroll
    for (int kc = 0; kc < 64; kc += 16) {
        uint32_t ah[2][4], bh[4][2];
#pragma unroll
        for (int mf = 0; mf < 2; mf++) ldsm_x4(ah[mf], aAddr[mf] + kc * 2);
#pragma unroll
        for (int nf = 0; nf < 4; nf += 2) {
            uint32_t rr[4];
            ldsm_x4(rr, bAddr + (nf * 8 * 72 + kc) * 2);
            bh[nf][0] = rr[0]; bh[nf][1] = rr[1];
            bh[nf+1][0] = rr[2]; bh[nf+1][1] = rr[3];
        }
#pragma unroll
        for (int mf = 0; mf < 2; mf++)
#pragma unroll
            for (int nf = 0; nf < 4; nf++) mma_f16(acc[mf][nf], ah[mf], bh[nf]);
    }

    // direct-register epilogue: per-thread float2 stores (32B sectors)
    float gm = gamma[0];
    float tlv[4][2];
#pragma unroll
    for (int nf = 0; nf < 4; nf++) {
        int n = nw + nf*8 + kq;
        tlv[nf][0] = gm * tl[n];
        tlv[nf][1] = gm * tl[n + 1];
    }
#pragma unroll
    for (int mf = 0; mf < 2; mf++) {
        int cA = cw + mf*16 + r, cB = cA + 8;
        float vA = vs[cA], vB = vs[cB];
        float* rowA = out + ((size_t)b * C_ + c0 + cA) * N_ + n0;
        float* rowB = out + ((size_t)b * C_ + c0 + cB) * N_ + n0;
#pragma unroll
        for (int nf = 0; nf < 4; nf++) {
            int n = nw + nf*8 + kq;
            float2 oA = make_float2(fixv(tlv[nf][0] * (vA + acc[mf][nf][0])),
                                    fixv(tlv[nf][1] * (vA + acc[mf][nf][1])));
            float2 oB = make_float2(fixv(tlv[nf][0] * (vB + acc[mf][nf][2])),
                                    fixv(tlv[nf][1] * (vB + acc[mf][nf][3])));
            __stcs((float2*)(rowA + n), oA);
            __stcs((float2*)(rowB + n), oB);
        }
    }
}

// ---------------------------------------------------------------
extern "C" void kernel_launch(void* const* d_in, const int* in_sizes, int n_in,
                              void* d_out, int out_size) {
    const float* x     = (const float*)d_in[0];
    const float* Wq    = (const float*)d_in[1];
    const float* bq    = (const float*)d_in[2];
    const float* Wk    = (const float*)d_in[3];
    const float* bk    = (const float*)d_in[4];
    const float* Wv    = (const float*)d_in[5];
    const float* bv    = (const float*)d_in[6];
    const float* gamma = (const float*)d_in[7];
    float* out = (float*)d_out;

    cudaFuncSetAttribute(qk_mma,    cudaFuncAttributeMaxDynamicSharedMemorySize, QK_BYTES);
    cudaFuncSetAttribute(final_mma, cudaFuncAttributeMaxDynamicSharedMemorySize, FN_BYTES);

    qk_mma   <<<dim3(32, 16), 256, QK_BYTES>>>(x, Wq, bq, Wk, bk);
    kx_mma   <<<dim3(4, 16, 4), 256>>>();
    mat_mma  <<<dim3(8, 16), 256>>>(Wv, bv);
    tailor_k <<<dim3(16, 16), 256>>>();
    final_mma<<<dim3(32, 8, 16), 256, FN_BYTES>>>(out, gamma);
}